// round 1
// baseline (speedup 1.0000x reference)
#include <cuda_runtime.h>
#include <cuda_bf16.h>
#include <math.h>

// Problem constants
#define BATCH 2
#define SEQ 2048
#define DMODEL 1024
#define NHEADS 16
#define DHEAD 64
#define DFF 2752
#define NTOK (BATCH * SEQ)          // 4096
#define EPSV 1e-5f

// ---------------- scratch (device globals; no allocation allowed) ----------
__device__ float g_xn  [NTOK * DMODEL];
__device__ float g_q   [NTOK * DMODEL];
__device__ float g_k   [NTOK * DMODEL];
__device__ float g_v   [NTOK * DMODEL];
__device__ float g_attn[NTOK * DMODEL];
__device__ float g_hres[NTOK * DMODEL];
__device__ float g_hn  [NTOK * DMODEL];
__device__ float g_tmp [NTOK * DMODEL];
__device__ float g_ff1 [NTOK * DFF];
__device__ float g_ff3 [NTOK * DFF];

// ---------------- RMSNorm: one block per row of 1024 -----------------------
__global__ void rmsnorm_kernel(const float* __restrict__ x,
                               const float* __restrict__ g,
                               float* __restrict__ y) {
    int row = blockIdx.x;
    const float* xr = x + (size_t)row * DMODEL;
    float* yr = y + (size_t)row * DMODEL;
    __shared__ float red[256];
    float s = 0.f;
    for (int i = threadIdx.x; i < DMODEL; i += 256) {
        float v = xr[i];
        s += v * v;
    }
    red[threadIdx.x] = s;
    __syncthreads();
    for (int st = 128; st > 0; st >>= 1) {
        if (threadIdx.x < st) red[threadIdx.x] += red[threadIdx.x + st];
        __syncthreads();
    }
    float inv = rsqrtf(red[0] * (1.0f / DMODEL) + EPSV);
    for (int i = threadIdx.x; i < DMODEL; i += 256)
        yr[i] = xr[i] * inv * g[i];
}

// ---------------- SGEMM: C[M,N] = A[M,K] @ B[K,N], all row-major -----------
// 128x128 block tile, 8 K-tile, 256 threads, 8x8 per thread.
__global__ void sgemm_kernel(const float* __restrict__ A,
                             const float* __restrict__ B,
                             float* __restrict__ C,
                             int M, int N, int K) {
    __shared__ float As[8][128];
    __shared__ float Bs[8][128];
    const int tid = threadIdx.x;
    const int bx = blockIdx.x, by = blockIdx.y;
    const int tx = tid & 15, ty = tid >> 4;
    const int rowBase = by * 128, colBase = bx * 128;

    float acc[8][8];
#pragma unroll
    for (int i = 0; i < 8; i++)
#pragma unroll
        for (int j = 0; j < 8; j++) acc[i][j] = 0.f;

    // A loads: 128 rows x 8 cols; 2 threads per row, 4 floats each
    const int a_r = tid >> 1, a_c = (tid & 1) * 4;
    // B loads: 8 rows x 128 cols; 32 threads per row, 4 floats each
    const int b_r = tid >> 5, b_c = (tid & 31) * 4;

    for (int k0 = 0; k0 < K; k0 += 8) {
        float4 av = *(const float4*)&A[(size_t)(rowBase + a_r) * K + k0 + a_c];
        As[a_c + 0][a_r] = av.x;
        As[a_c + 1][a_r] = av.y;
        As[a_c + 2][a_r] = av.z;
        As[a_c + 3][a_r] = av.w;

        float4 bv = make_float4(0.f, 0.f, 0.f, 0.f);
        if (colBase + b_c < N)
            bv = *(const float4*)&B[(size_t)(k0 + b_r) * N + colBase + b_c];
        Bs[b_r][b_c + 0] = bv.x;
        Bs[b_r][b_c + 1] = bv.y;
        Bs[b_r][b_c + 2] = bv.z;
        Bs[b_r][b_c + 3] = bv.w;
        __syncthreads();

#pragma unroll
        for (int k = 0; k < 8; k++) {
            float ra[8], rb[8];
#pragma unroll
            for (int i = 0; i < 8; i++) ra[i] = As[k][ty * 8 + i];
#pragma unroll
            for (int j = 0; j < 8; j++) rb[j] = Bs[k][tx * 8 + j];
#pragma unroll
            for (int i = 0; i < 8; i++)
#pragma unroll
                for (int j = 0; j < 8; j++)
                    acc[i][j] = fmaf(ra[i], rb[j], acc[i][j]);
        }
        __syncthreads();
    }

    // epilogue: per-thread 8 consecutive cols; N is a multiple of 8 in all our
    // calls, so a thread's 8 cols are either fully in-range or fully out.
    if (colBase + tx * 8 < N) {
#pragma unroll
        for (int i = 0; i < 8; i++) {
            int r = rowBase + ty * 8 + i;
            float4 v0 = make_float4(acc[i][0], acc[i][1], acc[i][2], acc[i][3]);
            float4 v1 = make_float4(acc[i][4], acc[i][5], acc[i][6], acc[i][7]);
            *(float4*)&C[(size_t)r * N + colBase + tx * 8 + 0] = v0;
            *(float4*)&C[(size_t)r * N + colBase + tx * 8 + 4] = v1;
        }
    }
}

// ---------------- causal attention: one block per (q, h, b) ----------------
// q/k/v layout: [b, s, h, dh] row-major (natural output of the projections).
__global__ void attn_kernel() {
    const int q_idx = blockIdx.x;
    const int h = blockIdx.y;
    const int b = blockIdx.z;
    const int tid = threadIdx.x;   // 128 threads

    __shared__ float sc[SEQ];          // 8 KB scores
    __shared__ float tile[128 * 65];   // 33.3 KB K/V chunk (padded)
    __shared__ float qv[DHEAD];
    __shared__ float red[128];

    const size_t rowstride = (size_t)NHEADS * DHEAD; // stride between s
    const float* qptr = g_q + ((size_t)(b * SEQ + q_idx) * NHEADS + h) * DHEAD;
    const float* kbase = g_k + ((size_t)b * SEQ * NHEADS + h) * DHEAD;
    const float* vbase = g_v + ((size_t)b * SEQ * NHEADS + h) * DHEAD;

    if (tid < DHEAD) qv[tid] = qptr[tid] * 0.125f;  // 1/sqrt(64)
    __syncthreads();

    const int jmax = q_idx; // inclusive causal bound

    // ---- scores ----
    for (int chunk = 0; chunk <= jmax; chunk += 128) {
        int nrows = min(128, jmax - chunk + 1);
        for (int i = tid; i < nrows * 64; i += 128) {
            int r = i >> 6, d = i & 63;
            tile[r * 65 + d] = kbase[(size_t)(chunk + r) * rowstride + d];
        }
        __syncthreads();
        if (tid < nrows) {
            float s = 0.f;
#pragma unroll
            for (int d = 0; d < 64; d++) s = fmaf(qv[d], tile[tid * 65 + d], s);
            sc[chunk + tid] = s;
        }
        __syncthreads();
    }

    // ---- softmax over sc[0..jmax] ----
    float m = -INFINITY;
    for (int j = tid; j <= jmax; j += 128) m = fmaxf(m, sc[j]);
    red[tid] = m;
    __syncthreads();
    for (int st = 64; st > 0; st >>= 1) {
        if (tid < st) red[tid] = fmaxf(red[tid], red[tid + st]);
        __syncthreads();
    }
    m = red[0];
    __syncthreads();
    float sum = 0.f;
    for (int j = tid; j <= jmax; j += 128) {
        float e = __expf(sc[j] - m);
        sc[j] = e;
        sum += e;
    }
    red[tid] = sum;
    __syncthreads();
    for (int st = 64; st > 0; st >>= 1) {
        if (tid < st) red[tid] += red[tid + st];
        __syncthreads();
    }
    float inv = 1.0f / red[0];
    __syncthreads();

    // ---- P @ V ----
    const int d = tid & 63, grp = tid >> 6;
    float acc = 0.f;
    for (int chunk = 0; chunk <= jmax; chunk += 128) {
        int nrows = min(128, jmax - chunk + 1);
        for (int i = tid; i < nrows * 64; i += 128) {
            int r = i >> 6, dd = i & 63;
            tile[r * 65 + dd] = vbase[(size_t)(chunk + r) * rowstride + dd];
        }
        __syncthreads();
        int r0 = grp * 64;
        int rend = min(nrows, r0 + 64);
        for (int r = r0; r < rend; r++)
            acc = fmaf(sc[chunk + r], tile[r * 65 + d], acc);
        __syncthreads();
    }
    red[tid] = acc;
    __syncthreads();
    if (tid < 64) {
        float o = (red[tid] + red[tid + 64]) * inv;
        g_attn[((size_t)(b * SEQ + q_idx) * NHEADS + h) * DHEAD + d] = o;
    }
}

// ---------------- elementwise kernels --------------------------------------
__global__ void add_kernel(const float* __restrict__ a,
                           const float* __restrict__ b,
                           float* __restrict__ out, int n) {
    int i = blockIdx.x * blockDim.x + threadIdx.x;
    if (i < n) out[i] = a[i] + b[i];
}

__global__ void swiglu_kernel(float* __restrict__ x1,
                              const float* __restrict__ x3, int n) {
    int i = blockIdx.x * blockDim.x + threadIdx.x;
    if (i < n) {
        float v = x1[i];
        float s = v / (1.f + __expf(-v));
        x1[i] = s * x3[i];
    }
}

// ---------------- launch ----------------------------------------------------
extern "C" void kernel_launch(void* const* d_in, const int* in_sizes, int n_in,
                              void* d_out, int out_size) {
    const float* x   = (const float*)d_in[0];
    const float* g1  = (const float*)d_in[1];
    const float* g2  = (const float*)d_in[2];
    const float* w_q = (const float*)d_in[3];
    const float* w_k = (const float*)d_in[4];
    const float* w_v = (const float*)d_in[5];
    const float* w_o = (const float*)d_in[6];
    const float* w1  = (const float*)d_in[7];
    const float* w2  = (const float*)d_in[8];
    const float* w3  = (const float*)d_in[9];
    float* out = (float*)d_out;

    float *p_xn, *p_q, *p_k, *p_v, *p_attn, *p_hres, *p_hn, *p_tmp, *p_ff1, *p_ff3;
    cudaGetSymbolAddress((void**)&p_xn,   g_xn);
    cudaGetSymbolAddress((void**)&p_q,    g_q);
    cudaGetSymbolAddress((void**)&p_k,    g_k);
    cudaGetSymbolAddress((void**)&p_v,    g_v);
    cudaGetSymbolAddress((void**)&p_attn, g_attn);
    cudaGetSymbolAddress((void**)&p_hres, g_hres);
    cudaGetSymbolAddress((void**)&p_hn,   g_hn);
    cudaGetSymbolAddress((void**)&p_tmp,  g_tmp);
    cudaGetSymbolAddress((void**)&p_ff1,  g_ff1);
    cudaGetSymbolAddress((void**)&p_ff3,  g_ff3);

    const int nTokD  = NTOK * DMODEL;   // 4194304
    const int nTokFF = NTOK * DFF;      // 11272192

    dim3 gemm_dmodel((DMODEL + 127) / 128, NTOK / 128); // 8 x 32
    dim3 gemm_ff((DFF + 127) / 128, NTOK / 128);        // 22 x 32

    // 1. xn = rmsnorm(x, g1)
    rmsnorm_kernel<<<NTOK, 256>>>(x, g1, p_xn);
    // 2-4. q/k/v projections
    sgemm_kernel<<<gemm_dmodel, 256>>>(p_xn, w_q, p_q, NTOK, DMODEL, DMODEL);
    sgemm_kernel<<<gemm_dmodel, 256>>>(p_xn, w_k, p_k, NTOK, DMODEL, DMODEL);
    sgemm_kernel<<<gemm_dmodel, 256>>>(p_xn, w_v, p_v, NTOK, DMODEL, DMODEL);
    // 5. causal attention
    attn_kernel<<<dim3(SEQ, NHEADS, BATCH), 128>>>();
    // 6. output projection
    sgemm_kernel<<<gemm_dmodel, 256>>>(p_attn, w_o, p_tmp, NTOK, DMODEL, DMODEL);
    // 7. h = x + attn @ Wo
    add_kernel<<<(nTokD + 255) / 256, 256>>>(x, p_tmp, p_hres, nTokD);
    // 8. hn = rmsnorm(h, g2)
    rmsnorm_kernel<<<NTOK, 256>>>(p_hres, g2, p_hn);
    // 9-10. FFN up projections
    sgemm_kernel<<<gemm_ff, 256>>>(p_hn, w1, p_ff1, NTOK, DFF, DMODEL);
    sgemm_kernel<<<gemm_ff, 256>>>(p_hn, w3, p_ff3, NTOK, DFF, DMODEL);
    // 11. gate = silu(x1) * x3 (in place into ff1)
    swiglu_kernel<<<(nTokFF + 255) / 256, 256>>>(p_ff1, p_ff3, nTokFF);
    // 12. ffn_out = gate @ w2
    sgemm_kernel<<<gemm_dmodel, 256>>>(p_ff1, w2, p_tmp, NTOK, DMODEL, DFF);
    // 13. out = h + ffn_out
    add_kernel<<<(nTokD + 255) / 256, 256>>>(p_hres, p_tmp, out, nTokD);
}

// round 2
// speedup vs baseline: 3.9994x; 3.9994x over previous
#include <cuda_runtime.h>
#include <cuda_bf16.h>
#include <math.h>

// Problem constants
#define BATCH 2
#define SEQ 2048
#define DMODEL 1024
#define NHEADS 16
#define DHEAD 64
#define DFF 2752
#define NTOK (BATCH * SEQ)          // 4096
#define EPSV 1e-5f

// ---------------- scratch (device globals; no allocation allowed) ----------
__device__ float g_xn  [NTOK * DMODEL];
__device__ float g_q   [NTOK * DMODEL];
__device__ float g_k   [NTOK * DMODEL];
__device__ float g_v   [NTOK * DMODEL];
__device__ float g_attn[NTOK * DMODEL];
__device__ float g_hres[NTOK * DMODEL];
__device__ float g_hn  [NTOK * DMODEL];
__device__ float g_ff1 [NTOK * DFF];
__device__ float g_ff3 [NTOK * DFF];

// ---------------- RMSNorm -----------------------------------------------
__global__ void rmsnorm_kernel(const float* __restrict__ x,
                               const float* __restrict__ g,
                               float* __restrict__ y) {
    int row = blockIdx.x;
    const float* xr = x + (size_t)row * DMODEL;
    float* yr = y + (size_t)row * DMODEL;
    __shared__ float red[256];
    float s = 0.f;
    for (int i = threadIdx.x; i < DMODEL; i += 256) {
        float v = xr[i];
        s += v * v;
    }
    red[threadIdx.x] = s;
    __syncthreads();
    for (int st = 128; st > 0; st >>= 1) {
        if (threadIdx.x < st) red[threadIdx.x] += red[threadIdx.x + st];
        __syncthreads();
    }
    float inv = rsqrtf(red[0] * (1.0f / DMODEL) + EPSV);
    for (int i = threadIdx.x; i < DMODEL; i += 256)
        yr[i] = xr[i] * inv * g[i];
}

// ---------------- tf32 helpers ------------------------------------------
__device__ __forceinline__ float to_tf32(float x) {
    unsigned u;
    asm("cvt.rna.tf32.f32 %0, %1;" : "=r"(u) : "f"(x));
    return __uint_as_float(u);
}

__device__ __forceinline__ void mma_tf32(float c[4], const float a[4], const float b[2]) {
    asm volatile(
        "mma.sync.aligned.m16n8k8.row.col.f32.tf32.tf32.f32 "
        "{%0,%1,%2,%3}, {%4,%5,%6,%7}, {%8,%9}, {%0,%1,%2,%3};\n"
        : "+f"(c[0]), "+f"(c[1]), "+f"(c[2]), "+f"(c[3])
        : "r"(__float_as_uint(a[0])), "r"(__float_as_uint(a[1])),
          "r"(__float_as_uint(a[2])), "r"(__float_as_uint(a[3])),
          "r"(__float_as_uint(b[0])), "r"(__float_as_uint(b[1])));
}

// ---------------- tf32 tensor-core GEMM ----------------------------------
// C[M,N] = A[M,K] @ B[K,N] (+ R), row-major. BM=BN=128, BK=16.
// 256 threads = 8 warps (4 m x 2 n), warp tile 32x64, mma m16n8k8.
#define GASTR 136
#define GBSTR 136

__global__ __launch_bounds__(256, 2)
void gemm_tf32(const float* __restrict__ A, const float* __restrict__ B,
               float* __restrict__ C, const float* __restrict__ R,
               int M, int N, int K) {
    __shared__ float As[16 * GASTR];   // [k][m]
    __shared__ float Bs[16 * GBSTR];   // [k][n]
    const int tid = threadIdx.x;
    const int warp = tid >> 5, lane = tid & 31;
    const int wm = warp & 3, wn = warp >> 2;
    const int gid = lane >> 2, tg = lane & 3;
    const int rowBase = blockIdx.y * 128, colBase = blockIdx.x * 128;

    const int a_r = tid >> 1, a_c = (tid & 1) * 8;
    const int b_r = tid >> 4, b_c = (tid & 15) * 8;
    const bool bvalid = (colBase + b_c) < N;

    float acc[2][8][4];
#pragma unroll
    for (int i = 0; i < 2; i++)
#pragma unroll
        for (int j = 0; j < 8; j++)
#pragma unroll
            for (int q = 0; q < 4; q++) acc[i][j][q] = 0.f;

    const float* Ap = A + (size_t)(rowBase + a_r) * K + a_c;
    const float* Bp = B + (size_t)b_r * N + colBase + b_c;

    float4 pa0 = *(const float4*)(Ap);
    float4 pa1 = *(const float4*)(Ap + 4);
    float4 pb0 = make_float4(0, 0, 0, 0), pb1 = make_float4(0, 0, 0, 0);
    if (bvalid) {
        pb0 = *(const float4*)(Bp);
        pb1 = *(const float4*)(Bp + 4);
    }

    for (int k0 = 0; k0 < K; k0 += 16) {
        // store current tile (tf32-rounded)
        As[(a_c + 0) * GASTR + a_r] = to_tf32(pa0.x);
        As[(a_c + 1) * GASTR + a_r] = to_tf32(pa0.y);
        As[(a_c + 2) * GASTR + a_r] = to_tf32(pa0.z);
        As[(a_c + 3) * GASTR + a_r] = to_tf32(pa0.w);
        As[(a_c + 4) * GASTR + a_r] = to_tf32(pa1.x);
        As[(a_c + 5) * GASTR + a_r] = to_tf32(pa1.y);
        As[(a_c + 6) * GASTR + a_r] = to_tf32(pa1.z);
        As[(a_c + 7) * GASTR + a_r] = to_tf32(pa1.w);
        {
            float4 t0 = make_float4(to_tf32(pb0.x), to_tf32(pb0.y), to_tf32(pb0.z), to_tf32(pb0.w));
            float4 t1 = make_float4(to_tf32(pb1.x), to_tf32(pb1.y), to_tf32(pb1.z), to_tf32(pb1.w));
            *(float4*)&Bs[b_r * GBSTR + b_c] = t0;
            *(float4*)&Bs[b_r * GBSTR + b_c + 4] = t1;
        }
        __syncthreads();

        // prefetch next tile
        if (k0 + 16 < K) {
            pa0 = *(const float4*)(Ap + k0 + 16);
            pa1 = *(const float4*)(Ap + k0 + 20);
            if (bvalid) {
                pb0 = *(const float4*)(Bp + (size_t)(k0 + 16) * N);
                pb1 = *(const float4*)(Bp + (size_t)(k0 + 16) * N + 4);
            }
        }

#pragma unroll
        for (int ks = 0; ks < 2; ks++) {
            float af[2][4];
#pragma unroll
            for (int mf = 0; mf < 2; mf++) {
                int mrow = wm * 32 + mf * 16;
                af[mf][0] = As[(ks * 8 + tg) * GASTR + mrow + gid];
                af[mf][1] = As[(ks * 8 + tg) * GASTR + mrow + gid + 8];
                af[mf][2] = As[(ks * 8 + tg + 4) * GASTR + mrow + gid];
                af[mf][3] = As[(ks * 8 + tg + 4) * GASTR + mrow + gid + 8];
            }
            float bf[8][2];
#pragma unroll
            for (int nf = 0; nf < 8; nf++) {
                int ncol = wn * 64 + nf * 8 + gid;
                bf[nf][0] = Bs[(ks * 8 + tg) * GBSTR + ncol];
                bf[nf][1] = Bs[(ks * 8 + tg + 4) * GBSTR + ncol];
            }
#pragma unroll
            for (int mf = 0; mf < 2; mf++)
#pragma unroll
                for (int nf = 0; nf < 8; nf++)
                    mma_tf32(acc[mf][nf], af[mf], bf[nf]);
        }
        __syncthreads();
    }

    // epilogue (+optional residual)
#pragma unroll
    for (int mf = 0; mf < 2; mf++) {
#pragma unroll
        for (int nf = 0; nf < 8; nf++) {
            int r0 = rowBase + wm * 32 + mf * 16 + gid;
            int c0 = colBase + wn * 64 + nf * 8 + tg * 2;
            if (c0 < N) {
                float v0 = acc[mf][nf][0], v1 = acc[mf][nf][1];
                float v2 = acc[mf][nf][2], v3 = acc[mf][nf][3];
                if (R) {
                    v0 += R[(size_t)r0 * N + c0];
                    v1 += R[(size_t)r0 * N + c0 + 1];
                    v2 += R[(size_t)(r0 + 8) * N + c0];
                    v3 += R[(size_t)(r0 + 8) * N + c0 + 1];
                }
                *(float2*)&C[(size_t)r0 * N + c0] = make_float2(v0, v1);
                *(float2*)&C[(size_t)(r0 + 8) * N + c0] = make_float2(v2, v3);
            }
        }
    }
}

// ---------------- flash-style causal attention ---------------------------
// Block: 64 q-rows x one head. Chunks of 128 keys through smem.
// smem (floats): Qs[64][QSTR] (d-major, swizzled), KV buffer (K d-major
// swizzled / V j-major), Ss[128][SSTR] scores (swizzled), rowf/rowinv.
#define TQ 64
#define CJ 128
#define QSTR 68
#define KSTR 132
#define VSTR 68
#define SSTR 68
#define KVWORDS 8704   // max(64*KSTR=8448, 128*VSTR=8704)

__global__ __launch_bounds__(256)
void attn_v2() {
    extern __shared__ float sm[];
    float* Qs = sm;                       // 64*QSTR = 4352
    float* KV = Qs + 64 * QSTR;           // 8704
    float* Ss = KV + KVWORDS;             // 128*SSTR = 8704
    float* rowf = Ss + 128 * SSTR;        // 64
    float* rowinv = rowf + 64;            // 64

    const int tid = threadIdx.x;
    const int qt = blockIdx.x, h = blockIdx.y, b = blockIdx.z;
    const int q0 = qt * TQ;

    const float* qg_base = g_q + (size_t)b * SEQ * DMODEL + h * DHEAD;
    const float* kg_base = g_k + (size_t)b * SEQ * DMODEL + h * DHEAD;
    const float* vg_base = g_v + (size_t)b * SEQ * DMODEL + h * DHEAD;

    // ---- load Q tile transposed (d-major) with swizzle, pre-scaled ----
#pragma unroll
    for (int it = 0; it < 4; it++) {
        int idx = tid + it * 256;          // 0..1023
        int r = idx >> 4;                  // 0..63
        int dblk = idx & 15;
        float4 v = *(const float4*)(qg_base + (size_t)(q0 + r) * DMODEL + dblk * 4);
        float vv[4] = {v.x, v.y, v.z, v.w};
#pragma unroll
        for (int q = 0; q < 4; q++) {
            int d = dblk * 4 + q;
            int pb = (r >> 2) ^ ((d >> 2) & 7);
            Qs[d * QSTR + pb * 4 + (r & 3)] = vv[q] * 0.125f;
        }
    }

    // per-row softmax state (threads 0..63 own row tid)
    float m_r = -1e30f, l_r = 0.f;

    // O accumulators: thread (td = tid&15 [d], tr2 = tid>>4 [r]) owns 4r x 4d
    const int td = tid & 15, tr2 = tid >> 4;
    float o[4][4];
#pragma unroll
    for (int i = 0; i < 4; i++)
#pragma unroll
        for (int j = 0; j < 4; j++) o[i][j] = 0.f;

    // scores thread layout
    const int tj = tid & 15, tr = tid >> 4;

    __syncthreads();

    const int jlast = q0 + TQ - 1;
    for (int j0 = 0; j0 <= jlast; j0 += CJ) {
        // ---- load K chunk transposed (d-major) with swizzle ----
#pragma unroll
        for (int it = 0; it < 8; it++) {
            int idx = tid + it * 256;      // 0..2047
            int j = idx >> 4;              // 0..127
            int dblk = idx & 15;
            float4 v = *(const float4*)(kg_base + (size_t)(j0 + j) * DMODEL + dblk * 4);
            float vv[4] = {v.x, v.y, v.z, v.w};
#pragma unroll
            for (int q = 0; q < 4; q++) {
                int d = dblk * 4 + q;
                int pb = (j >> 2) ^ ((d >> 2) & 7);
                KV[d * KSTR + pb * 4 + (j & 3)] = vv[q];
            }
        }
        __syncthreads();

        // ---- scores: Ss[j][r] = 0.125 * K[j]·Q[r], 8j x 4r per thread ----
        float sacc[8][4];
#pragma unroll
        for (int i = 0; i < 8; i++)
#pragma unroll
            for (int q = 0; q < 4; q++) sacc[i][q] = 0.f;

        for (int d = 0; d < 64; d++) {
            int swz = (d >> 2) & 7;
            float4 ka = *(float4*)&KV[d * KSTR + (((tj * 2) ^ swz) << 2)];
            float4 kb = *(float4*)&KV[d * KSTR + (((tj * 2 + 1) ^ swz) << 2)];
            float4 qv = *(float4*)&Qs[d * QSTR + ((tr ^ swz) << 2)];
            float kk[8] = {ka.x, ka.y, ka.z, ka.w, kb.x, kb.y, kb.z, kb.w};
            float qq[4] = {qv.x, qv.y, qv.z, qv.w};
#pragma unroll
            for (int i = 0; i < 8; i++)
#pragma unroll
                for (int q = 0; q < 4; q++)
                    sacc[i][q] = fmaf(kk[i], qq[q], sacc[i][q]);
        }
#pragma unroll
        for (int i = 0; i < 8; i++) {
            int j = tj * 8 + i;
            int pb = tr ^ ((j >> 3) & 7);
            *(float4*)&Ss[j * SSTR + pb * 4] =
                make_float4(sacc[i][0], sacc[i][1], sacc[i][2], sacc[i][3]);
        }
        __syncthreads();

        // ---- load V chunk (j-major, no swizzle) into KV ----
#pragma unroll
        for (int it = 0; it < 8; it++) {
            int idx = tid + it * 256;
            int j = idx >> 4;
            int dblk = idx & 15;
            float4 v = *(const float4*)(vg_base + (size_t)(j0 + j) * DMODEL + dblk * 4);
            *(float4*)&KV[j * VSTR + dblk * 4] = v;
        }

        // ---- online softmax (threads 0..63 own their row) ----
        if (tid < 64) {
            int r = tid;
            int qgl = q0 + r;
            int nv = qgl - j0 + 1;
            if (nv > CJ) nv = CJ;
            if (nv < 0) nv = 0;
            int rb4 = (r >> 2);
            float mc = -1e30f;
            for (int j = 0; j < nv; j++) {
                float s = Ss[j * SSTR + ((rb4 ^ ((j >> 3) & 7)) << 2) + (r & 3)];
                mc = fmaxf(mc, s);
            }
            float mnew = fmaxf(m_r, mc);
            float corr = __expf(m_r - mnew);
            float ssum = 0.f;
            for (int j = 0; j < CJ; j++) {
                int a = j * SSTR + ((rb4 ^ ((j >> 3) & 7)) << 2) + (r & 3);
                float p = 0.f;
                if (j < nv) {
                    p = __expf(Ss[a] - mnew);
                    ssum += p;
                }
                Ss[a] = p;
            }
            l_r = l_r * corr + ssum;
            m_r = mnew;
            rowf[r] = corr;
        }
        __syncthreads();

        // ---- rescale O, then PV accumulate ----
        float rf[4];
#pragma unroll
        for (int rr = 0; rr < 4; rr++) rf[rr] = rowf[tr2 * 4 + rr];
#pragma unroll
        for (int rr = 0; rr < 4; rr++)
#pragma unroll
            for (int dd = 0; dd < 4; dd++) o[rr][dd] *= rf[rr];

        for (int j = 0; j < CJ; j++) {
            int swzj = (j >> 3) & 7;
            float4 p = *(float4*)&Ss[j * SSTR + ((tr2 ^ swzj) << 2)];
            float4 vv = *(float4*)&KV[j * VSTR + td * 4];
            float pp[4] = {p.x, p.y, p.z, p.w};
            float vvv[4] = {vv.x, vv.y, vv.z, vv.w};
#pragma unroll
            for (int rr = 0; rr < 4; rr++)
#pragma unroll
                for (int dd = 0; dd < 4; dd++)
                    o[rr][dd] = fmaf(pp[rr], vvv[dd], o[rr][dd]);
        }
        __syncthreads();
    }

    // ---- finalize ----
    if (tid < 64) rowinv[tid] = 1.0f / l_r;
    __syncthreads();
#pragma unroll
    for (int rr = 0; rr < 4; rr++) {
        int r = tr2 * 4 + rr;
        float inv = rowinv[r];
        float4 res = make_float4(o[rr][0] * inv, o[rr][1] * inv,
                                 o[rr][2] * inv, o[rr][3] * inv);
        *(float4*)&g_attn[((size_t)(b * SEQ + q0 + r)) * DMODEL + h * DHEAD + td * 4] = res;
    }
}

// ---------------- elementwise ---------------------------------------------
__global__ void swiglu_kernel(float* __restrict__ x1,
                              const float* __restrict__ x3, int n) {
    int i = blockIdx.x * blockDim.x + threadIdx.x;
    if (i < n) {
        float v = x1[i];
        float s = v / (1.f + __expf(-v));
        x1[i] = s * x3[i];
    }
}

// ---------------- launch ----------------------------------------------------
extern "C" void kernel_launch(void* const* d_in, const int* in_sizes, int n_in,
                              void* d_out, int out_size) {
    const float* x   = (const float*)d_in[0];
    const float* g1  = (const float*)d_in[1];
    const float* g2  = (const float*)d_in[2];
    const float* w_q = (const float*)d_in[3];
    const float* w_k = (const float*)d_in[4];
    const float* w_v = (const float*)d_in[5];
    const float* w_o = (const float*)d_in[6];
    const float* w1  = (const float*)d_in[7];
    const float* w2  = (const float*)d_in[8];
    const float* w3  = (const float*)d_in[9];
    float* out = (float*)d_out;

    float *p_xn, *p_q, *p_k, *p_v, *p_attn, *p_hres, *p_hn, *p_ff1, *p_ff3;
    cudaGetSymbolAddress((void**)&p_xn,   g_xn);
    cudaGetSymbolAddress((void**)&p_q,    g_q);
    cudaGetSymbolAddress((void**)&p_k,    g_k);
    cudaGetSymbolAddress((void**)&p_v,    g_v);
    cudaGetSymbolAddress((void**)&p_attn, g_attn);
    cudaGetSymbolAddress((void**)&p_hres, g_hres);
    cudaGetSymbolAddress((void**)&p_hn,   g_hn);
    cudaGetSymbolAddress((void**)&p_ff1,  g_ff1);
    cudaGetSymbolAddress((void**)&p_ff3,  g_ff3);

    const int nTokFF = NTOK * DFF;

    static int attn_smem_set = 0;
    const int attn_smem = (64 * QSTR + KVWORDS + 128 * SSTR + 128) * 4;
    if (!attn_smem_set) {
        cudaFuncSetAttribute(attn_v2, cudaFuncAttributeMaxDynamicSharedMemorySize,
                             attn_smem);
        attn_smem_set = 1;
    }

    dim3 gD((DMODEL + 127) / 128, NTOK / 128);   // 8 x 32
    dim3 gF((DFF + 127) / 128, NTOK / 128);      // 22 x 32

    rmsnorm_kernel<<<NTOK, 256>>>(x, g1, p_xn);
    gemm_tf32<<<gD, 256>>>(p_xn, w_q, p_q, nullptr, NTOK, DMODEL, DMODEL);
    gemm_tf32<<<gD, 256>>>(p_xn, w_k, p_k, nullptr, NTOK, DMODEL, DMODEL);
    gemm_tf32<<<gD, 256>>>(p_xn, w_v, p_v, nullptr, NTOK, DMODEL, DMODEL);
    attn_v2<<<dim3(SEQ / TQ, NHEADS, BATCH), 256, attn_smem>>>();
    gemm_tf32<<<gD, 256>>>(p_attn, w_o, p_hres, x, NTOK, DMODEL, DMODEL);
    rmsnorm_kernel<<<NTOK, 256>>>(p_hres, g2, p_hn);
    gemm_tf32<<<gF, 256>>>(p_hn, w1, p_ff1, nullptr, NTOK, DFF, DMODEL);
    gemm_tf32<<<gF, 256>>>(p_hn, w3, p_ff3, nullptr, NTOK, DFF, DMODEL);
    swiglu_kernel<<<(nTokFF + 255) / 256, 256>>>(p_ff1, p_ff3, nTokFF);
    gemm_tf32<<<gD, 256>>>(p_ff1, w2, out, p_hres, NTOK, DMODEL, DFF);
}

// round 3
// speedup vs baseline: 6.0250x; 1.5065x over previous
#include <cuda_runtime.h>
#include <cuda_bf16.h>
#include <math.h>

#define BATCH 2
#define SEQ 2048
#define DMODEL 1024
#define NHEADS 16
#define DHEAD 64
#define DFF 2752
#define NTOK (BATCH * SEQ)
#define EPSV 1e-5f

// ---------------- scratch ----------------
__device__ float g_xn  [NTOK * DMODEL];
__device__ float g_q   [NTOK * DMODEL];
__device__ float g_k   [NTOK * DMODEL];
__device__ float g_v   [NTOK * DMODEL];
__device__ float g_attn[NTOK * DMODEL];
__device__ float g_hres[NTOK * DMODEL];
__device__ float g_hn  [NTOK * DMODEL];
__device__ float g_ff1 [NTOK * DFF];
__device__ float g_ff3 [NTOK * DFF];
__device__ float g_wqc [DMODEL * DMODEL];
__device__ float g_wkc [DMODEL * DMODEL];
__device__ float g_wvc [DMODEL * DMODEL];
__device__ float g_woc [DMODEL * DMODEL];
__device__ float g_w1c [DMODEL * DFF];
__device__ float g_w3c [DMODEL * DFF];
__device__ float g_w2c [DFF * DMODEL];

__device__ __forceinline__ float to_tf32(float x) {
    unsigned u;
    asm("cvt.rna.tf32.f32 %0, %1;" : "=r"(u) : "f"(x));
    return __uint_as_float(u);
}

__device__ __forceinline__ void mma_tf32(float c[4], const float a[4], const float b[2]) {
    asm volatile(
        "mma.sync.aligned.m16n8k8.row.col.f32.tf32.tf32.f32 "
        "{%0,%1,%2,%3}, {%4,%5,%6,%7}, {%8,%9}, {%0,%1,%2,%3};\n"
        : "+f"(c[0]), "+f"(c[1]), "+f"(c[2]), "+f"(c[3])
        : "r"(__float_as_uint(a[0])), "r"(__float_as_uint(a[1])),
          "r"(__float_as_uint(a[2])), "r"(__float_as_uint(a[3])),
          "r"(__float_as_uint(b[0])), "r"(__float_as_uint(b[1])));
}

__device__ __forceinline__ void cp_async16(float* smem_dst, const float* gsrc) {
    unsigned s = (unsigned)__cvta_generic_to_shared(smem_dst);
    asm volatile("cp.async.cg.shared.global [%0], [%1], 16;\n" :: "r"(s), "l"(gsrc));
}
__device__ __forceinline__ void cp_commit() {
    asm volatile("cp.async.commit_group;\n");
}

// ---------------- weight tf32 conversion ----------------
__global__ void cvt_tf32_kernel(const float* __restrict__ in, float* __restrict__ out, int n) {
    int i = blockIdx.x * blockDim.x + threadIdx.x;
    if (i < n) out[i] = to_tf32(in[i]);
}

// ---------------- RMSNorm (tf32-rounded output) ----------------
__global__ void rmsnorm_kernel(const float* __restrict__ x,
                               const float* __restrict__ g,
                               float* __restrict__ y) {
    int row = blockIdx.x;
    const float* xr = x + (size_t)row * DMODEL;
    float* yr = y + (size_t)row * DMODEL;
    __shared__ float red[256];
    float s = 0.f;
    for (int i = threadIdx.x; i < DMODEL; i += 256) {
        float v = xr[i];
        s += v * v;
    }
    red[threadIdx.x] = s;
    __syncthreads();
    for (int st = 128; st > 0; st >>= 1) {
        if (threadIdx.x < st) red[threadIdx.x] += red[threadIdx.x + st];
        __syncthreads();
    }
    float inv = rsqrtf(red[0] * (1.0f / DMODEL) + EPSV);
    for (int i = threadIdx.x; i < DMODEL; i += 256)
        yr[i] = to_tf32(xr[i] * inv * g[i]);
}

// ---------------- tf32 GEMM: 128x256 tile, cp.async 3-stage ----------------
#define BM 128
#define BN 256
#define BKK 16
#define ASTR 40     // [m][k] stride (8 mod 32)
#define BSTR 264    // [k][n] stride (8 mod 32)
#define ASTAGE (BM * ASTR)
#define BSTAGE (BKK * BSTR)
#define GSMEM_FLOATS (3 * ASTAGE + 3 * BSTAGE)

__global__ __launch_bounds__(256)
void gemm_tc(const float* __restrict__ A, const float* __restrict__ B,
             float* __restrict__ C, const float* __restrict__ R,
             int M, int N, int K, int round_out) {
    extern __shared__ float gsm[];
    float* As = gsm;                 // 3 stages
    float* Bs = gsm + 3 * ASTAGE;    // 3 stages

    const int tid = threadIdx.x;
    const int warp = tid >> 5, lane = tid & 31;
    const int gid = lane >> 2, tg = lane & 3;
    const int wm = warp >> 2, wn = warp & 3;   // 2 x 4 warps, 64x64 warp tile
    const int rowBase = blockIdx.y * BM, colBase = blockIdx.x * BN;
    const bool partial = (colBase + BN > N);

    if (partial) {
        for (int i = tid; i < 3 * BSTAGE; i += 256) Bs[i] = 0.f;
        __syncthreads();
    }

    // loader mapping
    const int a_r0 = tid >> 1, a_k0 = (tid & 1) * 2;       // 2 chunks/thread: rows tid>>1..,
    const int b_r = tid >> 4, b_c64 = (tid & 15) * 4;      // 4 chunks/thread
    const float* Abase = A + (size_t)rowBase * K;

    const int nIter = K / BKK;

#define ISSUE_TILE(stage, k0)                                                        \
    do {                                                                             \
        float* as = As + (stage) * ASTAGE;                                           \
        float* bs = Bs + (stage) * BSTAGE;                                           \
        _Pragma("unroll")                                                            \
        for (int i = 0; i < 2; i++) {                                                \
            int c = tid + i * 256;                                                   \
            int r = c >> 2, k4 = c & 3;                                              \
            cp_async16(as + r * ASTR + k4 * 4, Abase + (size_t)r * K + (k0) + k4 * 4);\
        }                                                                            \
        _Pragma("unroll")                                                            \
        for (int i = 0; i < 4; i++) {                                                \
            int c = tid + i * 256;                                                   \
            int r = c >> 6, c4 = c & 63;                                             \
            int col = colBase + c4 * 4;                                              \
            if (col < N)                                                             \
                cp_async16(bs + r * BSTR + c4 * 4, B + (size_t)((k0) + r) * N + col);\
        }                                                                            \
        cp_commit();                                                                 \
    } while (0)

    ISSUE_TILE(0, 0);
    if (nIter > 1) ISSUE_TILE(1, 16);

    float acc[4][8][4];
#pragma unroll
    for (int i = 0; i < 4; i++)
#pragma unroll
        for (int j = 0; j < 8; j++)
#pragma unroll
            for (int q = 0; q < 4; q++) acc[i][j][q] = 0.f;

    for (int it = 0; it < nIter; it++) {
        if (it + 1 < nIter) {
            asm volatile("cp.async.wait_group 1;\n");
        } else {
            asm volatile("cp.async.wait_group 0;\n");
        }
        __syncthreads();
        if (it + 2 < nIter) {
            int st = (it + 2) % 3;
            int k0n = (it + 2) * BKK;
            ISSUE_TILE(st, k0n);
        }
        const float* as = As + (it % 3) * ASTAGE;
        const float* bs = Bs + (it % 3) * BSTAGE;
#pragma unroll
        for (int ks = 0; ks < 2; ks++) {
            const int kk = ks * 8;
            float af[4][4];
#pragma unroll
            for (int mfi = 0; mfi < 4; mfi++) {
                int m0 = wm * 64 + mfi * 16;
                af[mfi][0] = as[(m0 + gid) * ASTR + kk + tg];
                af[mfi][1] = as[(m0 + gid + 8) * ASTR + kk + tg];
                af[mfi][2] = as[(m0 + gid) * ASTR + kk + tg + 4];
                af[mfi][3] = as[(m0 + gid + 8) * ASTR + kk + tg + 4];
            }
            float bf[8][2];
#pragma unroll
            for (int nfi = 0; nfi < 8; nfi++) {
                int n0 = wn * 64 + nfi * 8 + gid;
                bf[nfi][0] = bs[(kk + tg) * BSTR + n0];
                bf[nfi][1] = bs[(kk + tg + 4) * BSTR + n0];
            }
#pragma unroll
            for (int mfi = 0; mfi < 4; mfi++)
#pragma unroll
                for (int nfi = 0; nfi < 8; nfi++)
                    mma_tf32(acc[mfi][nfi], af[mfi], bf[nfi]);
        }
        __syncthreads();
    }

#pragma unroll
    for (int mfi = 0; mfi < 4; mfi++) {
#pragma unroll
        for (int nfi = 0; nfi < 8; nfi++) {
            int r0 = rowBase + wm * 64 + mfi * 16 + gid;
            int c0 = colBase + wn * 64 + nfi * 8 + tg * 2;
            if (c0 < N) {
                float v0 = acc[mfi][nfi][0], v1 = acc[mfi][nfi][1];
                float v2 = acc[mfi][nfi][2], v3 = acc[mfi][nfi][3];
                if (R) {
                    v0 += R[(size_t)r0 * N + c0];
                    v1 += R[(size_t)r0 * N + c0 + 1];
                    v2 += R[(size_t)(r0 + 8) * N + c0];
                    v3 += R[(size_t)(r0 + 8) * N + c0 + 1];
                }
                if (round_out) {
                    v0 = to_tf32(v0); v1 = to_tf32(v1);
                    v2 = to_tf32(v2); v3 = to_tf32(v3);
                }
                *(float2*)&C[(size_t)r0 * N + c0] = make_float2(v0, v1);
                *(float2*)&C[(size_t)(r0 + 8) * N + c0] = make_float2(v2, v3);
            }
        }
    }
#undef ISSUE_TILE
}

// ---------------- tensor-core flash attention ----------------
// TQ=64 queries, CJ=128 keys per chunk, 256 threads / 8 warps.
// Qm[64][72] (m-major), Kj[128][72] (n-major for B), Vs[128][72] (k-major for B),
// Ss[64][132] scores->probs in place.
#define ATQ 64
#define ACJ 128
#define QSTRD 72
#define KSTRD 72
#define VSTRD 72
#define SSTRD 132
#define ASM_FLOATS (ATQ * QSTRD + ACJ * KSTRD + ACJ * VSTRD + ATQ * SSTRD + 64 + 64 + 256 + 256)

__global__ __launch_bounds__(256)
void attn_tc() {
    extern __shared__ float sm[];
    float* Qm = sm;                              // 4608
    float* Kj = Qm + ATQ * QSTRD;                // 9216
    float* Vs = Kj + ACJ * KSTRD;                // 9216
    float* Ss = Vs + ACJ * VSTRD;                // 8448
    float* rowf = Ss + ATQ * SSTRD;              // 64
    float* rowinv = rowf + 64;                   // 64
    float* red1 = rowinv + 64;                   // 256
    float* red2 = red1 + 256;                    // 256

    const int tid = threadIdx.x;
    const int warp = tid >> 5, lane = tid & 31;
    const int gid = lane >> 2, tg = lane & 3;
    const int wm = warp >> 2, wn = warp & 3;     // QK: 2x4 warps, 32x32 S tile
    const int wm2 = warp >> 1, wn2 = warp & 1;   // PV: 4x2 warps, 16x32 O tile
    const int sr = tid >> 2, sq = tid & 3;       // softmax: 4 threads/row

    const int qt = blockIdx.x, h = blockIdx.y, b = blockIdx.z;
    const int q0 = qt * ATQ;

    const float* qg = g_q + (size_t)b * SEQ * DMODEL + h * DHEAD;
    const float* kg = g_k + (size_t)b * SEQ * DMODEL + h * DHEAD;
    const float* vg = g_v + (size_t)b * SEQ * DMODEL + h * DHEAD;

    // load Q tile (row-major, pre-scaled by 1/sqrt(64))
#pragma unroll
    for (int i = 0; i < 4; i++) {
        int c = tid + i * 256;
        int r = c >> 4, db = c & 15;
        float4 v = *(const float4*)(qg + (size_t)(q0 + r) * DMODEL + db * 4);
        v.x *= 0.125f; v.y *= 0.125f; v.z *= 0.125f; v.w *= 0.125f;
        *(float4*)&Qm[r * QSTRD + db * 4] = v;
    }

    float o[4][4];
#pragma unroll
    for (int i = 0; i < 4; i++)
#pragma unroll
        for (int j = 0; j < 4; j++) o[i][j] = 0.f;
    float m_r = -1e30f, l_r = 0.f;

    __syncthreads();

    const int nchunks = (q0 + ATQ + ACJ - 1) / ACJ;
    for (int c = 0; c < nchunks; c++) {
        const int j0 = c * ACJ;
        if (c) __syncthreads();   // protect Vs/Ss from previous PV reads

        // load K, V chunks (row-major as in global)
#pragma unroll
        for (int i = 0; i < 8; i++) {
            int cc = tid + i * 256;
            int j = cc >> 4, db = cc & 15;
            *(float4*)&Kj[j * KSTRD + db * 4] =
                *(const float4*)(kg + (size_t)(j0 + j) * DMODEL + db * 4);
            *(float4*)&Vs[j * VSTRD + db * 4] =
                *(const float4*)(vg + (size_t)(j0 + j) * DMODEL + db * 4);
        }
        __syncthreads();

        // ---- S = Q K^T ----
        float sacc[2][4][4];
#pragma unroll
        for (int i = 0; i < 2; i++)
#pragma unroll
            for (int j = 0; j < 4; j++)
#pragma unroll
                for (int q = 0; q < 4; q++) sacc[i][j][q] = 0.f;
#pragma unroll
        for (int kk = 0; kk < 64; kk += 8) {
            float af[2][4];
#pragma unroll
            for (int mfi = 0; mfi < 2; mfi++) {
                int m0 = wm * 32 + mfi * 16;
                af[mfi][0] = Qm[(m0 + gid) * QSTRD + kk + tg];
                af[mfi][1] = Qm[(m0 + gid + 8) * QSTRD + kk + tg];
                af[mfi][2] = Qm[(m0 + gid) * QSTRD + kk + tg + 4];
                af[mfi][3] = Qm[(m0 + gid + 8) * QSTRD + kk + tg + 4];
            }
            float bf[4][2];
#pragma unroll
            for (int nfi = 0; nfi < 4; nfi++) {
                int n0 = wn * 32 + nfi * 8 + gid;
                bf[nfi][0] = Kj[n0 * KSTRD + kk + tg];
                bf[nfi][1] = Kj[n0 * KSTRD + kk + tg + 4];
            }
#pragma unroll
            for (int mfi = 0; mfi < 2; mfi++)
#pragma unroll
                for (int nfi = 0; nfi < 4; nfi++)
                    mma_tf32(sacc[mfi][nfi], af[mfi], bf[nfi]);
        }
#pragma unroll
        for (int mfi = 0; mfi < 2; mfi++)
#pragma unroll
            for (int nfi = 0; nfi < 4; nfi++) {
                int r0 = wm * 32 + mfi * 16 + gid;
                int c0 = wn * 32 + nfi * 8 + tg * 2;
                *(float2*)&Ss[r0 * SSTRD + c0] = make_float2(sacc[mfi][nfi][0], sacc[mfi][nfi][1]);
                *(float2*)&Ss[(r0 + 8) * SSTRD + c0] = make_float2(sacc[mfi][nfi][2], sacc[mfi][nfi][3]);
            }
        __syncthreads();

        // ---- online softmax: 4 threads per row, 32 cols each ----
        int nv = q0 + sr - j0 + 1;
        if (nv > ACJ) nv = ACJ;
        const int jb = sq * 32;
        float msg = -1e30f;
        for (int i = 0; i < 32; i++) {
            int j = jb + i;
            if (j < nv) msg = fmaxf(msg, Ss[sr * SSTRD + j]);
        }
        red1[sq * 64 + sr] = msg;
        __syncthreads();
        float mnew = fmaxf(fmaxf(fmaxf(red1[sr], red1[64 + sr]),
                                 fmaxf(red1[128 + sr], red1[192 + sr])), m_r);
        float corr = __expf(m_r - mnew);
        float psum = 0.f;
        for (int i = 0; i < 32; i++) {
            int j = jb + i;
            float p = 0.f;
            if (j < nv) {
                p = to_tf32(__expf(Ss[sr * SSTRD + j] - mnew));
                psum += p;
            }
            Ss[sr * SSTRD + j] = p;
        }
        red2[sq * 64 + sr] = psum;
        if (sq == 0) rowf[sr] = corr;
        __syncthreads();
        l_r = l_r * corr + red2[sr] + red2[64 + sr] + red2[128 + sr] + red2[192 + sr];
        m_r = mnew;

        // ---- O = O*corr + P V ----
        const int m0p = wm2 * 16;
        float cg = rowf[m0p + gid], cg8 = rowf[m0p + gid + 8];
#pragma unroll
        for (int nfi = 0; nfi < 4; nfi++) {
            o[nfi][0] *= cg;  o[nfi][1] *= cg;
            o[nfi][2] *= cg8; o[nfi][3] *= cg8;
        }
#pragma unroll
        for (int kk = 0; kk < ACJ; kk += 8) {
            float paf[4];
            paf[0] = Ss[(m0p + gid) * SSTRD + kk + tg];
            paf[1] = Ss[(m0p + gid + 8) * SSTRD + kk + tg];
            paf[2] = Ss[(m0p + gid) * SSTRD + kk + tg + 4];
            paf[3] = Ss[(m0p + gid + 8) * SSTRD + kk + tg + 4];
            float bvf[4][2];
#pragma unroll
            for (int nfi = 0; nfi < 4; nfi++) {
                int n0 = wn2 * 32 + nfi * 8 + gid;
                bvf[nfi][0] = Vs[(kk + tg) * VSTRD + n0];
                bvf[nfi][1] = Vs[(kk + tg + 4) * VSTRD + n0];
            }
#pragma unroll
            for (int nfi = 0; nfi < 4; nfi++)
                mma_tf32(o[nfi], paf, bvf[nfi]);
        }
    }

    if (sq == 0) rowinv[sr] = 1.0f / l_r;
    __syncthreads();

    const int m0p = wm2 * 16;
    float iv = rowinv[m0p + gid], iv8 = rowinv[m0p + gid + 8];
#pragma unroll
    for (int nfi = 0; nfi < 4; nfi++) {
        int c0 = wn2 * 32 + nfi * 8 + tg * 2;
        int r0 = q0 + m0p + gid;
        float* dst = g_attn + ((size_t)(b * SEQ + r0)) * DMODEL + h * DHEAD + c0;
        *(float2*)dst = make_float2(to_tf32(o[nfi][0] * iv), to_tf32(o[nfi][1] * iv));
        float* dst8 = dst + 8 * DMODEL;
        *(float2*)dst8 = make_float2(to_tf32(o[nfi][2] * iv8), to_tf32(o[nfi][3] * iv8));
    }
}

// ---------------- elementwise ----------------
__global__ void swiglu_kernel(float* __restrict__ x1,
                              const float* __restrict__ x3, int n) {
    int i = blockIdx.x * blockDim.x + threadIdx.x;
    if (i < n) {
        float v = x1[i];
        float s = v / (1.f + __expf(-v));
        x1[i] = to_tf32(s * x3[i]);
    }
}

// ---------------- launch ----------------
extern "C" void kernel_launch(void* const* d_in, const int* in_sizes, int n_in,
                              void* d_out, int out_size) {
    const float* x   = (const float*)d_in[0];
    const float* g1  = (const float*)d_in[1];
    const float* g2  = (const float*)d_in[2];
    const float* w_q = (const float*)d_in[3];
    const float* w_k = (const float*)d_in[4];
    const float* w_v = (const float*)d_in[5];
    const float* w_o = (const float*)d_in[6];
    const float* w1  = (const float*)d_in[7];
    const float* w2  = (const float*)d_in[8];
    const float* w3  = (const float*)d_in[9];
    float* out = (float*)d_out;

    float *p_xn, *p_q, *p_k, *p_v, *p_attn, *p_hres, *p_hn, *p_ff1, *p_ff3;
    float *p_wq, *p_wk, *p_wv, *p_wo, *p_w1, *p_w3, *p_w2;
    cudaGetSymbolAddress((void**)&p_xn,   g_xn);
    cudaGetSymbolAddress((void**)&p_q,    g_q);
    cudaGetSymbolAddress((void**)&p_k,    g_k);
    cudaGetSymbolAddress((void**)&p_v,    g_v);
    cudaGetSymbolAddress((void**)&p_attn, g_attn);
    cudaGetSymbolAddress((void**)&p_hres, g_hres);
    cudaGetSymbolAddress((void**)&p_hn,   g_hn);
    cudaGetSymbolAddress((void**)&p_ff1,  g_ff1);
    cudaGetSymbolAddress((void**)&p_ff3,  g_ff3);
    cudaGetSymbolAddress((void**)&p_wq,   g_wqc);
    cudaGetSymbolAddress((void**)&p_wk,   g_wkc);
    cudaGetSymbolAddress((void**)&p_wv,   g_wvc);
    cudaGetSymbolAddress((void**)&p_wo,   g_woc);
    cudaGetSymbolAddress((void**)&p_w1,   g_w1c);
    cudaGetSymbolAddress((void**)&p_w3,   g_w3c);
    cudaGetSymbolAddress((void**)&p_w2,   g_w2c);

    static int attr_set = 0;
    const int gemm_smem = GSMEM_FLOATS * 4;
    const int attn_smem = ASM_FLOATS * 4;
    if (!attr_set) {
        cudaFuncSetAttribute(gemm_tc, cudaFuncAttributeMaxDynamicSharedMemorySize, gemm_smem);
        cudaFuncSetAttribute(attn_tc, cudaFuncAttributeMaxDynamicSharedMemorySize, attn_smem);
        attr_set = 1;
    }

    const int nDD = DMODEL * DMODEL;      // 1048576
    const int nDF = DMODEL * DFF;         // 2818048
    const int nTokFF = NTOK * DFF;

    // weight conversion to tf32
    cvt_tf32_kernel<<<(nDD + 255) / 256, 256>>>(w_q, p_wq, nDD);
    cvt_tf32_kernel<<<(nDD + 255) / 256, 256>>>(w_k, p_wk, nDD);
    cvt_tf32_kernel<<<(nDD + 255) / 256, 256>>>(w_v, p_wv, nDD);
    cvt_tf32_kernel<<<(nDD + 255) / 256, 256>>>(w_o, p_wo, nDD);
    cvt_tf32_kernel<<<(nDF + 255) / 256, 256>>>(w1, p_w1, nDF);
    cvt_tf32_kernel<<<(nDF + 255) / 256, 256>>>(w3, p_w3, nDF);
    cvt_tf32_kernel<<<(nDF + 255) / 256, 256>>>(w2, p_w2, nDF);

    dim3 gD((DMODEL + BN - 1) / BN, NTOK / BM);   // 4 x 32
    dim3 gF((DFF + BN - 1) / BN, NTOK / BM);      // 11 x 32

    rmsnorm_kernel<<<NTOK, 256>>>(x, g1, p_xn);
    gemm_tc<<<gD, 256, gemm_smem>>>(p_xn, p_wq, p_q, nullptr, NTOK, DMODEL, DMODEL, 1);
    gemm_tc<<<gD, 256, gemm_smem>>>(p_xn, p_wk, p_k, nullptr, NTOK, DMODEL, DMODEL, 1);
    gemm_tc<<<gD, 256, gemm_smem>>>(p_xn, p_wv, p_v, nullptr, NTOK, DMODEL, DMODEL, 1);
    attn_tc<<<dim3(SEQ / ATQ, NHEADS, BATCH), 256, attn_smem>>>();
    gemm_tc<<<gD, 256, gemm_smem>>>(p_attn, p_wo, p_hres, x, NTOK, DMODEL, DMODEL, 0);
    rmsnorm_kernel<<<NTOK, 256>>>(p_hres, g2, p_hn);
    gemm_tc<<<gF, 256, gemm_smem>>>(p_hn, p_w1, p_ff1, nullptr, NTOK, DFF, DMODEL, 0);
    gemm_tc<<<gF, 256, gemm_smem>>>(p_hn, p_w3, p_ff3, nullptr, NTOK, DFF, DMODEL, 0);
    swiglu_kernel<<<(nTokFF + 255) / 256, 256>>>(p_ff1, p_ff3, nTokFF);
    gemm_tc<<<gD, 256, gemm_smem>>>(p_ff1, p_w2, out, p_hres, NTOK, DMODEL, DFF, 0);
}

// round 5
// speedup vs baseline: 6.0952x; 1.0117x over previous
#include <cuda_runtime.h>
#include <cuda_bf16.h>
#include <math.h>

#define BATCH 2
#define SEQ 2048
#define DMODEL 1024
#define NHEADS 16
#define DHEAD 64
#define DFF 2752
#define NTOK (BATCH * SEQ)
#define EPSV 1e-5f
#define NQKV 3072
#define NFF2 (2 * DFF)   // 5504

// ---------------- scratch ----------------
__device__ float g_xn   [NTOK * DMODEL];
__device__ float g_qkv  [NTOK * NQKV];
__device__ float g_attn [NTOK * DMODEL];
__device__ float g_hres [NTOK * DMODEL];
__device__ float g_hn   [NTOK * DMODEL];
__device__ float g_ff13 [NTOK * NFF2];
__device__ float g_ff1  [NTOK * DFF];
__device__ float g_wqkvT[NQKV * DMODEL];
__device__ float g_woT  [DMODEL * DMODEL];
__device__ float g_w13T [NFF2 * DMODEL];
__device__ float g_w2T  [DMODEL * DFF];

__device__ __forceinline__ float to_tf32(float x) {
    unsigned u;
    asm("cvt.rna.tf32.f32 %0, %1;" : "=r"(u) : "f"(x));
    return __uint_as_float(u);
}

__device__ __forceinline__ void mma_tf32(float c[4], const float a[4], const float b[2]) {
    asm volatile(
        "mma.sync.aligned.m16n8k8.row.col.f32.tf32.tf32.f32 "
        "{%0,%1,%2,%3}, {%4,%5,%6,%7}, {%8,%9}, {%0,%1,%2,%3};\n"
        : "+f"(c[0]), "+f"(c[1]), "+f"(c[2]), "+f"(c[3])
        : "r"(__float_as_uint(a[0])), "r"(__float_as_uint(a[1])),
          "r"(__float_as_uint(a[2])), "r"(__float_as_uint(a[3])),
          "r"(__float_as_uint(b[0])), "r"(__float_as_uint(b[1])));
}

__device__ __forceinline__ void cp_async16(float* smem_dst, const float* gsrc) {
    unsigned s = (unsigned)__cvta_generic_to_shared(smem_dst);
    asm volatile("cp.async.cg.shared.global [%0], [%1], 16;\n" :: "r"(s), "l"(gsrc));
}
__device__ __forceinline__ void cp_commit() {
    asm volatile("cp.async.commit_group;\n");
}

__device__ __forceinline__ void ldsm_x4(unsigned addr, float& r0, float& r1,
                                        float& r2, float& r3) {
    unsigned a, b, c, d;
    asm volatile("ldmatrix.sync.aligned.m8n8.x4.shared.b16 {%0,%1,%2,%3}, [%4];"
                 : "=r"(a), "=r"(b), "=r"(c), "=r"(d) : "r"(addr));
    r0 = __uint_as_float(a); r1 = __uint_as_float(b);
    r2 = __uint_as_float(c); r3 = __uint_as_float(d);
}

// ---------------- transpose + tf32-round weights: out[c][r] = tf32(in[r][c])
__global__ void cvtT_kernel(const float* __restrict__ in, float* __restrict__ out,
                            int R, int C) {
    __shared__ float t[32][33];
    int c0 = blockIdx.x * 32, r0 = blockIdx.y * 32;
    int tx = threadIdx.x, ty = threadIdx.y;
#pragma unroll
    for (int j = 0; j < 4; j++)
        t[ty + j * 8][tx] = in[(size_t)(r0 + ty + j * 8) * C + c0 + tx];
    __syncthreads();
#pragma unroll
    for (int j = 0; j < 4; j++)
        out[(size_t)(c0 + ty + j * 8) * R + r0 + tx] = to_tf32(t[tx][ty + j * 8]);
}

// ---------------- RMSNorm (tf32-rounded output) ----------------
__global__ void rmsnorm_kernel(const float* __restrict__ x,
                               const float* __restrict__ g,
                               float* __restrict__ y) {
    int row = blockIdx.x;
    const float* xr = x + (size_t)row * DMODEL;
    float* yr = y + (size_t)row * DMODEL;
    __shared__ float red[256];
    float s = 0.f;
    for (int i = threadIdx.x; i < DMODEL; i += 256) {
        float v = xr[i];
        s += v * v;
    }
    red[threadIdx.x] = s;
    __syncthreads();
    for (int st = 128; st > 0; st >>= 1) {
        if (threadIdx.x < st) red[threadIdx.x] += red[threadIdx.x + st];
        __syncthreads();
    }
    float inv = rsqrtf(red[0] * (1.0f / DMODEL) + EPSV);
    for (int i = threadIdx.x; i < DMODEL; i += 256)
        yr[i] = to_tf32(xr[i] * inv * g[i]);
}

// ---------------- tf32 GEMM, B pre-transposed: C = A @ BT^T (+R) ----------
// A[M][K] row-major, BT[N][K] row-major. 128x256 tile, cp.async 3 stages,
// ldmatrix fragment loads. 8 warps = 2m x 4n, warp tile 64x64.
#define BM 128
#define BN 256
#define BKK 16
#define ASTR 20
#define BTSTR 20
#define ASTAGE (BM * ASTR)      // 2560
#define BSTAGE (BN * BTSTR)     // 5120
#define GSMEM_FLOATS (3 * (ASTAGE + BSTAGE))   // 23040 -> 92160 B

__global__ __launch_bounds__(256)
void gemm_tc(const float* __restrict__ A, const float* __restrict__ BT,
             float* __restrict__ C, const float* __restrict__ R,
             int M, int N, int K, int round_out) {
    extern __shared__ float gsm[];
    float* As = gsm;
    float* Bs = gsm + 3 * ASTAGE;
    const unsigned smem_u = (unsigned)__cvta_generic_to_shared(gsm);

    const int tid = threadIdx.x;
    const int warp = tid >> 5, lane = tid & 31;
    const int gid = lane >> 2, tg = lane & 3;
    const int wm = warp >> 2, wn = warp & 3;
    const int lrow = lane & 15, lcol4 = (lane >> 4) << 2;
    const int rowBase = blockIdx.y * BM, colBase = blockIdx.x * BN;
    const bool partial = (colBase + BN > N);

    if (partial) {
        for (int i = tid; i < 3 * BSTAGE; i += 256) Bs[i] = 0.f;
        __syncthreads();
    }

    const float* Abase = A + (size_t)rowBase * K;
    const int nIter = K / BKK;

#define ISSUE_TILE(stage, k0)                                                          \
    do {                                                                               \
        float* as = As + (stage) * ASTAGE;                                             \
        float* bs = Bs + (stage) * BSTAGE;                                             \
        _Pragma("unroll")                                                              \
        for (int i = 0; i < 2; i++) {                                                  \
            int c = tid + i * 256;                                                     \
            int r = c >> 2, k4 = c & 3;                                                \
            cp_async16(as + r * ASTR + k4 * 4, Abase + (size_t)r * K + (k0) + k4 * 4); \
        }                                                                              \
        _Pragma("unroll")                                                              \
        for (int i = 0; i < 4; i++) {                                                  \
            int c = tid + i * 256;                                                     \
            int n = c >> 2, k4 = c & 3;                                                \
            if (colBase + n < N)                                                       \
                cp_async16(bs + n * BTSTR + k4 * 4,                                    \
                           BT + (size_t)(colBase + n) * K + (k0) + k4 * 4);            \
        }                                                                              \
        cp_commit();                                                                   \
    } while (0)

    ISSUE_TILE(0, 0);
    if (nIter > 1) ISSUE_TILE(1, 16);

    float acc[4][8][4];
#pragma unroll
    for (int i = 0; i < 4; i++)
#pragma unroll
        for (int j = 0; j < 8; j++)
#pragma unroll
            for (int q = 0; q < 4; q++) acc[i][j][q] = 0.f;

    // per-lane ldmatrix address offsets (in floats)
    const int aoff = (wm * 64 + lrow) * ASTR + lcol4;
    const int boff = (wn * 64 + lrow) * BTSTR + lcol4;

    for (int it = 0; it < nIter; it++) {
        if (it + 1 < nIter) {
            asm volatile("cp.async.wait_group 1;\n");
        } else {
            asm volatile("cp.async.wait_group 0;\n");
        }
        __syncthreads();
        if (it + 2 < nIter) ISSUE_TILE((it + 2) % 3, (it + 2) * BKK);

        const unsigned asu = smem_u + ((it % 3) * ASTAGE) * 4;
        const unsigned bsu = smem_u + (3 * ASTAGE + (it % 3) * BSTAGE) * 4;

#pragma unroll
        for (int ks = 0; ks < 2; ks++) {
            const int kk = ks * 8;
            float af[4][4];
#pragma unroll
            for (int mfi = 0; mfi < 4; mfi++)
                ldsm_x4(asu + (unsigned)(aoff + mfi * 16 * ASTR + kk) * 4,
                        af[mfi][0], af[mfi][1], af[mfi][2], af[mfi][3]);
            float bf[8][2];
#pragma unroll
            for (int nfp = 0; nfp < 4; nfp++)
                ldsm_x4(bsu + (unsigned)(boff + nfp * 16 * BTSTR + kk) * 4,
                        bf[2 * nfp][0], bf[2 * nfp + 1][0],
                        bf[2 * nfp][1], bf[2 * nfp + 1][1]);
#pragma unroll
            for (int mfi = 0; mfi < 4; mfi++)
#pragma unroll
                for (int nfi = 0; nfi < 8; nfi++)
                    mma_tf32(acc[mfi][nfi], af[mfi], bf[nfi]);
        }
        __syncthreads();
    }

#pragma unroll
    for (int mfi = 0; mfi < 4; mfi++) {
#pragma unroll
        for (int nfi = 0; nfi < 8; nfi++) {
            int r0 = rowBase + wm * 64 + mfi * 16 + gid;
            int c0 = colBase + wn * 64 + nfi * 8 + tg * 2;
            if (c0 < N) {
                float v0 = acc[mfi][nfi][0], v1 = acc[mfi][nfi][1];
                float v2 = acc[mfi][nfi][2], v3 = acc[mfi][nfi][3];
                if (R) {
                    v0 += R[(size_t)r0 * N + c0];
                    v1 += R[(size_t)r0 * N + c0 + 1];
                    v2 += R[(size_t)(r0 + 8) * N + c0];
                    v3 += R[(size_t)(r0 + 8) * N + c0 + 1];
                }
                if (round_out) {
                    v0 = to_tf32(v0); v1 = to_tf32(v1);
                    v2 = to_tf32(v2); v3 = to_tf32(v3);
                }
                *(float2*)&C[(size_t)r0 * N + c0] = make_float2(v0, v1);
                *(float2*)&C[(size_t)(r0 + 8) * N + c0] = make_float2(v2, v3);
            }
        }
    }
#undef ISSUE_TILE
}

// ---------------- tensor-core flash attention (reads packed qkv) ----------
#define ATQ 64
#define ACJ 128
#define QSTRD 72
#define KSTRD 72
#define VSTRD 72
#define SSTRD 132
#define ASM_FLOATS (ATQ * QSTRD + ACJ * KSTRD + ACJ * VSTRD + ATQ * SSTRD + 64 + 64 + 256 + 256)

__global__ __launch_bounds__(256)
void attn_tc() {
    extern __shared__ float sm[];
    float* Qm = sm;
    float* Kj = Qm + ATQ * QSTRD;
    float* Vs = Kj + ACJ * KSTRD;
    float* Ss = Vs + ACJ * VSTRD;
    float* rowf = Ss + ATQ * SSTRD;
    float* rowinv = rowf + 64;
    float* red1 = rowinv + 64;
    float* red2 = red1 + 256;

    const int tid = threadIdx.x;
    const int warp = tid >> 5, lane = tid & 31;
    const int gid = lane >> 2, tg = lane & 3;
    const int wm = warp >> 2, wn = warp & 3;
    const int wm2 = warp >> 1, wn2 = warp & 1;
    const int sr = tid >> 2, sq = tid & 3;

    const int qt = blockIdx.x, h = blockIdx.y, b = blockIdx.z;
    const int q0 = qt * ATQ;

    const float* qg = g_qkv + (size_t)b * SEQ * NQKV + h * DHEAD;
    const float* kg = qg + DMODEL;
    const float* vg = qg + 2 * DMODEL;

#pragma unroll
    for (int i = 0; i < 4; i++) {
        int c = tid + i * 256;
        int r = c >> 4, db = c & 15;
        float4 v = *(const float4*)(qg + (size_t)(q0 + r) * NQKV + db * 4);
        v.x *= 0.125f; v.y *= 0.125f; v.z *= 0.125f; v.w *= 0.125f;
        *(float4*)&Qm[r * QSTRD + db * 4] = v;
    }

    float o[4][4];
#pragma unroll
    for (int i = 0; i < 4; i++)
#pragma unroll
        for (int j = 0; j < 4; j++) o[i][j] = 0.f;
    float m_r = -1e30f, l_r = 0.f;

    __syncthreads();

    const int nchunks = (q0 + ATQ + ACJ - 1) / ACJ;
    for (int c = 0; c < nchunks; c++) {
        const int j0 = c * ACJ;
        if (c) __syncthreads();

#pragma unroll
        for (int i = 0; i < 8; i++) {
            int cc = tid + i * 256;
            int j = cc >> 4, db = cc & 15;
            *(float4*)&Kj[j * KSTRD + db * 4] =
                *(const float4*)(kg + (size_t)(j0 + j) * NQKV + db * 4);
            *(float4*)&Vs[j * VSTRD + db * 4] =
                *(const float4*)(vg + (size_t)(j0 + j) * NQKV + db * 4);
        }
        __syncthreads();

        float sacc[2][4][4];
#pragma unroll
        for (int i = 0; i < 2; i++)
#pragma unroll
            for (int j = 0; j < 4; j++)
#pragma unroll
                for (int q = 0; q < 4; q++) sacc[i][j][q] = 0.f;
#pragma unroll
        for (int kk = 0; kk < 64; kk += 8) {
            float af[2][4];
#pragma unroll
            for (int mfi = 0; mfi < 2; mfi++) {
                int m0 = wm * 32 + mfi * 16;
                af[mfi][0] = Qm[(m0 + gid) * QSTRD + kk + tg];
                af[mfi][1] = Qm[(m0 + gid + 8) * QSTRD + kk + tg];
                af[mfi][2] = Qm[(m0 + gid) * QSTRD + kk + tg + 4];
                af[mfi][3] = Qm[(m0 + gid + 8) * QSTRD + kk + tg + 4];
            }
            float bf[4][2];
#pragma unroll
            for (int nfi = 0; nfi < 4; nfi++) {
                int n0 = wn * 32 + nfi * 8 + gid;
                bf[nfi][0] = Kj[n0 * KSTRD + kk + tg];
                bf[nfi][1] = Kj[n0 * KSTRD + kk + tg + 4];
            }
#pragma unroll
            for (int mfi = 0; mfi < 2; mfi++)
#pragma unroll
                for (int nfi = 0; nfi < 4; nfi++)
                    mma_tf32(sacc[mfi][nfi], af[mfi], bf[nfi]);
        }
#pragma unroll
        for (int mfi = 0; mfi < 2; mfi++)
#pragma unroll
            for (int nfi = 0; nfi < 4; nfi++) {
                int r0 = wm * 32 + mfi * 16 + gid;
                int c0 = wn * 32 + nfi * 8 + tg * 2;
                *(float2*)&Ss[r0 * SSTRD + c0] = make_float2(sacc[mfi][nfi][0], sacc[mfi][nfi][1]);
                *(float2*)&Ss[(r0 + 8) * SSTRD + c0] = make_float2(sacc[mfi][nfi][2], sacc[mfi][nfi][3]);
            }
        __syncthreads();

        int nv = q0 + sr - j0 + 1;
        if (nv > ACJ) nv = ACJ;
        const int jb = sq * 32;
        float msg = -1e30f;
        for (int i = 0; i < 32; i++) {
            int j = jb + i;
            if (j < nv) msg = fmaxf(msg, Ss[sr * SSTRD + j]);
        }
        red1[sq * 64 + sr] = msg;
        __syncthreads();
        float mnew = fmaxf(fmaxf(fmaxf(red1[sr], red1[64 + sr]),
                                 fmaxf(red1[128 + sr], red1[192 + sr])), m_r);
        float corr = __expf(m_r - mnew);
        float psum = 0.f;
        for (int i = 0; i < 32; i++) {
            int j = jb + i;
            float p = 0.f;
            if (j < nv) {
                p = to_tf32(__expf(Ss[sr * SSTRD + j] - mnew));
                psum += p;
            }
            Ss[sr * SSTRD + j] = p;
        }
        red2[sq * 64 + sr] = psum;
        if (sq == 0) rowf[sr] = corr;
        __syncthreads();
        l_r = l_r * corr + red2[sr] + red2[64 + sr] + red2[128 + sr] + red2[192 + sr];
        m_r = mnew;

        const int m0p = wm2 * 16;
        float cg = rowf[m0p + gid], cg8 = rowf[m0p + gid + 8];
#pragma unroll
        for (int nfi = 0; nfi < 4; nfi++) {
            o[nfi][0] *= cg;  o[nfi][1] *= cg;
            o[nfi][2] *= cg8; o[nfi][3] *= cg8;
        }
#pragma unroll
        for (int kk = 0; kk < ACJ; kk += 8) {
            float paf[4];
            paf[0] = Ss[(m0p + gid) * SSTRD + kk + tg];
            paf[1] = Ss[(m0p + gid + 8) * SSTRD + kk + tg];
            paf[2] = Ss[(m0p + gid) * SSTRD + kk + tg + 4];
            paf[3] = Ss[(m0p + gid + 8) * SSTRD + kk + tg + 4];
            float bvf[4][2];
#pragma unroll
            for (int nfi = 0; nfi < 4; nfi++) {
                int n0 = wn2 * 32 + nfi * 8 + gid;
                bvf[nfi][0] = Vs[(kk + tg) * VSTRD + n0];
                bvf[nfi][1] = Vs[(kk + tg + 4) * VSTRD + n0];
            }
#pragma unroll
            for (int nfi = 0; nfi < 4; nfi++)
                mma_tf32(o[nfi], paf, bvf[nfi]);
        }
    }

    if (sq == 0) rowinv[sr] = 1.0f / l_r;
    __syncthreads();

    const int m0p = wm2 * 16;
    float iv = rowinv[m0p + gid], iv8 = rowinv[m0p + gid + 8];
#pragma unroll
    for (int nfi = 0; nfi < 4; nfi++) {
        int c0 = wn2 * 32 + nfi * 8 + tg * 2;
        int r0 = q0 + m0p + gid;
        float* dst = g_attn + ((size_t)(b * SEQ + r0)) * DMODEL + h * DHEAD + c0;
        *(float2*)dst = make_float2(to_tf32(o[nfi][0] * iv), to_tf32(o[nfi][1] * iv));
        float* dst8 = dst + 8 * DMODEL;
        *(float2*)dst8 = make_float2(to_tf32(o[nfi][2] * iv8), to_tf32(o[nfi][3] * iv8));
    }
}

// ---------------- swiglu on fused ff13 buffer ----------------
__global__ void swiglu_kernel(const float* __restrict__ ff13,
                              float* __restrict__ gate) {
    int c = blockIdx.x * 256 + threadIdx.x;
    int r = blockIdx.y;
    if (c < DFF) {
        float v = ff13[(size_t)r * NFF2 + c];
        float x3 = ff13[(size_t)r * NFF2 + DFF + c];
        float s = v / (1.f + __expf(-v));
        gate[(size_t)r * DFF + c] = to_tf32(s * x3);
    }
}

// ---------------- launch ----------------
extern "C" void kernel_launch(void* const* d_in, const int* in_sizes, int n_in,
                              void* d_out, int out_size) {
    const float* x   = (const float*)d_in[0];
    const float* g1  = (const float*)d_in[1];
    const float* g2  = (const float*)d_in[2];
    const float* w_q = (const float*)d_in[3];
    const float* w_k = (const float*)d_in[4];
    const float* w_v = (const float*)d_in[5];
    const float* w_o = (const float*)d_in[6];
    const float* w1  = (const float*)d_in[7];
    const float* w2  = (const float*)d_in[8];
    const float* w3  = (const float*)d_in[9];
    float* out = (float*)d_out;

    float *p_xn, *p_qkv, *p_attn, *p_hres, *p_hn, *p_ff13, *p_ff1;
    float *p_wqkvT, *p_woT, *p_w13T, *p_w2T;
    cudaGetSymbolAddress((void**)&p_xn,    g_xn);
    cudaGetSymbolAddress((void**)&p_qkv,   g_qkv);
    cudaGetSymbolAddress((void**)&p_attn,  g_attn);
    cudaGetSymbolAddress((void**)&p_hres,  g_hres);
    cudaGetSymbolAddress((void**)&p_hn,    g_hn);
    cudaGetSymbolAddress((void**)&p_ff13,  g_ff13);
    cudaGetSymbolAddress((void**)&p_ff1,   g_ff1);
    cudaGetSymbolAddress((void**)&p_wqkvT, g_wqkvT);
    cudaGetSymbolAddress((void**)&p_woT,   g_woT);
    cudaGetSymbolAddress((void**)&p_w13T,  g_w13T);
    cudaGetSymbolAddress((void**)&p_w2T,   g_w2T);

    static int attr_set = 0;
    const int gemm_smem = GSMEM_FLOATS * 4;
    const int attn_smem = ASM_FLOATS * 4;
    if (!attr_set) {
        cudaFuncSetAttribute(gemm_tc, cudaFuncAttributeMaxDynamicSharedMemorySize, gemm_smem);
        cudaFuncSetAttribute(attn_tc, cudaFuncAttributeMaxDynamicSharedMemorySize, attn_smem);
        attr_set = 1;
    }

    dim3 tb(32, 8);
    // packed QKV^T: rows 0..1023 = wq^T, 1024.. = wk^T, 2048.. = wv^T
    cvtT_kernel<<<dim3(32, 32), tb>>>(w_q, p_wqkvT, DMODEL, DMODEL);
    cvtT_kernel<<<dim3(32, 32), tb>>>(w_k, p_wqkvT + DMODEL * DMODEL, DMODEL, DMODEL);
    cvtT_kernel<<<dim3(32, 32), tb>>>(w_v, p_wqkvT + 2 * DMODEL * DMODEL, DMODEL, DMODEL);
    cvtT_kernel<<<dim3(32, 32), tb>>>(w_o, p_woT, DMODEL, DMODEL);
    // packed FF^T: rows 0..2751 = w1^T, 2752.. = w3^T
    cvtT_kernel<<<dim3(DFF / 32, 32), tb>>>(w1, p_w13T, DMODEL, DFF);
    cvtT_kernel<<<dim3(DFF / 32, 32), tb>>>(w3, p_w13T + DFF * DMODEL, DMODEL, DFF);
    cvtT_kernel<<<dim3(32, DFF / 32), tb>>>(w2, p_w2T, DFF, DMODEL);

    rmsnorm_kernel<<<NTOK, 256>>>(x, g1, p_xn);
    gemm_tc<<<dim3(NQKV / BN, NTOK / BM), 256, gemm_smem>>>(
        p_xn, p_wqkvT, p_qkv, nullptr, NTOK, NQKV, DMODEL, 1);
    attn_tc<<<dim3(SEQ / ATQ, NHEADS, BATCH), 256, attn_smem>>>();
    gemm_tc<<<dim3(DMODEL / BN, NTOK / BM), 256, gemm_smem>>>(
        p_attn, p_woT, p_hres, x, NTOK, DMODEL, DMODEL, 0);
    rmsnorm_kernel<<<NTOK, 256>>>(p_hres, g2, p_hn);
    gemm_tc<<<dim3((NFF2 + BN - 1) / BN, NTOK / BM), 256, gemm_smem>>>(
        p_hn, p_w13T, p_ff13, nullptr, NTOK, NFF2, DMODEL, 0);
    swiglu_kernel<<<dim3((DFF + 255) / 256, NTOK), 256>>>(p_ff13, p_ff1);
    gemm_tc<<<dim3(DMODEL / BN, NTOK / BM), 256, gemm_smem>>>(
        p_ff1, p_w2T, out, p_hres, NTOK, DMODEL, DFF, 0);
}

// round 7
// speedup vs baseline: 8.7112x; 1.4292x over previous
#include <cuda_runtime.h>
#include <cuda_fp16.h>
#include <math.h>
#include <stdint.h>

#define BATCH 2
#define SEQ 2048
#define DMODEL 1024
#define NHEADS 16
#define DHEAD 64
#define DFF 2752
#define NTOK (BATCH * SEQ)
#define EPSV 1e-5f
#define NQKV 3072
#define NFF2P 5632          // padded 2*DFF to multiple of 256
#define FFPAD 2816          // offset of w3 half within padded buffer

// ---------------- scratch ----------------
__device__ __half g_xn   [NTOK * DMODEL];
__device__ float  g_qkv  [NTOK * NQKV];
__device__ __half g_attnH[NTOK * DMODEL];
__device__ float  g_hres [NTOK * DMODEL];
__device__ __half g_hn   [NTOK * DMODEL];
__device__ float  g_ff13 [NTOK * NFF2P];
__device__ __half g_ff1  [NTOK * DFF];
__device__ __half g_wqkvT[NQKV * DMODEL];
__device__ __half g_woT  [DMODEL * DMODEL];
__device__ __half g_w13T [NFF2P * DMODEL];
__device__ __half g_w2T  [DMODEL * DFF];

// ---------------- helpers ----------------
__device__ __forceinline__ float to_tf32(float x) {
    unsigned u;
    asm("cvt.rna.tf32.f32 %0, %1;" : "=r"(u) : "f"(x));
    return __uint_as_float(u);
}

__device__ __forceinline__ void mma_tf32(float c[4], const float a[4], const float b[2]) {
    asm volatile(
        "mma.sync.aligned.m16n8k8.row.col.f32.tf32.tf32.f32 "
        "{%0,%1,%2,%3}, {%4,%5,%6,%7}, {%8,%9}, {%0,%1,%2,%3};\n"
        : "+f"(c[0]), "+f"(c[1]), "+f"(c[2]), "+f"(c[3])
        : "r"(__float_as_uint(a[0])), "r"(__float_as_uint(a[1])),
          "r"(__float_as_uint(a[2])), "r"(__float_as_uint(a[3])),
          "r"(__float_as_uint(b[0])), "r"(__float_as_uint(b[1])));
}

__device__ __forceinline__ void mma_f16(float c[4], const uint32_t a[4], const uint32_t b[2]) {
    asm volatile(
        "mma.sync.aligned.m16n8k16.row.col.f32.f16.f16.f32 "
        "{%0,%1,%2,%3}, {%4,%5,%6,%7}, {%8,%9}, {%0,%1,%2,%3};\n"
        : "+f"(c[0]), "+f"(c[1]), "+f"(c[2]), "+f"(c[3])
        : "r"(a[0]), "r"(a[1]), "r"(a[2]), "r"(a[3]), "r"(b[0]), "r"(b[1]));
}

__device__ __forceinline__ void cp_async16(void* smem_dst, const void* gsrc) {
    unsigned s = (unsigned)__cvta_generic_to_shared(smem_dst);
    asm volatile("cp.async.cg.shared.global [%0], [%1], 16;\n" :: "r"(s), "l"(gsrc));
}
__device__ __forceinline__ void cp_commit() {
    asm volatile("cp.async.commit_group;\n");
}

__device__ __forceinline__ void ldsm4(uint32_t addr, uint32_t& r0, uint32_t& r1,
                                      uint32_t& r2, uint32_t& r3) {
    asm volatile("ldmatrix.sync.aligned.m8n8.x4.shared.b16 {%0,%1,%2,%3}, [%4];"
                 : "=r"(r0), "=r"(r1), "=r"(r2), "=r"(r3) : "r"(addr));
}

// ---------------- transpose + fp16 weights: out[c][r] = half(in[r][c]) ----
__global__ void cvtT_kernel(const float* __restrict__ in, __half* __restrict__ out,
                            int R, int C) {
    __shared__ float t[32][33];
    int c0 = blockIdx.x * 32, r0 = blockIdx.y * 32;
    int tx = threadIdx.x, ty = threadIdx.y;
#pragma unroll
    for (int j = 0; j < 4; j++)
        t[ty + j * 8][tx] = in[(size_t)(r0 + ty + j * 8) * C + c0 + tx];
    __syncthreads();
#pragma unroll
    for (int j = 0; j < 4; j++)
        out[(size_t)(c0 + ty + j * 8) * R + r0 + tx] = __float2half(t[tx][ty + j * 8]);
}

// ---------------- RMSNorm -> fp16 ----------------
__global__ void rmsnorm_kernel(const float* __restrict__ x,
                               const float* __restrict__ g,
                               __half* __restrict__ y) {
    int row = blockIdx.x;
    const float* xr = x + (size_t)row * DMODEL;
    __half* yr = y + (size_t)row * DMODEL;
    __shared__ float red[256];
    float s = 0.f;
    for (int i = threadIdx.x; i < DMODEL; i += 256) {
        float v = xr[i];
        s += v * v;
    }
    red[threadIdx.x] = s;
    __syncthreads();
    for (int st = 128; st > 0; st >>= 1) {
        if (threadIdx.x < st) red[threadIdx.x] += red[threadIdx.x + st];
        __syncthreads();
    }
    float inv = rsqrtf(red[0] * (1.0f / DMODEL) + EPSV);
    for (int i = threadIdx.x; i < DMODEL; i += 256)
        yr[i] = __float2half(xr[i] * inv * g[i]);
}

// ---------------- fp16 GEMM: C[M][N] = A[M][K] @ BT[N][K]^T (+R) ----------
// 128x256 tile, BK=32 halves, 3-stage cp.async, ldmatrix.x4 fragments.
// 8 warps = 2m x 4n, warp tile 64x64, mma m16n8k16.
#define BM 128
#define BN 256
#define BK 32
#define HSTR 40                      // halves per smem row (80 B, conflict-free)
#define ASTG_H (BM * HSTR)           // 5120 halves = 10240 B
#define BSTG_H (BN * HSTR)           // 10240 halves = 20480 B
#define GH_SMEM ((3 * (ASTG_H + BSTG_H)) * 2)   // 92160 B

__global__ __launch_bounds__(256)
void gemm_h(const __half* __restrict__ A, const __half* __restrict__ BT,
            float* __restrict__ C, const float* __restrict__ R,
            int N, int K, int round_out) {
    extern __shared__ __half hsm[];
    __half* As = hsm;
    __half* Bs = hsm + 3 * ASTG_H;
    const uint32_t sbase = (uint32_t)__cvta_generic_to_shared(hsm);

    const int tid = threadIdx.x;
    const int warp = tid >> 5, lane = tid & 31;
    const int gid = lane >> 2, tg = lane & 3;
    const int wm = warp >> 2, wn = warp & 3;
    const int ttile = lane >> 3, trow = lane & 7;
    const int rowBase = blockIdx.y * BM, colBase = blockIdx.x * BN;

    const __half* Abase = A + (size_t)rowBase * K;
    const __half* Bbase = BT + (size_t)colBase * K;
    const int nst = K / BK;

#define ISSUE_STAGE(s, k0)                                                       \
    do {                                                                         \
        __half* as = As + (s) * ASTG_H;                                          \
        __half* bs = Bs + (s) * BSTG_H;                                          \
        _Pragma("unroll")                                                        \
        for (int i = 0; i < 2; i++) {                                            \
            int c = tid + i * 256;                                               \
            int r = c >> 2, ch = c & 3;                                          \
            cp_async16(as + r * HSTR + ch * 8, Abase + (size_t)r * K + (k0) + ch * 8); \
        }                                                                        \
        _Pragma("unroll")                                                        \
        for (int i = 0; i < 4; i++) {                                            \
            int c = tid + i * 256;                                               \
            int n = c >> 2, ch = c & 3;                                          \
            cp_async16(bs + n * HSTR + ch * 8, Bbase + (size_t)n * K + (k0) + ch * 8); \
        }                                                                        \
        cp_commit();                                                             \
    } while (0)

    ISSUE_STAGE(0, 0);
    if (nst > 1) ISSUE_STAGE(1, BK);

    float acc[4][8][4];
#pragma unroll
    for (int i = 0; i < 4; i++)
#pragma unroll
        for (int j = 0; j < 8; j++)
#pragma unroll
            for (int q = 0; q < 4; q++) acc[i][j][q] = 0.f;

    // ldmatrix per-lane row/koff within tile group
    const int frag_m = (ttile & 1) * 8 + trow;   // row within 16-row block
    const int frag_k = (ttile >> 1) * 8;         // k offset within 16-k step

    for (int it = 0; it < nst; it++) {
        if (it + 1 < nst) {
            asm volatile("cp.async.wait_group 1;\n");
        } else {
            asm volatile("cp.async.wait_group 0;\n");
        }
        __syncthreads();
        if (it + 2 < nst) ISSUE_STAGE((it + 2) % 3, (it + 2) * BK);

        const uint32_t asu = sbase + ((it % 3) * ASTG_H) * 2;
        const uint32_t bsu = sbase + (3 * ASTG_H + (it % 3) * BSTG_H) * 2;

#pragma unroll
        for (int ks = 0; ks < 2; ks++) {
            const int kk = ks * 16;
            uint32_t af[4][4];
#pragma unroll
            for (int mfi = 0; mfi < 4; mfi++) {
                int m0 = wm * 64 + mfi * 16;
                ldsm4(asu + (uint32_t)((m0 + frag_m) * HSTR + kk + frag_k) * 2,
                      af[mfi][0], af[mfi][1], af[mfi][2], af[mfi][3]);
            }
            uint32_t bf[8][2];
#pragma unroll
            for (int nfp = 0; nfp < 4; nfp++) {
                int n0 = wn * 64 + nfp * 16;
                ldsm4(bsu + (uint32_t)((n0 + frag_m) * HSTR + kk + frag_k) * 2,
                      bf[2 * nfp][0], bf[2 * nfp + 1][0],
                      bf[2 * nfp][1], bf[2 * nfp + 1][1]);
            }
#pragma unroll
            for (int mfi = 0; mfi < 4; mfi++)
#pragma unroll
                for (int nfi = 0; nfi < 8; nfi++)
                    mma_f16(acc[mfi][nfi], af[mfi], bf[nfi]);
        }
        __syncthreads();
    }
#undef ISSUE_STAGE

#pragma unroll
    for (int mfi = 0; mfi < 4; mfi++) {
#pragma unroll
        for (int nfi = 0; nfi < 8; nfi++) {
            int r0 = rowBase + wm * 64 + mfi * 16 + gid;
            int c0 = colBase + wn * 64 + nfi * 8 + tg * 2;
            float v0 = acc[mfi][nfi][0], v1 = acc[mfi][nfi][1];
            float v2 = acc[mfi][nfi][2], v3 = acc[mfi][nfi][3];
            if (R) {
                v0 += R[(size_t)r0 * N + c0];
                v1 += R[(size_t)r0 * N + c0 + 1];
                v2 += R[(size_t)(r0 + 8) * N + c0];
                v3 += R[(size_t)(r0 + 8) * N + c0 + 1];
            }
            if (round_out) {
                v0 = to_tf32(v0); v1 = to_tf32(v1);
                v2 = to_tf32(v2); v3 = to_tf32(v3);
            }
            *(float2*)&C[(size_t)r0 * N + c0] = make_float2(v0, v1);
            *(float2*)&C[(size_t)(r0 + 8) * N + c0] = make_float2(v2, v3);
        }
    }
}

// ---------------- tensor-core flash attention (tf32, fp16 output) ---------
#define ATQ 64
#define ACJ 128
#define QSTRD 72
#define KSTRD 72
#define VSTRD 72
#define SSTRD 132
#define ASM_FLOATS (ATQ * QSTRD + ACJ * KSTRD + ACJ * VSTRD + ATQ * SSTRD + 64 + 64 + 256 + 256)

__global__ __launch_bounds__(256)
void attn_tc() {
    extern __shared__ float sm[];
    float* Qm = sm;
    float* Kj = Qm + ATQ * QSTRD;
    float* Vs = Kj + ACJ * KSTRD;
    float* Ss = Vs + ACJ * VSTRD;
    float* rowf = Ss + ATQ * SSTRD;
    float* rowinv = rowf + 64;
    float* red1 = rowinv + 64;
    float* red2 = red1 + 256;

    const int tid = threadIdx.x;
    const int warp = tid >> 5, lane = tid & 31;
    const int gid = lane >> 2, tg = lane & 3;
    const int wm = warp >> 2, wn = warp & 3;
    const int wm2 = warp >> 1, wn2 = warp & 1;
    const int sr = tid >> 2, sq = tid & 3;

    const int qt = blockIdx.x, h = blockIdx.y, b = blockIdx.z;
    const int q0 = qt * ATQ;

    const float* qg = g_qkv + (size_t)b * SEQ * NQKV + h * DHEAD;
    const float* kg = qg + DMODEL;
    const float* vg = qg + 2 * DMODEL;

#pragma unroll
    for (int i = 0; i < 4; i++) {
        int c = tid + i * 256;
        int r = c >> 4, db = c & 15;
        float4 v = *(const float4*)(qg + (size_t)(q0 + r) * NQKV + db * 4);
        v.x *= 0.125f; v.y *= 0.125f; v.z *= 0.125f; v.w *= 0.125f;
        *(float4*)&Qm[r * QSTRD + db * 4] = v;
    }

    float o[4][4];
#pragma unroll
    for (int i = 0; i < 4; i++)
#pragma unroll
        for (int j = 0; j < 4; j++) o[i][j] = 0.f;
    float m_r = -1e30f, l_r = 0.f;

    __syncthreads();

    const int nchunks = (q0 + ATQ + ACJ - 1) / ACJ;
    for (int c = 0; c < nchunks; c++) {
        const int j0 = c * ACJ;
        if (c) __syncthreads();

#pragma unroll
        for (int i = 0; i < 8; i++) {
            int cc = tid + i * 256;
            int j = cc >> 4, db = cc & 15;
            *(float4*)&Kj[j * KSTRD + db * 4] =
                *(const float4*)(kg + (size_t)(j0 + j) * NQKV + db * 4);
            *(float4*)&Vs[j * VSTRD + db * 4] =
                *(const float4*)(vg + (size_t)(j0 + j) * NQKV + db * 4);
        }
        __syncthreads();

        float sacc[2][4][4];
#pragma unroll
        for (int i = 0; i < 2; i++)
#pragma unroll
            for (int j = 0; j < 4; j++)
#pragma unroll
                for (int q = 0; q < 4; q++) sacc[i][j][q] = 0.f;
#pragma unroll
        for (int kk = 0; kk < 64; kk += 8) {
            float af[2][4];
#pragma unroll
            for (int mfi = 0; mfi < 2; mfi++) {
                int m0 = wm * 32 + mfi * 16;
                af[mfi][0] = Qm[(m0 + gid) * QSTRD + kk + tg];
                af[mfi][1] = Qm[(m0 + gid + 8) * QSTRD + kk + tg];
                af[mfi][2] = Qm[(m0 + gid) * QSTRD + kk + tg + 4];
                af[mfi][3] = Qm[(m0 + gid + 8) * QSTRD + kk + tg + 4];
            }
            float bf[4][2];
#pragma unroll
            for (int nfi = 0; nfi < 4; nfi++) {
                int n0 = wn * 32 + nfi * 8 + gid;
                bf[nfi][0] = Kj[n0 * KSTRD + kk + tg];
                bf[nfi][1] = Kj[n0 * KSTRD + kk + tg + 4];
            }
#pragma unroll
            for (int mfi = 0; mfi < 2; mfi++)
#pragma unroll
                for (int nfi = 0; nfi < 4; nfi++)
                    mma_tf32(sacc[mfi][nfi], af[mfi], bf[nfi]);
        }
#pragma unroll
        for (int mfi = 0; mfi < 2; mfi++)
#pragma unroll
            for (int nfi = 0; nfi < 4; nfi++) {
                int r0 = wm * 32 + mfi * 16 + gid;
                int c0 = wn * 32 + nfi * 8 + tg * 2;
                *(float2*)&Ss[r0 * SSTRD + c0] = make_float2(sacc[mfi][nfi][0], sacc[mfi][nfi][1]);
                *(float2*)&Ss[(r0 + 8) * SSTRD + c0] = make_float2(sacc[mfi][nfi][2], sacc[mfi][nfi][3]);
            }
        __syncthreads();

        int nv = q0 + sr - j0 + 1;
        if (nv > ACJ) nv = ACJ;
        const int jb = sq * 32;
        float msg = -1e30f;
        for (int i = 0; i < 32; i++) {
            int j = jb + i;
            if (j < nv) msg = fmaxf(msg, Ss[sr * SSTRD + j]);
        }
        red1[sq * 64 + sr] = msg;
        __syncthreads();
        float mnew = fmaxf(fmaxf(fmaxf(red1[sr], red1[64 + sr]),
                                 fmaxf(red1[128 + sr], red1[192 + sr])), m_r);
        float corr = __expf(m_r - mnew);
        float psum = 0.f;
        for (int i = 0; i < 32; i++) {
            int j = jb + i;
            float p = 0.f;
            if (j < nv) {
                p = to_tf32(__expf(Ss[sr * SSTRD + j] - mnew));
                psum += p;
            }
            Ss[sr * SSTRD + j] = p;
        }
        red2[sq * 64 + sr] = psum;
        if (sq == 0) rowf[sr] = corr;
        __syncthreads();
        l_r = l_r * corr + red2[sr] + red2[64 + sr] + red2[128 + sr] + red2[192 + sr];
        m_r = mnew;

        const int m0p = wm2 * 16;
        float cg = rowf[m0p + gid], cg8 = rowf[m0p + gid + 8];
#pragma unroll
        for (int nfi = 0; nfi < 4; nfi++) {
            o[nfi][0] *= cg;  o[nfi][1] *= cg;
            o[nfi][2] *= cg8; o[nfi][3] *= cg8;
        }
#pragma unroll
        for (int kk = 0; kk < ACJ; kk += 8) {
            float paf[4];
            paf[0] = Ss[(m0p + gid) * SSTRD + kk + tg];
            paf[1] = Ss[(m0p + gid + 8) * SSTRD + kk + tg];
            paf[2] = Ss[(m0p + gid) * SSTRD + kk + tg + 4];
            paf[3] = Ss[(m0p + gid + 8) * SSTRD + kk + tg + 4];
            float bvf[4][2];
#pragma unroll
            for (int nfi = 0; nfi < 4; nfi++) {
                int n0 = wn2 * 32 + nfi * 8 + gid;
                bvf[nfi][0] = Vs[(kk + tg) * VSTRD + n0];
                bvf[nfi][1] = Vs[(kk + tg + 4) * VSTRD + n0];
            }
#pragma unroll
            for (int nfi = 0; nfi < 4; nfi++)
                mma_tf32(o[nfi], paf, bvf[nfi]);
        }
    }

    if (sq == 0) rowinv[sr] = 1.0f / l_r;
    __syncthreads();

    const int m0p = wm2 * 16;
    float iv = rowinv[m0p + gid], iv8 = rowinv[m0p + gid + 8];
#pragma unroll
    for (int nfi = 0; nfi < 4; nfi++) {
        int c0 = wn2 * 32 + nfi * 8 + tg * 2;
        int r0 = q0 + m0p + gid;
        __half* dst = g_attnH + ((size_t)(b * SEQ + r0)) * DMODEL + h * DHEAD + c0;
        dst[0] = __float2half(o[nfi][0] * iv);
        dst[1] = __float2half(o[nfi][1] * iv);
        __half* dst8 = dst + 8 * DMODEL;
        dst8[0] = __float2half(o[nfi][2] * iv8);
        dst8[1] = __float2half(o[nfi][3] * iv8);
    }
}

// ---------------- swiglu: fp32 fused ff13 -> fp16 gate -------------------
__global__ void swiglu_kernel(const float* __restrict__ ff13,
                              __half* __restrict__ gate) {
    int c = blockIdx.x * 256 + threadIdx.x;
    int r = blockIdx.y;
    if (c < DFF) {
        float v = ff13[(size_t)r * NFF2P + c];
        float x3 = ff13[(size_t)r * NFF2P + FFPAD + c];
        float s = v / (1.f + __expf(-v));
        gate[(size_t)r * DFF + c] = __float2half(s * x3);
    }
}

// ---------------- launch ----------------
extern "C" void kernel_launch(void* const* d_in, const int* in_sizes, int n_in,
                              void* d_out, int out_size) {
    const float* x   = (const float*)d_in[0];
    const float* g1  = (const float*)d_in[1];
    const float* g2  = (const float*)d_in[2];
    const float* w_q = (const float*)d_in[3];
    const float* w_k = (const float*)d_in[4];
    const float* w_v = (const float*)d_in[5];
    const float* w_o = (const float*)d_in[6];
    const float* w1  = (const float*)d_in[7];
    const float* w2  = (const float*)d_in[8];
    const float* w3  = (const float*)d_in[9];
    float* out = (float*)d_out;

    __half *p_xn, *p_attnH, *p_hn, *p_ff1, *p_wqkvT, *p_woT, *p_w13T, *p_w2T;
    float *p_qkv, *p_hres, *p_ff13;
    cudaGetSymbolAddress((void**)&p_xn,    g_xn);
    cudaGetSymbolAddress((void**)&p_qkv,   g_qkv);
    cudaGetSymbolAddress((void**)&p_attnH, g_attnH);
    cudaGetSymbolAddress((void**)&p_hres,  g_hres);
    cudaGetSymbolAddress((void**)&p_hn,    g_hn);
    cudaGetSymbolAddress((void**)&p_ff13,  g_ff13);
    cudaGetSymbolAddress((void**)&p_ff1,   g_ff1);
    cudaGetSymbolAddress((void**)&p_wqkvT, g_wqkvT);
    cudaGetSymbolAddress((void**)&p_woT,   g_woT);
    cudaGetSymbolAddress((void**)&p_w13T,  g_w13T);
    cudaGetSymbolAddress((void**)&p_w2T,   g_w2T);

    static int attr_set = 0;
    const int attn_smem = ASM_FLOATS * 4;
    if (!attr_set) {
        cudaFuncSetAttribute(gemm_h, cudaFuncAttributeMaxDynamicSharedMemorySize, GH_SMEM);
        cudaFuncSetAttribute(attn_tc, cudaFuncAttributeMaxDynamicSharedMemorySize, attn_smem);
        attr_set = 1;
    }

    dim3 tb(32, 8);
    // packed QKV^T (half): rows 0..1023 = wq^T, 1024.. = wk^T, 2048.. = wv^T
    cvtT_kernel<<<dim3(32, 32), tb>>>(w_q, p_wqkvT, DMODEL, DMODEL);
    cvtT_kernel<<<dim3(32, 32), tb>>>(w_k, p_wqkvT + DMODEL * DMODEL, DMODEL, DMODEL);
    cvtT_kernel<<<dim3(32, 32), tb>>>(w_v, p_wqkvT + 2 * DMODEL * DMODEL, DMODEL, DMODEL);
    cvtT_kernel<<<dim3(32, 32), tb>>>(w_o, p_woT, DMODEL, DMODEL);
    // padded FF^T: rows 0..2751 = w1^T, rows 2816..5567 = w3^T
    cvtT_kernel<<<dim3(DFF / 32, 32), tb>>>(w1, p_w13T, DMODEL, DFF);
    cvtT_kernel<<<dim3(DFF / 32, 32), tb>>>(w3, p_w13T + (size_t)FFPAD * DMODEL, DMODEL, DFF);
    cvtT_kernel<<<dim3(32, DFF / 32), tb>>>(w2, p_w2T, DFF, DMODEL);

    rmsnorm_kernel<<<NTOK, 256>>>(x, g1, p_xn);
    gemm_h<<<dim3(NQKV / BN, NTOK / BM), 256, GH_SMEM>>>(
        p_xn, p_wqkvT, p_qkv, nullptr, NQKV, DMODEL, 1);
    attn_tc<<<dim3(SEQ / ATQ, NHEADS, BATCH), 256, attn_smem>>>();
    gemm_h<<<dim3(DMODEL / BN, NTOK / BM), 256, GH_SMEM>>>(
        p_attnH, p_woT, p_hres, x, DMODEL, DMODEL, 0);
    rmsnorm_kernel<<<NTOK, 256>>>(p_hres, g2, p_hn);
    gemm_h<<<dim3(NFF2P / BN, NTOK / BM), 256, GH_SMEM>>>(
        p_hn, p_w13T, p_ff13, nullptr, NFF2P, DMODEL, 0);
    swiglu_kernel<<<dim3((DFF + 255) / 256, NTOK), 256>>>(p_ff13, p_ff1);
    gemm_h<<<dim3(DMODEL / BN, NTOK / BM), 256, GH_SMEM>>>(
        p_ff1, p_w2T, out, p_hres, DMODEL, DFF, 0);
}

// round 8
// speedup vs baseline: 10.7197x; 1.2306x over previous
#include <cuda_runtime.h>
#include <cuda_fp16.h>
#include <math.h>
#include <stdint.h>

#define BATCH 2
#define SEQ 2048
#define DMODEL 1024
#define NHEADS 16
#define DHEAD 64
#define DFF 2752
#define NTOK (BATCH * SEQ)
#define EPSV 1e-5f
#define NQKV 3072
#define NFF2P 5632
#define FFPAD 2816

// ---------------- scratch ----------------
__device__ __half g_xn   [NTOK * DMODEL];
__device__ __half g_qkvH [NTOK * NQKV];
__device__ __half g_attnH[NTOK * DMODEL];
__device__ float  g_hres [NTOK * DMODEL];
__device__ __half g_hn   [NTOK * DMODEL];
__device__ float  g_ff13 [NTOK * NFF2P];
__device__ __half g_ff1  [NTOK * DFF];
__device__ __half g_wqkvT[NQKV * DMODEL];
__device__ __half g_woT  [DMODEL * DMODEL];
__device__ __half g_w13T [NFF2P * DMODEL];
__device__ __half g_w2T  [DMODEL * DFF];

// ---------------- helpers ----------------
__device__ __forceinline__ void mma_f16(float c[4], const uint32_t a[4], const uint32_t b[2]) {
    asm volatile(
        "mma.sync.aligned.m16n8k16.row.col.f32.f16.f16.f32 "
        "{%0,%1,%2,%3}, {%4,%5,%6,%7}, {%8,%9}, {%0,%1,%2,%3};\n"
        : "+f"(c[0]), "+f"(c[1]), "+f"(c[2]), "+f"(c[3])
        : "r"(a[0]), "r"(a[1]), "r"(a[2]), "r"(a[3]), "r"(b[0]), "r"(b[1]));
}

__device__ __forceinline__ void cp_async16(void* smem_dst, const void* gsrc) {
    unsigned s = (unsigned)__cvta_generic_to_shared(smem_dst);
    asm volatile("cp.async.cg.shared.global [%0], [%1], 16;\n" :: "r"(s), "l"(gsrc));
}
__device__ __forceinline__ void cp_commit() {
    asm volatile("cp.async.commit_group;\n");
}

__device__ __forceinline__ void ldsm4(uint32_t addr, uint32_t& r0, uint32_t& r1,
                                      uint32_t& r2, uint32_t& r3) {
    asm volatile("ldmatrix.sync.aligned.m8n8.x4.shared.b16 {%0,%1,%2,%3}, [%4];"
                 : "=r"(r0), "=r"(r1), "=r"(r2), "=r"(r3) : "r"(addr));
}
__device__ __forceinline__ void ldsm4t(uint32_t addr, uint32_t& r0, uint32_t& r1,
                                       uint32_t& r2, uint32_t& r3) {
    asm volatile("ldmatrix.sync.aligned.m8n8.x4.trans.shared.b16 {%0,%1,%2,%3}, [%4];"
                 : "=r"(r0), "=r"(r1), "=r"(r2), "=r"(r3) : "r"(addr));
}

// ---------------- transpose + fp16 weights ----------------
__global__ void cvtT_kernel(const float* __restrict__ in, __half* __restrict__ out,
                            int R, int C) {
    __shared__ float t[32][33];
    int c0 = blockIdx.x * 32, r0 = blockIdx.y * 32;
    int tx = threadIdx.x, ty = threadIdx.y;
#pragma unroll
    for (int j = 0; j < 4; j++)
        t[ty + j * 8][tx] = in[(size_t)(r0 + ty + j * 8) * C + c0 + tx];
    __syncthreads();
#pragma unroll
    for (int j = 0; j < 4; j++)
        out[(size_t)(c0 + ty + j * 8) * R + r0 + tx] = __float2half(t[tx][ty + j * 8]);
}

// ---------------- RMSNorm -> fp16 ----------------
__global__ void rmsnorm_kernel(const float* __restrict__ x,
                               const float* __restrict__ g,
                               __half* __restrict__ y) {
    int row = blockIdx.x;
    const float* xr = x + (size_t)row * DMODEL;
    __half* yr = y + (size_t)row * DMODEL;
    __shared__ float red[256];
    float s = 0.f;
    for (int i = threadIdx.x; i < DMODEL; i += 256) {
        float v = xr[i];
        s += v * v;
    }
    red[threadIdx.x] = s;
    __syncthreads();
    for (int st = 128; st > 0; st >>= 1) {
        if (threadIdx.x < st) red[threadIdx.x] += red[threadIdx.x + st];
        __syncthreads();
    }
    float inv = rsqrtf(red[0] * (1.0f / DMODEL) + EPSV);
    for (int i = threadIdx.x; i < DMODEL; i += 256)
        yr[i] = __float2half(xr[i] * inv * g[i]);
}

// ---------------- fp16 GEMM ----------------
#define BM 128
#define BN 256
#define BK 32
#define HSTR 40
#define ASTG_H (BM * HSTR)
#define BSTG_H (BN * HSTR)
#define GH_SMEM ((3 * (ASTG_H + BSTG_H)) * 2)

__global__ __launch_bounds__(256)
void gemm_h(const __half* __restrict__ A, const __half* __restrict__ BT,
            void* __restrict__ Cv, const float* __restrict__ R,
            int N, int K, int out_half) {
    extern __shared__ __half hsm[];
    __half* As = hsm;
    __half* Bs = hsm + 3 * ASTG_H;
    const uint32_t sbase = (uint32_t)__cvta_generic_to_shared(hsm);

    const int tid = threadIdx.x;
    const int warp = tid >> 5, lane = tid & 31;
    const int gid = lane >> 2, tg = lane & 3;
    const int wm = warp >> 2, wn = warp & 3;
    const int ttile = lane >> 3, trow = lane & 7;
    const int rowBase = blockIdx.y * BM, colBase = blockIdx.x * BN;

    const __half* Abase = A + (size_t)rowBase * K;
    const __half* Bbase = BT + (size_t)colBase * K;
    const int nst = K / BK;

#define ISSUE_STAGE(s, k0)                                                       \
    do {                                                                         \
        __half* as = As + (s) * ASTG_H;                                          \
        __half* bs = Bs + (s) * BSTG_H;                                          \
        _Pragma("unroll")                                                        \
        for (int i = 0; i < 2; i++) {                                            \
            int c = tid + i * 256;                                               \
            int r = c >> 2, ch = c & 3;                                          \
            cp_async16(as + r * HSTR + ch * 8, Abase + (size_t)r * K + (k0) + ch * 8); \
        }                                                                        \
        _Pragma("unroll")                                                        \
        for (int i = 0; i < 4; i++) {                                            \
            int c = tid + i * 256;                                               \
            int n = c >> 2, ch = c & 3;                                          \
            cp_async16(bs + n * HSTR + ch * 8, Bbase + (size_t)n * K + (k0) + ch * 8); \
        }                                                                        \
        cp_commit();                                                             \
    } while (0)

    ISSUE_STAGE(0, 0);
    if (nst > 1) ISSUE_STAGE(1, BK);

    float acc[4][8][4];
#pragma unroll
    for (int i = 0; i < 4; i++)
#pragma unroll
        for (int j = 0; j < 8; j++)
#pragma unroll
            for (int q = 0; q < 4; q++) acc[i][j][q] = 0.f;

    const int frag_m = (ttile & 1) * 8 + trow;
    const int frag_k = (ttile >> 1) * 8;

    for (int it = 0; it < nst; it++) {
        if (it + 1 < nst) {
            asm volatile("cp.async.wait_group 1;\n");
        } else {
            asm volatile("cp.async.wait_group 0;\n");
        }
        __syncthreads();
        if (it + 2 < nst) ISSUE_STAGE((it + 2) % 3, (it + 2) * BK);

        const uint32_t asu = sbase + ((it % 3) * ASTG_H) * 2;
        const uint32_t bsu = sbase + (3 * ASTG_H + (it % 3) * BSTG_H) * 2;

#pragma unroll
        for (int ks = 0; ks < 2; ks++) {
            const int kk = ks * 16;
            uint32_t af[4][4];
#pragma unroll
            for (int mfi = 0; mfi < 4; mfi++) {
                int m0 = wm * 64 + mfi * 16;
                ldsm4(asu + (uint32_t)((m0 + frag_m) * HSTR + kk + frag_k) * 2,
                      af[mfi][0], af[mfi][1], af[mfi][2], af[mfi][3]);
            }
            uint32_t bf[8][2];
#pragma unroll
            for (int nfp = 0; nfp < 4; nfp++) {
                int n0 = wn * 64 + nfp * 16;
                ldsm4(bsu + (uint32_t)((n0 + frag_m) * HSTR + kk + frag_k) * 2,
                      bf[2 * nfp][0], bf[2 * nfp + 1][0],
                      bf[2 * nfp][1], bf[2 * nfp + 1][1]);
            }
#pragma unroll
            for (int mfi = 0; mfi < 4; mfi++)
#pragma unroll
                for (int nfi = 0; nfi < 8; nfi++)
                    mma_f16(acc[mfi][nfi], af[mfi], bf[nfi]);
        }
        __syncthreads();
    }
#undef ISSUE_STAGE

#pragma unroll
    for (int mfi = 0; mfi < 4; mfi++) {
#pragma unroll
        for (int nfi = 0; nfi < 8; nfi++) {
            int r0 = rowBase + wm * 64 + mfi * 16 + gid;
            int c0 = colBase + wn * 64 + nfi * 8 + tg * 2;
            float v0 = acc[mfi][nfi][0], v1 = acc[mfi][nfi][1];
            float v2 = acc[mfi][nfi][2], v3 = acc[mfi][nfi][3];
            if (out_half) {
                __half* Ch = (__half*)Cv;
                *(__half2*)&Ch[(size_t)r0 * N + c0] = __floats2half2_rn(v0, v1);
                *(__half2*)&Ch[(size_t)(r0 + 8) * N + c0] = __floats2half2_rn(v2, v3);
            } else {
                float* C = (float*)Cv;
                if (R) {
                    v0 += R[(size_t)r0 * N + c0];
                    v1 += R[(size_t)r0 * N + c0 + 1];
                    v2 += R[(size_t)(r0 + 8) * N + c0];
                    v3 += R[(size_t)(r0 + 8) * N + c0 + 1];
                }
                *(float2*)&C[(size_t)r0 * N + c0] = make_float2(v0, v1);
                *(float2*)&C[(size_t)(r0 + 8) * N + c0] = make_float2(v2, v3);
            }
        }
    }
}

// ---------------- fp16 flash attention ----------------
#define ATQ 64
#define ACJ 128
#define QSTRH 72
#define KSTRH 72
#define VSTRH 72
#define SSTRD 132
#define PSTRH 136
// bytes: Q 9216 + K 18432 + V 18432 + Ss 33792 + Ph 17408 + red 2560
#define ATT_SMEM (9216 + 18432 + 18432 + 33792 + 17408 + 2560)

__global__ __launch_bounds__(256)
void attn_h() {
    extern __shared__ char asm_[];
    __half* Qh = (__half*)asm_;                        // 9216 B
    __half* Kh = (__half*)(asm_ + 9216);               // 18432 B
    __half* Vh = (__half*)(asm_ + 27648);              // 18432 B
    float*  Ss = (float*)(asm_ + 46080);               // 33792 B
    __half* Ph = (__half*)(asm_ + 79872);              // 17408 B
    float*  rowf   = (float*)(asm_ + 97280);           // 64
    float*  rowinv = rowf + 64;
    float*  red1   = rowinv + 64;                      // 256
    float*  red2   = red1 + 256;                       // 256

    const uint32_t qbase = (uint32_t)__cvta_generic_to_shared(Qh);
    const uint32_t kbase = (uint32_t)__cvta_generic_to_shared(Kh);
    const uint32_t vbase = (uint32_t)__cvta_generic_to_shared(Vh);
    const uint32_t pbase = (uint32_t)__cvta_generic_to_shared(Ph);

    const int tid = threadIdx.x;
    const int warp = tid >> 5, lane = tid & 31;
    const int gid = lane >> 2, tg = lane & 3;
    const int wm = warp >> 2, wn = warp & 3;       // 2m x 4n
    const int ttile = lane >> 3, trow = lane & 7;
    const int frag_m = (ttile & 1) * 8 + trow;
    const int frag_k = (ttile >> 1) * 8;
    const int sr = tid >> 2, sq = tid & 3;

    const int qt = blockIdx.x, h = blockIdx.y, b = blockIdx.z;
    const int q0 = qt * ATQ;

    const __half* qg = g_qkvH + (size_t)b * SEQ * NQKV + h * DHEAD;
    const __half* kg = qg + DMODEL;
    const __half* vg = qg + 2 * DMODEL;

    // load Q tile (64 x 64 halves)
#pragma unroll
    for (int i = 0; i < 2; i++) {
        int c = tid + i * 256;
        int r = c >> 3, p = c & 7;
        *(uint4*)&Qh[r * QSTRH + p * 8] =
            *(const uint4*)(qg + (size_t)(q0 + r) * NQKV + p * 8);
    }

    // O accumulators: warp tile 32x16 (2 mfi x 2 nfi)
    float o[2][2][4];
#pragma unroll
    for (int i = 0; i < 2; i++)
#pragma unroll
        for (int j = 0; j < 2; j++)
#pragma unroll
            for (int q = 0; q < 4; q++) o[i][j][q] = 0.f;
    float m_r = -1e30f, l_r = 0.f;

    __syncthreads();

    const int nchunks = (q0 + ATQ + ACJ - 1) / ACJ;
    for (int c = 0; c < nchunks; c++) {
        const int j0 = c * ACJ;
        if (c) __syncthreads();

        // load K, V chunks (128 x 64 halves each)
#pragma unroll
        for (int i = 0; i < 4; i++) {
            int cc = tid + i * 256;
            int j = cc >> 3, p = cc & 7;
            *(uint4*)&Kh[j * KSTRH + p * 8] =
                *(const uint4*)(kg + (size_t)(j0 + j) * NQKV + p * 8);
            *(uint4*)&Vh[j * VSTRH + p * 8] =
                *(const uint4*)(vg + (size_t)(j0 + j) * NQKV + p * 8);
        }
        __syncthreads();

        // ---- S = Q K^T (warp tile 32x32) ----
        float sacc[2][4][4];
#pragma unroll
        for (int i = 0; i < 2; i++)
#pragma unroll
            for (int j = 0; j < 4; j++)
#pragma unroll
                for (int q = 0; q < 4; q++) sacc[i][j][q] = 0.f;
#pragma unroll
        for (int kk = 0; kk < 64; kk += 16) {
            uint32_t af[2][4];
#pragma unroll
            for (int mfi = 0; mfi < 2; mfi++) {
                int m0 = wm * 32 + mfi * 16;
                ldsm4(qbase + (uint32_t)((m0 + frag_m) * QSTRH + kk + frag_k) * 2,
                      af[mfi][0], af[mfi][1], af[mfi][2], af[mfi][3]);
            }
            uint32_t bf[4][2];
#pragma unroll
            for (int nfp = 0; nfp < 2; nfp++) {
                int n0 = wn * 32 + nfp * 16;
                ldsm4(kbase + (uint32_t)((n0 + frag_m) * KSTRH + kk + frag_k) * 2,
                      bf[2 * nfp][0], bf[2 * nfp + 1][0],
                      bf[2 * nfp][1], bf[2 * nfp + 1][1]);
            }
#pragma unroll
            for (int mfi = 0; mfi < 2; mfi++)
#pragma unroll
                for (int nfi = 0; nfi < 4; nfi++)
                    mma_f16(sacc[mfi][nfi], af[mfi], bf[nfi]);
        }
#pragma unroll
        for (int mfi = 0; mfi < 2; mfi++)
#pragma unroll
            for (int nfi = 0; nfi < 4; nfi++) {
                int r0 = wm * 32 + mfi * 16 + gid;
                int c0 = wn * 32 + nfi * 8 + tg * 2;
                *(float2*)&Ss[r0 * SSTRD + c0] =
                    make_float2(sacc[mfi][nfi][0] * 0.125f, sacc[mfi][nfi][1] * 0.125f);
                *(float2*)&Ss[(r0 + 8) * SSTRD + c0] =
                    make_float2(sacc[mfi][nfi][2] * 0.125f, sacc[mfi][nfi][3] * 0.125f);
            }
        __syncthreads();

        // ---- online softmax: 4 threads/row, write probs to Ph (half) ----
        int nv = q0 + sr - j0 + 1;
        if (nv > ACJ) nv = ACJ;
        const int jb = sq * 32;
        float msg = -1e30f;
        for (int i = 0; i < 32; i++) {
            int j = jb + i;
            if (j < nv) msg = fmaxf(msg, Ss[sr * SSTRD + j]);
        }
        red1[sq * 64 + sr] = msg;
        __syncthreads();
        float mnew = fmaxf(fmaxf(fmaxf(red1[sr], red1[64 + sr]),
                                 fmaxf(red1[128 + sr], red1[192 + sr])), m_r);
        float corr = __expf(m_r - mnew);
        float psum = 0.f;
        for (int i = 0; i < 32; i++) {
            int j = jb + i;
            float p = 0.f;
            if (j < nv) {
                p = __expf(Ss[sr * SSTRD + j] - mnew);
                psum += p;
            }
            Ph[sr * PSTRH + j] = __float2half(p);
        }
        red2[sq * 64 + sr] = psum;
        if (sq == 0) rowf[sr] = corr;
        __syncthreads();
        l_r = l_r * corr + red2[sr] + red2[64 + sr] + red2[128 + sr] + red2[192 + sr];
        m_r = mnew;

        // ---- O = O*corr + P V  (warp tile 32x16) ----
        {
            float cg = rowf[wm * 32 + 0 * 16 + gid];   // placeholder replaced below
        }
#pragma unroll
        for (int mfi = 0; mfi < 2; mfi++) {
            float cg  = rowf[wm * 32 + mfi * 16 + gid];
            float cg8 = rowf[wm * 32 + mfi * 16 + gid + 8];
#pragma unroll
            for (int nfi = 0; nfi < 2; nfi++) {
                o[mfi][nfi][0] *= cg;  o[mfi][nfi][1] *= cg;
                o[mfi][nfi][2] *= cg8; o[mfi][nfi][3] *= cg8;
            }
        }
#pragma unroll
        for (int kk = 0; kk < ACJ; kk += 16) {
            uint32_t pa[2][4];
#pragma unroll
            for (int mfi = 0; mfi < 2; mfi++) {
                int m0 = wm * 32 + mfi * 16;
                ldsm4(pbase + (uint32_t)((m0 + frag_m) * PSTRH + kk + frag_k) * 2,
                      pa[mfi][0], pa[mfi][1], pa[mfi][2], pa[mfi][3]);
            }
            uint32_t v0r, v1r, v2r, v3r;
            ldsm4t(vbase + (uint32_t)(((kk + (lane & 15)) * VSTRH +
                                       wn * 16 + ((lane >> 4) << 3)) * 2),
                   v0r, v1r, v2r, v3r);
            uint32_t b_lo[2] = {v0r, v1r};
            uint32_t b_hi[2] = {v2r, v3r};
#pragma unroll
            for (int mfi = 0; mfi < 2; mfi++) {
                mma_f16(o[mfi][0], pa[mfi], b_lo);
                mma_f16(o[mfi][1], pa[mfi], b_hi);
            }
        }
    }

    if (sq == 0) rowinv[sr] = 1.0f / l_r;
    __syncthreads();

#pragma unroll
    for (int mfi = 0; mfi < 2; mfi++) {
        float iv  = rowinv[wm * 32 + mfi * 16 + gid];
        float iv8 = rowinv[wm * 32 + mfi * 16 + gid + 8];
        int r0 = q0 + wm * 32 + mfi * 16 + gid;
#pragma unroll
        for (int nfi = 0; nfi < 2; nfi++) {
            int c0 = h * DHEAD + wn * 16 + nfi * 8 + tg * 2;
            __half* dst = g_attnH + ((size_t)(b * SEQ + r0)) * DMODEL + c0;
            *(__half2*)dst = __floats2half2_rn(o[mfi][nfi][0] * iv, o[mfi][nfi][1] * iv);
            __half* dst8 = dst + 8 * DMODEL;
            *(__half2*)dst8 = __floats2half2_rn(o[mfi][nfi][2] * iv8, o[mfi][nfi][3] * iv8);
        }
    }
}

// ---------------- swiglu: fp32 fused ff13 -> fp16 gate -------------------
__global__ void swiglu_kernel(const float* __restrict__ ff13,
                              __half* __restrict__ gate) {
    int c = blockIdx.x * 256 + threadIdx.x;
    int r = blockIdx.y;
    if (c < DFF) {
        float v = ff13[(size_t)r * NFF2P + c];
        float x3 = ff13[(size_t)r * NFF2P + FFPAD + c];
        float s = v / (1.f + __expf(-v));
        gate[(size_t)r * DFF + c] = __float2half(s * x3);
    }
}

// ---------------- launch ----------------
extern "C" void kernel_launch(void* const* d_in, const int* in_sizes, int n_in,
                              void* d_out, int out_size) {
    const float* x   = (const float*)d_in[0];
    const float* g1  = (const float*)d_in[1];
    const float* g2  = (const float*)d_in[2];
    const float* w_q = (const float*)d_in[3];
    const float* w_k = (const float*)d_in[4];
    const float* w_v = (const float*)d_in[5];
    const float* w_o = (const float*)d_in[6];
    const float* w1  = (const float*)d_in[7];
    const float* w2  = (const float*)d_in[8];
    const float* w3  = (const float*)d_in[9];
    float* out = (float*)d_out;

    __half *p_xn, *p_qkvH, *p_attnH, *p_hn, *p_ff1, *p_wqkvT, *p_woT, *p_w13T, *p_w2T;
    float *p_hres, *p_ff13;
    cudaGetSymbolAddress((void**)&p_xn,    g_xn);
    cudaGetSymbolAddress((void**)&p_qkvH,  g_qkvH);
    cudaGetSymbolAddress((void**)&p_attnH, g_attnH);
    cudaGetSymbolAddress((void**)&p_hres,  g_hres);
    cudaGetSymbolAddress((void**)&p_hn,    g_hn);
    cudaGetSymbolAddress((void**)&p_ff13,  g_ff13);
    cudaGetSymbolAddress((void**)&p_ff1,   g_ff1);
    cudaGetSymbolAddress((void**)&p_wqkvT, g_wqkvT);
    cudaGetSymbolAddress((void**)&p_woT,   g_woT);
    cudaGetSymbolAddress((void**)&p_w13T,  g_w13T);
    cudaGetSymbolAddress((void**)&p_w2T,   g_w2T);

    static int attr_set = 0;
    if (!attr_set) {
        cudaFuncSetAttribute(gemm_h, cudaFuncAttributeMaxDynamicSharedMemorySize, GH_SMEM);
        cudaFuncSetAttribute(attn_h, cudaFuncAttributeMaxDynamicSharedMemorySize, ATT_SMEM);
        attr_set = 1;
    }

    dim3 tb(32, 8);
    cvtT_kernel<<<dim3(32, 32), tb>>>(w_q, p_wqkvT, DMODEL, DMODEL);
    cvtT_kernel<<<dim3(32, 32), tb>>>(w_k, p_wqkvT + DMODEL * DMODEL, DMODEL, DMODEL);
    cvtT_kernel<<<dim3(32, 32), tb>>>(w_v, p_wqkvT + 2 * DMODEL * DMODEL, DMODEL, DMODEL);
    cvtT_kernel<<<dim3(32, 32), tb>>>(w_o, p_woT, DMODEL, DMODEL);
    cvtT_kernel<<<dim3(DFF / 32, 32), tb>>>(w1, p_w13T, DMODEL, DFF);
    cvtT_kernel<<<dim3(DFF / 32, 32), tb>>>(w3, p_w13T + (size_t)FFPAD * DMODEL, DMODEL, DFF);
    cvtT_kernel<<<dim3(32, DFF / 32), tb>>>(w2, p_w2T, DFF, DMODEL);

    rmsnorm_kernel<<<NTOK, 256>>>(x, g1, p_xn);
    gemm_h<<<dim3(NQKV / BN, NTOK / BM), 256, GH_SMEM>>>(
        p_xn, p_wqkvT, p_qkvH, nullptr, NQKV, DMODEL, 1);
    attn_h<<<dim3(SEQ / ATQ, NHEADS, BATCH), 256, ATT_SMEM>>>();
    gemm_h<<<dim3(DMODEL / BN, NTOK / BM), 256, GH_SMEM>>>(
        p_attnH, p_woT, p_hres, x, DMODEL, DMODEL, 0);
    rmsnorm_kernel<<<NTOK, 256>>>(p_hres, g2, p_hn);
    gemm_h<<<dim3(NFF2P / BN, NTOK / BM), 256, GH_SMEM>>>(
        p_hn, p_w13T, p_ff13, nullptr, NFF2P, DMODEL, 0);
    swiglu_kernel<<<dim3((DFF + 255) / 256, NTOK), 256>>>(p_ff13, p_ff1);
    gemm_h<<<dim3(DMODEL / BN, NTOK / BM), 256, GH_SMEM>>>(
        p_ff1, p_w2T, out, p_hres, DMODEL, DFF, 0);
}

// round 9
// speedup vs baseline: 10.7548x; 1.0033x over previous
#include <cuda_runtime.h>
#include <cuda_fp16.h>
#include <math.h>
#include <stdint.h>

#define BATCH 2
#define SEQ 2048
#define DMODEL 1024
#define NHEADS 16
#define DHEAD 64
#define DFF 2752
#define NTOK (BATCH * SEQ)
#define EPSV 1e-5f
#define NQKV 3072
#define NFF2P 5632
#define FFPAD 2816

// ---------------- scratch ----------------
__device__ __half g_xn   [NTOK * DMODEL];
__device__ __half g_qkvH [NTOK * NQKV];
__device__ __half g_attnH[NTOK * DMODEL];
__device__ float  g_hres [NTOK * DMODEL];
__device__ __half g_hn   [NTOK * DMODEL];
__device__ float  g_ff13 [NTOK * NFF2P];
__device__ __half g_ff1  [NTOK * DFF];
__device__ __half g_wqkvT[NQKV * DMODEL];
__device__ __half g_woT  [DMODEL * DMODEL];
__device__ __half g_w13T [NFF2P * DMODEL];
__device__ __half g_w2T  [DMODEL * DFF];

// ---------------- helpers ----------------
__device__ __forceinline__ void mma_f16(float c[4], const uint32_t a[4], const uint32_t b[2]) {
    asm volatile(
        "mma.sync.aligned.m16n8k16.row.col.f32.f16.f16.f32 "
        "{%0,%1,%2,%3}, {%4,%5,%6,%7}, {%8,%9}, {%0,%1,%2,%3};\n"
        : "+f"(c[0]), "+f"(c[1]), "+f"(c[2]), "+f"(c[3])
        : "r"(a[0]), "r"(a[1]), "r"(a[2]), "r"(a[3]), "r"(b[0]), "r"(b[1]));
}

__device__ __forceinline__ void cp_async16(void* smem_dst, const void* gsrc) {
    unsigned s = (unsigned)__cvta_generic_to_shared(smem_dst);
    asm volatile("cp.async.cg.shared.global [%0], [%1], 16;\n" :: "r"(s), "l"(gsrc));
}
__device__ __forceinline__ void cp_commit() {
    asm volatile("cp.async.commit_group;\n");
}

__device__ __forceinline__ void ldsm4(uint32_t addr, uint32_t& r0, uint32_t& r1,
                                      uint32_t& r2, uint32_t& r3) {
    asm volatile("ldmatrix.sync.aligned.m8n8.x4.shared.b16 {%0,%1,%2,%3}, [%4];"
                 : "=r"(r0), "=r"(r1), "=r"(r2), "=r"(r3) : "r"(addr));
}
__device__ __forceinline__ void ldsm4t(uint32_t addr, uint32_t& r0, uint32_t& r1,
                                       uint32_t& r2, uint32_t& r3) {
    asm volatile("ldmatrix.sync.aligned.m8n8.x4.trans.shared.b16 {%0,%1,%2,%3}, [%4];"
                 : "=r"(r0), "=r"(r1), "=r"(r2), "=r"(r3) : "r"(addr));
}

// ---------------- transpose + fp16 weights (vectorized stores) -----------
__global__ void cvtT_kernel(const float* __restrict__ in, __half* __restrict__ out,
                            int R, int C) {
    __shared__ float t[32][33];
    int c0 = blockIdx.x * 32, r0 = blockIdx.y * 32;
    int tid = threadIdx.x;
#pragma unroll
    for (int i = 0; i < 4; i++) {
        int idx = tid + i * 256;
        int r = idx >> 5, c = idx & 31;
        t[r][c] = in[(size_t)(r0 + r) * C + c0 + c];
    }
    __syncthreads();
#pragma unroll
    for (int i = 0; i < 2; i++) {
        int idx = tid + i * 256;
        int c = idx >> 4, rh = idx & 15;
        __half2 v = __floats2half2_rn(t[2 * rh][c], t[2 * rh + 1][c]);
        *(__half2*)&out[(size_t)(c0 + c) * R + r0 + 2 * rh] = v;
    }
}

// ---------------- RMSNorm -> fp16 ----------------
__global__ void rmsnorm_kernel(const float* __restrict__ x,
                               const float* __restrict__ g,
                               __half* __restrict__ y) {
    int row = blockIdx.x;
    const float* xr = x + (size_t)row * DMODEL;
    __half* yr = y + (size_t)row * DMODEL;
    __shared__ float red[256];
    float s = 0.f;
    for (int i = threadIdx.x; i < DMODEL; i += 256) {
        float v = xr[i];
        s += v * v;
    }
    red[threadIdx.x] = s;
    __syncthreads();
    for (int st = 128; st > 0; st >>= 1) {
        if (threadIdx.x < st) red[threadIdx.x] += red[threadIdx.x + st];
        __syncthreads();
    }
    float inv = rsqrtf(red[0] * (1.0f / DMODEL) + EPSV);
    for (int i = threadIdx.x; i < DMODEL; i += 256)
        yr[i] = __float2half(xr[i] * inv * g[i]);
}

// ---------------- fp16 GEMM (templated tile width) ----------------
#define BM 128
#define BK 32
#define HSTR 40
#define ASTG_H (BM * HSTR)

template<int TBN>
__device__ __forceinline__ void issue_stage(
    __half* As, __half* Bs, int s,
    const __half* Abase, const __half* Bbase, int K, int k0, int tid) {
    __half* as = As + s * ASTG_H;
    __half* bs = Bs + s * (TBN * HSTR);
#pragma unroll
    for (int i = 0; i < 2; i++) {
        int c = tid + i * 256;
        int r = c >> 2, ch = c & 3;
        cp_async16(as + r * HSTR + ch * 8, Abase + (size_t)r * K + k0 + ch * 8);
    }
#pragma unroll
    for (int i = 0; i < TBN / 64; i++) {
        int c = tid + i * 256;
        int n = c >> 2, ch = c & 3;
        cp_async16(bs + n * HSTR + ch * 8, Bbase + (size_t)n * K + k0 + ch * 8);
    }
    cp_commit();
}

template<int TBN>
__global__ __launch_bounds__(256, TBN == 128 ? 2 : 1)
void gemm_h(const __half* __restrict__ A, const __half* __restrict__ BT,
            void* __restrict__ Cv, const float* __restrict__ R,
            int N, int K, int out_half) {
    constexpr int BSTG_H = TBN * HSTR;
    constexpr int WSPAN = TBN / 4;      // warp n-span: 64 or 32
    constexpr int NFI = WSPAN / 8;      // 8 or 4
    constexpr int NLD = WSPAN / 16;     // 4 or 2

    extern __shared__ __half hsm[];
    __half* As = hsm;
    __half* Bs = hsm + 3 * ASTG_H;
    const uint32_t sbase = (uint32_t)__cvta_generic_to_shared(hsm);

    const int tid = threadIdx.x;
    const int warp = tid >> 5, lane = tid & 31;
    const int gid = lane >> 2, tg = lane & 3;
    const int wm = warp >> 2, wn = warp & 3;
    const int ttile = lane >> 3, trow = lane & 7;
    const int rowBase = blockIdx.y * BM, colBase = blockIdx.x * TBN;

    const __half* Abase = A + (size_t)rowBase * K;
    const __half* Bbase = BT + (size_t)colBase * K;
    const int nst = K / BK;

    issue_stage<TBN>(As, Bs, 0, Abase, Bbase, K, 0, tid);
    if (nst > 1) issue_stage<TBN>(As, Bs, 1, Abase, Bbase, K, BK, tid);

    float acc[4][NFI][4];
#pragma unroll
    for (int i = 0; i < 4; i++)
#pragma unroll
        for (int j = 0; j < NFI; j++)
#pragma unroll
            for (int q = 0; q < 4; q++) acc[i][j][q] = 0.f;

    const int frag_m = (ttile & 1) * 8 + trow;
    const int frag_k = (ttile >> 1) * 8;

    for (int it = 0; it < nst; it++) {
        if (it + 1 < nst) {
            asm volatile("cp.async.wait_group 1;\n");
        } else {
            asm volatile("cp.async.wait_group 0;\n");
        }
        __syncthreads();
        if (it + 2 < nst)
            issue_stage<TBN>(As, Bs, (it + 2) % 3, Abase, Bbase, K, (it + 2) * BK, tid);

        const uint32_t asu = sbase + ((it % 3) * ASTG_H) * 2;
        const uint32_t bsu = sbase + (3 * ASTG_H + (it % 3) * BSTG_H) * 2;

#pragma unroll
        for (int ks = 0; ks < 2; ks++) {
            const int kk = ks * 16;
            uint32_t af[4][4];
#pragma unroll
            for (int mfi = 0; mfi < 4; mfi++) {
                int m0 = wm * 64 + mfi * 16;
                ldsm4(asu + (uint32_t)((m0 + frag_m) * HSTR + kk + frag_k) * 2,
                      af[mfi][0], af[mfi][1], af[mfi][2], af[mfi][3]);
            }
            uint32_t bf[NFI][2];
#pragma unroll
            for (int nfp = 0; nfp < NLD; nfp++) {
                int n0 = wn * WSPAN + nfp * 16;
                ldsm4(bsu + (uint32_t)((n0 + frag_m) * HSTR + kk + frag_k) * 2,
                      bf[2 * nfp][0], bf[2 * nfp + 1][0],
                      bf[2 * nfp][1], bf[2 * nfp + 1][1]);
            }
#pragma unroll
            for (int mfi = 0; mfi < 4; mfi++)
#pragma unroll
                for (int nfi = 0; nfi < NFI; nfi++)
                    mma_f16(acc[mfi][nfi], af[mfi], bf[nfi]);
        }
        __syncthreads();
    }

#pragma unroll
    for (int mfi = 0; mfi < 4; mfi++) {
#pragma unroll
        for (int nfi = 0; nfi < NFI; nfi++) {
            int r0 = rowBase + wm * 64 + mfi * 16 + gid;
            int c0 = colBase + wn * WSPAN + nfi * 8 + tg * 2;
            float v0 = acc[mfi][nfi][0], v1 = acc[mfi][nfi][1];
            float v2 = acc[mfi][nfi][2], v3 = acc[mfi][nfi][3];
            if (out_half) {
                __half* Ch = (__half*)Cv;
                *(__half2*)&Ch[(size_t)r0 * N + c0] = __floats2half2_rn(v0, v1);
                *(__half2*)&Ch[(size_t)(r0 + 8) * N + c0] = __floats2half2_rn(v2, v3);
            } else {
                float* C = (float*)Cv;
                if (R) {
                    v0 += R[(size_t)r0 * N + c0];
                    v1 += R[(size_t)r0 * N + c0 + 1];
                    v2 += R[(size_t)(r0 + 8) * N + c0];
                    v3 += R[(size_t)(r0 + 8) * N + c0 + 1];
                }
                *(float2*)&C[(size_t)r0 * N + c0] = make_float2(v0, v1);
                *(float2*)&C[(size_t)(r0 + 8) * N + c0] = make_float2(v2, v3);
            }
        }
    }
}

#define GH_SMEM_256 ((3 * (ASTG_H + 256 * HSTR)) * 2)
#define GH_SMEM_128 ((3 * (ASTG_H + 128 * HSTR)) * 2)

// ---------------- fp16 flash attention ----------------
#define ATQ 64
#define ACJ 128
#define QSTRH 72
#define KSTRH 72
#define VSTRH 72
#define SSTRD 132
#define PSTRH 136
#define ATT_SMEM (9216 + 18432 + 18432 + 33792 + 17408 + 2560)

__global__ __launch_bounds__(256)
void attn_h() {
    extern __shared__ char asm_[];
    __half* Qh = (__half*)asm_;
    __half* Kh = (__half*)(asm_ + 9216);
    __half* Vh = (__half*)(asm_ + 27648);
    float*  Ss = (float*)(asm_ + 46080);
    __half* Ph = (__half*)(asm_ + 79872);
    float*  rowf   = (float*)(asm_ + 97280);
    float*  rowinv = rowf + 64;
    float*  red1   = rowinv + 64;
    float*  red2   = red1 + 256;

    const uint32_t qbase = (uint32_t)__cvta_generic_to_shared(Qh);
    const uint32_t kbase = (uint32_t)__cvta_generic_to_shared(Kh);
    const uint32_t vbase = (uint32_t)__cvta_generic_to_shared(Vh);
    const uint32_t pbase = (uint32_t)__cvta_generic_to_shared(Ph);

    const int tid = threadIdx.x;
    const int warp = tid >> 5, lane = tid & 31;
    const int gid = lane >> 2, tg = lane & 3;
    const int wm = warp >> 2, wn = warp & 3;
    const int ttile = lane >> 3, trow = lane & 7;
    const int frag_m = (ttile & 1) * 8 + trow;
    const int frag_k = (ttile >> 1) * 8;
    const int sr = tid >> 2, sq = tid & 3;

    const int qt = blockIdx.x, h = blockIdx.y, b = blockIdx.z;
    const int q0 = qt * ATQ;

    const __half* qg = g_qkvH + (size_t)b * SEQ * NQKV + h * DHEAD;
    const __half* kg = qg + DMODEL;
    const __half* vg = qg + 2 * DMODEL;

#pragma unroll
    for (int i = 0; i < 2; i++) {
        int c = tid + i * 256;
        int r = c >> 3, p = c & 7;
        *(uint4*)&Qh[r * QSTRH + p * 8] =
            *(const uint4*)(qg + (size_t)(q0 + r) * NQKV + p * 8);
    }

    float o[2][2][4];
#pragma unroll
    for (int i = 0; i < 2; i++)
#pragma unroll
        for (int j = 0; j < 2; j++)
#pragma unroll
            for (int q = 0; q < 4; q++) o[i][j][q] = 0.f;
    float m_r = -1e30f, l_r = 0.f;

    __syncthreads();

    const int nchunks = (q0 + ATQ + ACJ - 1) / ACJ;
    for (int c = 0; c < nchunks; c++) {
        const int j0 = c * ACJ;
        if (c) __syncthreads();

#pragma unroll
        for (int i = 0; i < 4; i++) {
            int cc = tid + i * 256;
            int j = cc >> 3, p = cc & 7;
            *(uint4*)&Kh[j * KSTRH + p * 8] =
                *(const uint4*)(kg + (size_t)(j0 + j) * NQKV + p * 8);
            *(uint4*)&Vh[j * VSTRH + p * 8] =
                *(const uint4*)(vg + (size_t)(j0 + j) * NQKV + p * 8);
        }
        __syncthreads();

        float sacc[2][4][4];
#pragma unroll
        for (int i = 0; i < 2; i++)
#pragma unroll
            for (int j = 0; j < 4; j++)
#pragma unroll
                for (int q = 0; q < 4; q++) sacc[i][j][q] = 0.f;
#pragma unroll
        for (int kk = 0; kk < 64; kk += 16) {
            uint32_t af[2][4];
#pragma unroll
            for (int mfi = 0; mfi < 2; mfi++) {
                int m0 = wm * 32 + mfi * 16;
                ldsm4(qbase + (uint32_t)((m0 + frag_m) * QSTRH + kk + frag_k) * 2,
                      af[mfi][0], af[mfi][1], af[mfi][2], af[mfi][3]);
            }
            uint32_t bf[4][2];
#pragma unroll
            for (int nfp = 0; nfp < 2; nfp++) {
                int n0 = wn * 32 + nfp * 16;
                ldsm4(kbase + (uint32_t)((n0 + frag_m) * KSTRH + kk + frag_k) * 2,
                      bf[2 * nfp][0], bf[2 * nfp + 1][0],
                      bf[2 * nfp][1], bf[2 * nfp + 1][1]);
            }
#pragma unroll
            for (int mfi = 0; mfi < 2; mfi++)
#pragma unroll
                for (int nfi = 0; nfi < 4; nfi++)
                    mma_f16(sacc[mfi][nfi], af[mfi], bf[nfi]);
        }
#pragma unroll
        for (int mfi = 0; mfi < 2; mfi++)
#pragma unroll
            for (int nfi = 0; nfi < 4; nfi++) {
                int r0 = wm * 32 + mfi * 16 + gid;
                int c0 = wn * 32 + nfi * 8 + tg * 2;
                *(float2*)&Ss[r0 * SSTRD + c0] =
                    make_float2(sacc[mfi][nfi][0] * 0.125f, sacc[mfi][nfi][1] * 0.125f);
                *(float2*)&Ss[(r0 + 8) * SSTRD + c0] =
                    make_float2(sacc[mfi][nfi][2] * 0.125f, sacc[mfi][nfi][3] * 0.125f);
            }
        __syncthreads();

        int nv = q0 + sr - j0 + 1;
        if (nv > ACJ) nv = ACJ;
        const int jb = sq * 32;
        float msg = -1e30f;
        for (int i = 0; i < 32; i++) {
            int j = jb + i;
            if (j < nv) msg = fmaxf(msg, Ss[sr * SSTRD + j]);
        }
        red1[sq * 64 + sr] = msg;
        __syncthreads();
        float mnew = fmaxf(fmaxf(fmaxf(red1[sr], red1[64 + sr]),
                                 fmaxf(red1[128 + sr], red1[192 + sr])), m_r);
        float corr = __expf(m_r - mnew);
        float psum = 0.f;
        for (int i = 0; i < 32; i++) {
            int j = jb + i;
            float p = 0.f;
            if (j < nv) {
                p = __expf(Ss[sr * SSTRD + j] - mnew);
                psum += p;
            }
            Ph[sr * PSTRH + j] = __float2half(p);
        }
        red2[sq * 64 + sr] = psum;
        if (sq == 0) rowf[sr] = corr;
        __syncthreads();
        l_r = l_r * corr + red2[sr] + red2[64 + sr] + red2[128 + sr] + red2[192 + sr];
        m_r = mnew;

#pragma unroll
        for (int mfi = 0; mfi < 2; mfi++) {
            float cg  = rowf[wm * 32 + mfi * 16 + gid];
            float cg8 = rowf[wm * 32 + mfi * 16 + gid + 8];
#pragma unroll
            for (int nfi = 0; nfi < 2; nfi++) {
                o[mfi][nfi][0] *= cg;  o[mfi][nfi][1] *= cg;
                o[mfi][nfi][2] *= cg8; o[mfi][nfi][3] *= cg8;
            }
        }
#pragma unroll
        for (int kk = 0; kk < ACJ; kk += 16) {
            uint32_t pa[2][4];
#pragma unroll
            for (int mfi = 0; mfi < 2; mfi++) {
                int m0 = wm * 32 + mfi * 16;
                ldsm4(pbase + (uint32_t)((m0 + frag_m) * PSTRH + kk + frag_k) * 2,
                      pa[mfi][0], pa[mfi][1], pa[mfi][2], pa[mfi][3]);
            }
            uint32_t v0r, v1r, v2r, v3r;
            ldsm4t(vbase + (uint32_t)(((kk + (lane & 15)) * VSTRH +
                                       wn * 16 + ((lane >> 4) << 3)) * 2),
                   v0r, v1r, v2r, v3r);
            uint32_t b_lo[2] = {v0r, v1r};
            uint32_t b_hi[2] = {v2r, v3r};
#pragma unroll
            for (int mfi = 0; mfi < 2; mfi++) {
                mma_f16(o[mfi][0], pa[mfi], b_lo);
                mma_f16(o[mfi][1], pa[mfi], b_hi);
            }
        }
    }

    if (sq == 0) rowinv[sr] = 1.0f / l_r;
    __syncthreads();

#pragma unroll
    for (int mfi = 0; mfi < 2; mfi++) {
        float iv  = rowinv[wm * 32 + mfi * 16 + gid];
        float iv8 = rowinv[wm * 32 + mfi * 16 + gid + 8];
        int r0 = q0 + wm * 32 + mfi * 16 + gid;
#pragma unroll
        for (int nfi = 0; nfi < 2; nfi++) {
            int c0 = h * DHEAD + wn * 16 + nfi * 8 + tg * 2;
            __half* dst = g_attnH + ((size_t)(b * SEQ + r0)) * DMODEL + c0;
            *(__half2*)dst = __floats2half2_rn(o[mfi][nfi][0] * iv, o[mfi][nfi][1] * iv);
            __half* dst8 = dst + 8 * DMODEL;
            *(__half2*)dst8 = __floats2half2_rn(o[mfi][nfi][2] * iv8, o[mfi][nfi][3] * iv8);
        }
    }
}

// ---------------- swiglu ----------------
__global__ void swiglu_kernel(const float* __restrict__ ff13,
                              __half* __restrict__ gate) {
    int c = blockIdx.x * 256 + threadIdx.x;
    int r = blockIdx.y;
    if (c < DFF) {
        float v = ff13[(size_t)r * NFF2P + c];
        float x3 = ff13[(size_t)r * NFF2P + FFPAD + c];
        float s = v / (1.f + __expf(-v));
        gate[(size_t)r * DFF + c] = __float2half(s * x3);
    }
}

// ---------------- launch ----------------
extern "C" void kernel_launch(void* const* d_in, const int* in_sizes, int n_in,
                              void* d_out, int out_size) {
    const float* x   = (const float*)d_in[0];
    const float* g1  = (const float*)d_in[1];
    const float* g2  = (const float*)d_in[2];
    const float* w_q = (const float*)d_in[3];
    const float* w_k = (const float*)d_in[4];
    const float* w_v = (const float*)d_in[5];
    const float* w_o = (const float*)d_in[6];
    const float* w1  = (const float*)d_in[7];
    const float* w2  = (const float*)d_in[8];
    const float* w3  = (const float*)d_in[9];
    float* out = (float*)d_out;

    __half *p_xn, *p_qkvH, *p_attnH, *p_hn, *p_ff1, *p_wqkvT, *p_woT, *p_w13T, *p_w2T;
    float *p_hres, *p_ff13;
    cudaGetSymbolAddress((void**)&p_xn,    g_xn);
    cudaGetSymbolAddress((void**)&p_qkvH,  g_qkvH);
    cudaGetSymbolAddress((void**)&p_attnH, g_attnH);
    cudaGetSymbolAddress((void**)&p_hres,  g_hres);
    cudaGetSymbolAddress((void**)&p_hn,    g_hn);
    cudaGetSymbolAddress((void**)&p_ff13,  g_ff13);
    cudaGetSymbolAddress((void**)&p_ff1,   g_ff1);
    cudaGetSymbolAddress((void**)&p_wqkvT, g_wqkvT);
    cudaGetSymbolAddress((void**)&p_woT,   g_woT);
    cudaGetSymbolAddress((void**)&p_w13T,  g_w13T);
    cudaGetSymbolAddress((void**)&p_w2T,   g_w2T);

    static int attr_set = 0;
    if (!attr_set) {
        cudaFuncSetAttribute(gemm_h<256>, cudaFuncAttributeMaxDynamicSharedMemorySize, GH_SMEM_256);
        cudaFuncSetAttribute(gemm_h<128>, cudaFuncAttributeMaxDynamicSharedMemorySize, GH_SMEM_128);
        cudaFuncSetAttribute(attn_h, cudaFuncAttributeMaxDynamicSharedMemorySize, ATT_SMEM);
        attr_set = 1;
    }

    cvtT_kernel<<<dim3(32, 32), 256>>>(w_q, p_wqkvT, DMODEL, DMODEL);
    cvtT_kernel<<<dim3(32, 32), 256>>>(w_k, p_wqkvT + DMODEL * DMODEL, DMODEL, DMODEL);
    cvtT_kernel<<<dim3(32, 32), 256>>>(w_v, p_wqkvT + 2 * DMODEL * DMODEL, DMODEL, DMODEL);
    cvtT_kernel<<<dim3(32, 32), 256>>>(w_o, p_woT, DMODEL, DMODEL);
    cvtT_kernel<<<dim3(DFF / 32, 32), 256>>>(w1, p_w13T, DMODEL, DFF);
    cvtT_kernel<<<dim3(DFF / 32, 32), 256>>>(w3, p_w13T + (size_t)FFPAD * DMODEL, DMODEL, DFF);
    cvtT_kernel<<<dim3(32, DFF / 32), 256>>>(w2, p_w2T, DFF, DMODEL);

    rmsnorm_kernel<<<NTOK, 256>>>(x, g1, p_xn);
    gemm_h<256><<<dim3(NQKV / 256, NTOK / BM), 256, GH_SMEM_256>>>(
        p_xn, p_wqkvT, p_qkvH, nullptr, NQKV, DMODEL, 1);
    attn_h<<<dim3(SEQ / ATQ, NHEADS, BATCH), 256, ATT_SMEM>>>();
    gemm_h<128><<<dim3(DMODEL / 128, NTOK / BM), 256, GH_SMEM_128>>>(
        p_attnH, p_woT, p_hres, x, DMODEL, DMODEL, 0);
    rmsnorm_kernel<<<NTOK, 256>>>(p_hres, g2, p_hn);
    gemm_h<256><<<dim3(NFF2P / 256, NTOK / BM), 256, GH_SMEM_256>>>(
        p_hn, p_w13T, p_ff13, nullptr, NFF2P, DMODEL, 0);
    swiglu_kernel<<<dim3((DFF + 255) / 256, NTOK), 256>>>(p_ff13, p_ff1);
    gemm_h<128><<<dim3(DMODEL / 128, NTOK / BM), 256, GH_SMEM_128>>>(
        p_ff1, p_w2T, out, p_hres, DMODEL, DFF, 0);
}

// round 10
// speedup vs baseline: 12.6523x; 1.1764x over previous
#include <cuda_runtime.h>
#include <cuda_fp16.h>
#include <math.h>
#include <stdint.h>

#define BATCH 2
#define SEQ 2048
#define DMODEL 1024
#define NHEADS 16
#define DHEAD 64
#define DFF 2752
#define NTOK (BATCH * SEQ)
#define EPSV 1e-5f
#define NQKV 3072
#define NFF2P 5632
#define FFPAD 2816

// ---------------- scratch ----------------
__device__ __half g_xn   [NTOK * DMODEL];
__device__ __half g_qkvH [NTOK * NQKV];
__device__ __half g_attnH[NTOK * DMODEL];
__device__ float  g_hres [NTOK * DMODEL];
__device__ __half g_hn   [NTOK * DMODEL];
__device__ __half g_ff13 [NTOK * NFF2P];
__device__ __half g_ff1  [NTOK * DFF];
__device__ __half g_wqkvT[NQKV * DMODEL];
__device__ __half g_woT  [DMODEL * DMODEL];
__device__ __half g_w13T [NFF2P * DMODEL];
__device__ __half g_w2T  [DMODEL * DFF];

// ---------------- helpers ----------------
__device__ __forceinline__ void mma_f16(float c[4], const uint32_t a[4], const uint32_t b[2]) {
    asm volatile(
        "mma.sync.aligned.m16n8k16.row.col.f32.f16.f16.f32 "
        "{%0,%1,%2,%3}, {%4,%5,%6,%7}, {%8,%9}, {%0,%1,%2,%3};\n"
        : "+f"(c[0]), "+f"(c[1]), "+f"(c[2]), "+f"(c[3])
        : "r"(a[0]), "r"(a[1]), "r"(a[2]), "r"(a[3]), "r"(b[0]), "r"(b[1]));
}

__device__ __forceinline__ void cp_async16(void* smem_dst, const void* gsrc) {
    unsigned s = (unsigned)__cvta_generic_to_shared(smem_dst);
    asm volatile("cp.async.cg.shared.global [%0], [%1], 16;\n" :: "r"(s), "l"(gsrc));
}
__device__ __forceinline__ void cp_commit() {
    asm volatile("cp.async.commit_group;\n");
}

__device__ __forceinline__ void ldsm4(uint32_t addr, uint32_t& r0, uint32_t& r1,
                                      uint32_t& r2, uint32_t& r3) {
    asm volatile("ldmatrix.sync.aligned.m8n8.x4.shared.b16 {%0,%1,%2,%3}, [%4];"
                 : "=r"(r0), "=r"(r1), "=r"(r2), "=r"(r3) : "r"(addr));
}
__device__ __forceinline__ void ldsm4t(uint32_t addr, uint32_t& r0, uint32_t& r1,
                                       uint32_t& r2, uint32_t& r3) {
    asm volatile("ldmatrix.sync.aligned.m8n8.x4.trans.shared.b16 {%0,%1,%2,%3}, [%4];"
                 : "=r"(r0), "=r"(r1), "=r"(r2), "=r"(r3) : "r"(addr));
}

// ---------------- transpose + fp16 weights ----------------
__global__ void cvtT_kernel(const float* __restrict__ in, __half* __restrict__ out,
                            int R, int C) {
    __shared__ float t[32][33];
    int c0 = blockIdx.x * 32, r0 = blockIdx.y * 32;
    int tid = threadIdx.x;
#pragma unroll
    for (int i = 0; i < 4; i++) {
        int idx = tid + i * 256;
        int r = idx >> 5, c = idx & 31;
        t[r][c] = in[(size_t)(r0 + r) * C + c0 + c];
    }
    __syncthreads();
#pragma unroll
    for (int i = 0; i < 2; i++) {
        int idx = tid + i * 256;
        int c = idx >> 4, rh = idx & 15;
        __half2 v = __floats2half2_rn(t[2 * rh][c], t[2 * rh + 1][c]);
        *(__half2*)&out[(size_t)(c0 + c) * R + r0 + 2 * rh] = v;
    }
}

// ---------------- RMSNorm -> fp16 ----------------
__global__ void rmsnorm_kernel(const float* __restrict__ x,
                               const float* __restrict__ g,
                               __half* __restrict__ y) {
    int row = blockIdx.x;
    const float* xr = x + (size_t)row * DMODEL;
    __half* yr = y + (size_t)row * DMODEL;
    __shared__ float red[256];
    float s = 0.f;
    for (int i = threadIdx.x; i < DMODEL; i += 256) {
        float v = xr[i];
        s += v * v;
    }
    red[threadIdx.x] = s;
    __syncthreads();
    for (int st = 128; st > 0; st >>= 1) {
        if (threadIdx.x < st) red[threadIdx.x] += red[threadIdx.x + st];
        __syncthreads();
    }
    float inv = rsqrtf(red[0] * (1.0f / DMODEL) + EPSV);
    for (int i = threadIdx.x; i < DMODEL; i += 256)
        yr[i] = __float2half(xr[i] * inv * g[i]);
}

// ---------------- fp16 GEMM (templated tile width) ----------------
#define BM 128
#define BK 32
#define HSTR 40
#define ASTG_H (BM * HSTR)

template<int TBN>
__device__ __forceinline__ void issue_stage(
    __half* As, __half* Bs, int s,
    const __half* Abase, const __half* Bbase, int K, int k0, int tid) {
    __half* as = As + s * ASTG_H;
    __half* bs = Bs + s * (TBN * HSTR);
#pragma unroll
    for (int i = 0; i < 2; i++) {
        int c = tid + i * 256;
        int r = c >> 2, ch = c & 3;
        cp_async16(as + r * HSTR + ch * 8, Abase + (size_t)r * K + k0 + ch * 8);
    }
#pragma unroll
    for (int i = 0; i < TBN / 64; i++) {
        int c = tid + i * 256;
        int n = c >> 2, ch = c & 3;
        cp_async16(bs + n * HSTR + ch * 8, Bbase + (size_t)n * K + k0 + ch * 8);
    }
    cp_commit();
}

template<int TBN>
__global__ __launch_bounds__(256, TBN == 128 ? 2 : 1)
void gemm_h(const __half* __restrict__ A, const __half* __restrict__ BT,
            void* __restrict__ Cv, const float* __restrict__ R,
            int N, int K, int out_half) {
    constexpr int BSTG_H = TBN * HSTR;
    constexpr int WSPAN = TBN / 4;
    constexpr int NFI = WSPAN / 8;
    constexpr int NLD = WSPAN / 16;

    extern __shared__ __half hsm[];
    __half* As = hsm;
    __half* Bs = hsm + 3 * ASTG_H;
    const uint32_t sbase = (uint32_t)__cvta_generic_to_shared(hsm);

    const int tid = threadIdx.x;
    const int warp = tid >> 5, lane = tid & 31;
    const int gid = lane >> 2, tg = lane & 3;
    const int wm = warp >> 2, wn = warp & 3;
    const int ttile = lane >> 3, trow = lane & 7;
    const int rowBase = blockIdx.y * BM, colBase = blockIdx.x * TBN;

    const __half* Abase = A + (size_t)rowBase * K;
    const __half* Bbase = BT + (size_t)colBase * K;
    const int nst = K / BK;

    issue_stage<TBN>(As, Bs, 0, Abase, Bbase, K, 0, tid);
    if (nst > 1) issue_stage<TBN>(As, Bs, 1, Abase, Bbase, K, BK, tid);

    float acc[4][NFI][4];
#pragma unroll
    for (int i = 0; i < 4; i++)
#pragma unroll
        for (int j = 0; j < NFI; j++)
#pragma unroll
            for (int q = 0; q < 4; q++) acc[i][j][q] = 0.f;

    const int frag_m = (ttile & 1) * 8 + trow;
    const int frag_k = (ttile >> 1) * 8;

    for (int it = 0; it < nst; it++) {
        if (it + 1 < nst) {
            asm volatile("cp.async.wait_group 1;\n");
        } else {
            asm volatile("cp.async.wait_group 0;\n");
        }
        __syncthreads();
        if (it + 2 < nst)
            issue_stage<TBN>(As, Bs, (it + 2) % 3, Abase, Bbase, K, (it + 2) * BK, tid);

        const uint32_t asu = sbase + ((it % 3) * ASTG_H) * 2;
        const uint32_t bsu = sbase + (3 * ASTG_H + (it % 3) * BSTG_H) * 2;

#pragma unroll
        for (int ks = 0; ks < 2; ks++) {
            const int kk = ks * 16;
            uint32_t af[4][4];
#pragma unroll
            for (int mfi = 0; mfi < 4; mfi++) {
                int m0 = wm * 64 + mfi * 16;
                ldsm4(asu + (uint32_t)((m0 + frag_m) * HSTR + kk + frag_k) * 2,
                      af[mfi][0], af[mfi][1], af[mfi][2], af[mfi][3]);
            }
            uint32_t bf[NFI][2];
#pragma unroll
            for (int nfp = 0; nfp < NLD; nfp++) {
                int n0 = wn * WSPAN + nfp * 16;
                ldsm4(bsu + (uint32_t)((n0 + frag_m) * HSTR + kk + frag_k) * 2,
                      bf[2 * nfp][0], bf[2 * nfp + 1][0],
                      bf[2 * nfp][1], bf[2 * nfp + 1][1]);
            }
#pragma unroll
            for (int mfi = 0; mfi < 4; mfi++)
#pragma unroll
                for (int nfi = 0; nfi < NFI; nfi++)
                    mma_f16(acc[mfi][nfi], af[mfi], bf[nfi]);
        }
        __syncthreads();
    }

#pragma unroll
    for (int mfi = 0; mfi < 4; mfi++) {
#pragma unroll
        for (int nfi = 0; nfi < NFI; nfi++) {
            int r0 = rowBase + wm * 64 + mfi * 16 + gid;
            int c0 = colBase + wn * WSPAN + nfi * 8 + tg * 2;
            float v0 = acc[mfi][nfi][0], v1 = acc[mfi][nfi][1];
            float v2 = acc[mfi][nfi][2], v3 = acc[mfi][nfi][3];
            if (out_half) {
                __half* Ch = (__half*)Cv;
                *(__half2*)&Ch[(size_t)r0 * N + c0] = __floats2half2_rn(v0, v1);
                *(__half2*)&Ch[(size_t)(r0 + 8) * N + c0] = __floats2half2_rn(v2, v3);
            } else {
                float* C = (float*)Cv;
                if (R) {
                    v0 += R[(size_t)r0 * N + c0];
                    v1 += R[(size_t)r0 * N + c0 + 1];
                    v2 += R[(size_t)(r0 + 8) * N + c0];
                    v3 += R[(size_t)(r0 + 8) * N + c0 + 1];
                }
                *(float2*)&C[(size_t)r0 * N + c0] = make_float2(v0, v1);
                *(float2*)&C[(size_t)(r0 + 8) * N + c0] = make_float2(v2, v3);
            }
        }
    }
}

#define GH_SMEM_256 ((3 * (ASTG_H + 256 * HSTR)) * 2)
#define GH_SMEM_128 ((3 * (ASTG_H + 128 * HSTR)) * 2)

// ---------------- fp16 flash attention, register softmax ----------------
#define ATQ 64
#define ACJ 128
#define QSTRH 72
#define KSTRH 72
#define VSTRH 72
#define PSTRH 136
// smem: Q 9216 + K 18432 + V 18432 + Ph 17408 + redm 1024 + reds 1024 = 65536
#define ATT_SMEM 65536

__global__ __launch_bounds__(256, 2)
void attn_h() {
    extern __shared__ char asm_[];
    __half* Qh = (__half*)asm_;
    __half* Kh = (__half*)(asm_ + 9216);
    __half* Vh = (__half*)(asm_ + 27648);
    __half* Ph = (__half*)(asm_ + 46080);
    float*  redm = (float*)(asm_ + 63488);   // [4][64]
    float*  reds = (float*)(asm_ + 64512);   // [4][64]

    const uint32_t qbase = (uint32_t)__cvta_generic_to_shared(Qh);
    const uint32_t kbase = (uint32_t)__cvta_generic_to_shared(Kh);
    const uint32_t vbase = (uint32_t)__cvta_generic_to_shared(Vh);
    const uint32_t pbase = (uint32_t)__cvta_generic_to_shared(Ph);

    const int tid = threadIdx.x;
    const int warp = tid >> 5, lane = tid & 31;
    const int gid = lane >> 2, tg = lane & 3;
    const int wm = warp >> 2, wn = warp & 3;
    const int ttile = lane >> 3, trow = lane & 7;
    const int frag_m = (ttile & 1) * 8 + trow;
    const int frag_k = (ttile >> 1) * 8;

    const int qt = blockIdx.x, h = blockIdx.y, b = blockIdx.z;
    const int q0 = qt * ATQ;

    const __half* qg = g_qkvH + (size_t)b * SEQ * NQKV + h * DHEAD;
    const __half* kg = qg + DMODEL;
    const __half* vg = qg + 2 * DMODEL;

#pragma unroll
    for (int i = 0; i < 2; i++) {
        int c = tid + i * 256;
        int r = c >> 3, p = c & 7;
        *(uint4*)&Qh[r * QSTRH + p * 8] =
            *(const uint4*)(qg + (size_t)(q0 + r) * NQKV + p * 8);
    }

    float o[2][2][4];
#pragma unroll
    for (int i = 0; i < 2; i++)
#pragma unroll
        for (int j = 0; j < 2; j++)
#pragma unroll
            for (int q = 0; q < 4; q++) o[i][j][q] = 0.f;
    // per-thread softmax state for its 4 rows: [mfi] x {lo=gid, hi=gid+8}
    float m_lo[2] = {-1e30f, -1e30f}, m_hi[2] = {-1e30f, -1e30f};
    float l_lo[2] = {0.f, 0.f}, l_hi[2] = {0.f, 0.f};

    __syncthreads();

    const int nchunks = (q0 + ATQ + ACJ - 1) / ACJ;
    for (int c = 0; c < nchunks; c++) {
        const int j0 = c * ACJ;
        if (c) __syncthreads();

#pragma unroll
        for (int i = 0; i < 4; i++) {
            int cc = tid + i * 256;
            int j = cc >> 3, p = cc & 7;
            *(uint4*)&Kh[j * KSTRH + p * 8] =
                *(const uint4*)(kg + (size_t)(j0 + j) * NQKV + p * 8);
            *(uint4*)&Vh[j * VSTRH + p * 8] =
                *(const uint4*)(vg + (size_t)(j0 + j) * NQKV + p * 8);
        }
        __syncthreads();

        // ---- S = Q K^T (warp tile 32x32), kept in registers ----
        float sacc[2][4][4];
#pragma unroll
        for (int i = 0; i < 2; i++)
#pragma unroll
            for (int j = 0; j < 4; j++)
#pragma unroll
                for (int q = 0; q < 4; q++) sacc[i][j][q] = 0.f;
#pragma unroll
        for (int kk = 0; kk < 64; kk += 16) {
            uint32_t af[2][4];
#pragma unroll
            for (int mfi = 0; mfi < 2; mfi++) {
                int m0 = wm * 32 + mfi * 16;
                ldsm4(qbase + (uint32_t)((m0 + frag_m) * QSTRH + kk + frag_k) * 2,
                      af[mfi][0], af[mfi][1], af[mfi][2], af[mfi][3]);
            }
            uint32_t bf[4][2];
#pragma unroll
            for (int nfp = 0; nfp < 2; nfp++) {
                int n0 = wn * 32 + nfp * 16;
                ldsm4(kbase + (uint32_t)((n0 + frag_m) * KSTRH + kk + frag_k) * 2,
                      bf[2 * nfp][0], bf[2 * nfp + 1][0],
                      bf[2 * nfp][1], bf[2 * nfp + 1][1]);
            }
#pragma unroll
            for (int mfi = 0; mfi < 2; mfi++)
#pragma unroll
                for (int nfi = 0; nfi < 4; nfi++)
                    mma_f16(sacc[mfi][nfi], af[mfi], bf[nfi]);
        }

        // ---- scale + causal mask in registers ----
        float mx_lo[2], mx_hi[2];
#pragma unroll
        for (int mfi = 0; mfi < 2; mfi++) {
            int r = wm * 32 + mfi * 16 + gid;      // tile-local row
            int lim_lo = q0 + r - j0;              // valid cols <= lim
            int lim_hi = lim_lo + 8;
            mx_lo[mfi] = -1e30f; mx_hi[mfi] = -1e30f;
#pragma unroll
            for (int nfi = 0; nfi < 4; nfi++) {
                int cb = wn * 32 + nfi * 8 + tg * 2;
                float s0 = (cb     <= lim_lo) ? sacc[mfi][nfi][0] * 0.125f : -1e30f;
                float s1 = (cb + 1 <= lim_lo) ? sacc[mfi][nfi][1] * 0.125f : -1e30f;
                float s2 = (cb     <= lim_hi) ? sacc[mfi][nfi][2] * 0.125f : -1e30f;
                float s3 = (cb + 1 <= lim_hi) ? sacc[mfi][nfi][3] * 0.125f : -1e30f;
                sacc[mfi][nfi][0] = s0; sacc[mfi][nfi][1] = s1;
                sacc[mfi][nfi][2] = s2; sacc[mfi][nfi][3] = s3;
                mx_lo[mfi] = fmaxf(mx_lo[mfi], fmaxf(s0, s1));
                mx_hi[mfi] = fmaxf(mx_hi[mfi], fmaxf(s2, s3));
            }
            // reduce across the 4 tg lanes (quad owns the row's 8 cols x4)
            mx_lo[mfi] = fmaxf(mx_lo[mfi], __shfl_xor_sync(0xffffffffu, mx_lo[mfi], 1));
            mx_lo[mfi] = fmaxf(mx_lo[mfi], __shfl_xor_sync(0xffffffffu, mx_lo[mfi], 2));
            mx_hi[mfi] = fmaxf(mx_hi[mfi], __shfl_xor_sync(0xffffffffu, mx_hi[mfi], 1));
            mx_hi[mfi] = fmaxf(mx_hi[mfi], __shfl_xor_sync(0xffffffffu, mx_hi[mfi], 2));
            if (tg == 0) {
                redm[wn * 64 + r] = mx_lo[mfi];
                redm[wn * 64 + r + 8] = mx_hi[mfi];
            }
        }
        __syncthreads();

        float corr_lo[2], corr_hi[2];
#pragma unroll
        for (int mfi = 0; mfi < 2; mfi++) {
            int r = wm * 32 + mfi * 16 + gid;
            float ml = fmaxf(fmaxf(redm[r], redm[64 + r]),
                             fmaxf(redm[128 + r], redm[192 + r]));
            float mh = fmaxf(fmaxf(redm[r + 8], redm[64 + r + 8]),
                             fmaxf(redm[128 + r + 8], redm[192 + r + 8]));
            float mnl = fmaxf(m_lo[mfi], ml);
            float mnh = fmaxf(m_hi[mfi], mh);
            corr_lo[mfi] = __expf(m_lo[mfi] - mnl);
            corr_hi[mfi] = __expf(m_hi[mfi] - mnh);
            m_lo[mfi] = mnl; m_hi[mfi] = mnh;

            // exp + partial sums + write probs (half) to Ph
            float ps_lo = 0.f, ps_hi = 0.f;
#pragma unroll
            for (int nfi = 0; nfi < 4; nfi++) {
                int cb = wn * 32 + nfi * 8 + tg * 2;
                float p0 = __expf(sacc[mfi][nfi][0] - mnl);
                float p1 = __expf(sacc[mfi][nfi][1] - mnl);
                float p2 = __expf(sacc[mfi][nfi][2] - mnh);
                float p3 = __expf(sacc[mfi][nfi][3] - mnh);
                ps_lo += p0 + p1; ps_hi += p2 + p3;
                *(__half2*)&Ph[r * PSTRH + cb] = __floats2half2_rn(p0, p1);
                *(__half2*)&Ph[(r + 8) * PSTRH + cb] = __floats2half2_rn(p2, p3);
            }
            ps_lo += __shfl_xor_sync(0xffffffffu, ps_lo, 1);
            ps_lo += __shfl_xor_sync(0xffffffffu, ps_lo, 2);
            ps_hi += __shfl_xor_sync(0xffffffffu, ps_hi, 1);
            ps_hi += __shfl_xor_sync(0xffffffffu, ps_hi, 2);
            if (tg == 0) {
                reds[wn * 64 + r] = ps_lo;
                reds[wn * 64 + r + 8] = ps_hi;
            }
        }
        __syncthreads();

#pragma unroll
        for (int mfi = 0; mfi < 2; mfi++) {
            int r = wm * 32 + mfi * 16 + gid;
            float sl = reds[r] + reds[64 + r] + reds[128 + r] + reds[192 + r];
            float sh = reds[r + 8] + reds[64 + r + 8] + reds[128 + r + 8] + reds[192 + r + 8];
            l_lo[mfi] = l_lo[mfi] * corr_lo[mfi] + sl;
            l_hi[mfi] = l_hi[mfi] * corr_hi[mfi] + sh;
            // rescale O
#pragma unroll
            for (int nfi = 0; nfi < 2; nfi++) {
                o[mfi][nfi][0] *= corr_lo[mfi]; o[mfi][nfi][1] *= corr_lo[mfi];
                o[mfi][nfi][2] *= corr_hi[mfi]; o[mfi][nfi][3] *= corr_hi[mfi];
            }
        }

        // ---- O += P V (P from Ph cross-warp, V via ldsm trans) ----
#pragma unroll
        for (int kk = 0; kk < ACJ; kk += 16) {
            uint32_t pa[2][4];
#pragma unroll
            for (int mfi = 0; mfi < 2; mfi++) {
                int m0 = wm * 32 + mfi * 16;
                ldsm4(pbase + (uint32_t)((m0 + frag_m) * PSTRH + kk + frag_k) * 2,
                      pa[mfi][0], pa[mfi][1], pa[mfi][2], pa[mfi][3]);
            }
            uint32_t v0r, v1r, v2r, v3r;
            ldsm4t(vbase + (uint32_t)(((kk + (lane & 15)) * VSTRH +
                                       wn * 16 + ((lane >> 4) << 3)) * 2),
                   v0r, v1r, v2r, v3r);
            uint32_t b_lo[2] = {v0r, v1r};
            uint32_t b_hi[2] = {v2r, v3r};
#pragma unroll
            for (int mfi = 0; mfi < 2; mfi++) {
                mma_f16(o[mfi][0], pa[mfi], b_lo);
                mma_f16(o[mfi][1], pa[mfi], b_hi);
            }
        }
    }

    // ---- finalize ----
#pragma unroll
    for (int mfi = 0; mfi < 2; mfi++) {
        float iv  = 1.0f / l_lo[mfi];
        float iv8 = 1.0f / l_hi[mfi];
        int r0 = q0 + wm * 32 + mfi * 16 + gid;
#pragma unroll
        for (int nfi = 0; nfi < 2; nfi++) {
            int c0 = h * DHEAD + wn * 16 + nfi * 8 + tg * 2;
            __half* dst = g_attnH + ((size_t)(b * SEQ + r0)) * DMODEL + c0;
            *(__half2*)dst = __floats2half2_rn(o[mfi][nfi][0] * iv, o[mfi][nfi][1] * iv);
            __half* dst8 = dst + 8 * DMODEL;
            *(__half2*)dst8 = __floats2half2_rn(o[mfi][nfi][2] * iv8, o[mfi][nfi][3] * iv8);
        }
    }
}

// ---------------- swiglu: half ff13 -> half gate ----------------
__global__ void swiglu_kernel(const __half* __restrict__ ff13,
                              __half* __restrict__ gate) {
    int c = blockIdx.x * 256 + threadIdx.x;
    int r = blockIdx.y;
    if (c < DFF) {
        float v = __half2float(ff13[(size_t)r * NFF2P + c]);
        float x3 = __half2float(ff13[(size_t)r * NFF2P + FFPAD + c]);
        float s = v / (1.f + __expf(-v));
        gate[(size_t)r * DFF + c] = __float2half(s * x3);
    }
}

// ---------------- launch ----------------
extern "C" void kernel_launch(void* const* d_in, const int* in_sizes, int n_in,
                              void* d_out, int out_size) {
    const float* x   = (const float*)d_in[0];
    const float* g1  = (const float*)d_in[1];
    const float* g2  = (const float*)d_in[2];
    const float* w_q = (const float*)d_in[3];
    const float* w_k = (const float*)d_in[4];
    const float* w_v = (const float*)d_in[5];
    const float* w_o = (const float*)d_in[6];
    const float* w1  = (const float*)d_in[7];
    const float* w2  = (const float*)d_in[8];
    const float* w3  = (const float*)d_in[9];
    float* out = (float*)d_out;

    __half *p_xn, *p_qkvH, *p_attnH, *p_hn, *p_ff13, *p_ff1;
    __half *p_wqkvT, *p_woT, *p_w13T, *p_w2T;
    float *p_hres;
    cudaGetSymbolAddress((void**)&p_xn,    g_xn);
    cudaGetSymbolAddress((void**)&p_qkvH,  g_qkvH);
    cudaGetSymbolAddress((void**)&p_attnH, g_attnH);
    cudaGetSymbolAddress((void**)&p_hres,  g_hres);
    cudaGetSymbolAddress((void**)&p_hn,    g_hn);
    cudaGetSymbolAddress((void**)&p_ff13,  g_ff13);
    cudaGetSymbolAddress((void**)&p_ff1,   g_ff1);
    cudaGetSymbolAddress((void**)&p_wqkvT, g_wqkvT);
    cudaGetSymbolAddress((void**)&p_woT,   g_woT);
    cudaGetSymbolAddress((void**)&p_w13T,  g_w13T);
    cudaGetSymbolAddress((void**)&p_w2T,   g_w2T);

    static int attr_set = 0;
    if (!attr_set) {
        cudaFuncSetAttribute(gemm_h<256>, cudaFuncAttributeMaxDynamicSharedMemorySize, GH_SMEM_256);
        cudaFuncSetAttribute(gemm_h<128>, cudaFuncAttributeMaxDynamicSharedMemorySize, GH_SMEM_128);
        cudaFuncSetAttribute(attn_h, cudaFuncAttributeMaxDynamicSharedMemorySize, ATT_SMEM);
        attr_set = 1;
    }

    cvtT_kernel<<<dim3(32, 32), 256>>>(w_q, p_wqkvT, DMODEL, DMODEL);
    cvtT_kernel<<<dim3(32, 32), 256>>>(w_k, p_wqkvT + DMODEL * DMODEL, DMODEL, DMODEL);
    cvtT_kernel<<<dim3(32, 32), 256>>>(w_v, p_wqkvT + 2 * DMODEL * DMODEL, DMODEL, DMODEL);
    cvtT_kernel<<<dim3(32, 32), 256>>>(w_o, p_woT, DMODEL, DMODEL);
    cvtT_kernel<<<dim3(DFF / 32, 32), 256>>>(w1, p_w13T, DMODEL, DFF);
    cvtT_kernel<<<dim3(DFF / 32, 32), 256>>>(w3, p_w13T + (size_t)FFPAD * DMODEL, DMODEL, DFF);
    cvtT_kernel<<<dim3(32, DFF / 32), 256>>>(w2, p_w2T, DFF, DMODEL);

    rmsnorm_kernel<<<NTOK, 256>>>(x, g1, p_xn);
    gemm_h<256><<<dim3(NQKV / 256, NTOK / BM), 256, GH_SMEM_256>>>(
        p_xn, p_wqkvT, p_qkvH, nullptr, NQKV, DMODEL, 1);
    attn_h<<<dim3(SEQ / ATQ, NHEADS, BATCH), 256, ATT_SMEM>>>();
    gemm_h<128><<<dim3(DMODEL / 128, NTOK / BM), 256, GH_SMEM_128>>>(
        p_attnH, p_woT, p_hres, x, DMODEL, DMODEL, 0);
    rmsnorm_kernel<<<NTOK, 256>>>(p_hres, g2, p_hn);
    gemm_h<256><<<dim3(NFF2P / 256, NTOK / BM), 256, GH_SMEM_256>>>(
        p_hn, p_w13T, p_ff13, nullptr, NFF2P, DMODEL, 1);
    swiglu_kernel<<<dim3((DFF + 255) / 256, NTOK), 256>>>(p_ff13, p_ff1);
    gemm_h<128><<<dim3(DMODEL / 128, NTOK / BM), 256, GH_SMEM_128>>>(
        p_ff1, p_w2T, out, p_hres, DMODEL, DFF, 0);
}

// round 11
// speedup vs baseline: 13.0231x; 1.0293x over previous
#include <cuda_runtime.h>
#include <cuda_fp16.h>
#include <math.h>
#include <stdint.h>

#define BATCH 2
#define SEQ 2048
#define DMODEL 1024
#define NHEADS 16
#define DHEAD 64
#define DFF 2752
#define NTOK (BATCH * SEQ)
#define EPSV 1e-5f
#define NQKV 3072
#define NFF2P 5632          // interleaved w1/w3, padded (rows 5504.. stay zero)
#define KP2 2816            // padded K for w2 GEMM / gate stride

// ---------------- scratch ----------------
__device__ __half g_xn   [NTOK * DMODEL];
__device__ __half g_qkvH [NTOK * NQKV];
__device__ __half g_attnH[NTOK * DMODEL];
__device__ float  g_hres [NTOK * DMODEL];
__device__ __half g_hn   [NTOK * DMODEL];
__device__ __half g_gate [NTOK * KP2];
__device__ __half g_wqkvT[NQKV * DMODEL];
__device__ __half g_woT  [DMODEL * DMODEL];
__device__ __half g_w13T [NFF2P * DMODEL];   // rows 5504..5631 remain zero
__device__ __half g_w2T  [DMODEL * KP2];     // cols 2752..2815 remain zero

// ---------------- helpers ----------------
__device__ __forceinline__ void mma_f16(float c[4], const uint32_t a[4], const uint32_t b[2]) {
    asm volatile(
        "mma.sync.aligned.m16n8k16.row.col.f32.f16.f16.f32 "
        "{%0,%1,%2,%3}, {%4,%5,%6,%7}, {%8,%9}, {%0,%1,%2,%3};\n"
        : "+f"(c[0]), "+f"(c[1]), "+f"(c[2]), "+f"(c[3])
        : "r"(a[0]), "r"(a[1]), "r"(a[2]), "r"(a[3]), "r"(b[0]), "r"(b[1]));
}

__device__ __forceinline__ void cp_async16(void* smem_dst, const void* gsrc) {
    unsigned s = (unsigned)__cvta_generic_to_shared(smem_dst);
    asm volatile("cp.async.cg.shared.global [%0], [%1], 16;\n" :: "r"(s), "l"(gsrc));
}
__device__ __forceinline__ void cp_commit() {
    asm volatile("cp.async.commit_group;\n");
}

__device__ __forceinline__ void ldsm4(uint32_t addr, uint32_t& r0, uint32_t& r1,
                                      uint32_t& r2, uint32_t& r3) {
    asm volatile("ldmatrix.sync.aligned.m8n8.x4.shared.b16 {%0,%1,%2,%3}, [%4];"
                 : "=r"(r0), "=r"(r1), "=r"(r2), "=r"(r3) : "r"(addr));
}
__device__ __forceinline__ void ldsm4t(uint32_t addr, uint32_t& r0, uint32_t& r1,
                                       uint32_t& r2, uint32_t& r3) {
    asm volatile("ldmatrix.sync.aligned.m8n8.x4.trans.shared.b16 {%0,%1,%2,%3}, [%4];"
                 : "=r"(r0), "=r"(r1), "=r"(r2), "=r"(r3) : "r"(addr));
}

// ---------------- fused weight prep: all 7 transposes in one launch -------
// jobs (block ranges): 0-3 qkv/o (1024 tiles each), 4/5 w1/w3 interleaved
// (2752 each), 6 w2 (2752).
__global__ void cvt_all(const float* __restrict__ wq, const float* __restrict__ wk,
                        const float* __restrict__ wv, const float* __restrict__ wo,
                        const float* __restrict__ w1, const float* __restrict__ w3,
                        const float* __restrict__ w2,
                        __half* __restrict__ wqkvT, __half* __restrict__ woT,
                        __half* __restrict__ w13T, __half* __restrict__ w2T) {
    __shared__ float t[32][33];
    int bid = blockIdx.x;
    const float* in;
    __half* out;
    int C, ostride, rowmul, rowoff, local;
    if (bid < 1024)      { in = wq; out = wqkvT;               C = 1024; ostride = 1024; rowmul = 1; rowoff = 0; local = bid; }
    else if (bid < 2048) { in = wk; out = wqkvT + 1024 * 1024; C = 1024; ostride = 1024; rowmul = 1; rowoff = 0; local = bid - 1024; }
    else if (bid < 3072) { in = wv; out = wqkvT + 2 * 1024 * 1024; C = 1024; ostride = 1024; rowmul = 1; rowoff = 0; local = bid - 2048; }
    else if (bid < 4096) { in = wo; out = woT;                 C = 1024; ostride = 1024; rowmul = 1; rowoff = 0; local = bid - 3072; }
    else if (bid < 6848) { in = w1; out = w13T;                C = DFF;  ostride = 1024; rowmul = 2; rowoff = 0; local = bid - 4096; }
    else if (bid < 9600) { in = w3; out = w13T;                C = DFF;  ostride = 1024; rowmul = 2; rowoff = 1; local = bid - 6848; }
    else                 { in = w2; out = w2T;                 C = 1024; ostride = KP2;  rowmul = 1; rowoff = 0; local = bid - 9600; }
    int ntx = C >> 5;
    int c0 = (local % ntx) * 32, r0 = (local / ntx) * 32;
    int tid = threadIdx.x;
#pragma unroll
    for (int i = 0; i < 4; i++) {
        int idx = tid + i * 256;
        int r = idx >> 5, c = idx & 31;
        t[r][c] = in[(size_t)(r0 + r) * C + c0 + c];
    }
    __syncthreads();
#pragma unroll
    for (int i = 0; i < 2; i++) {
        int idx = tid + i * 256;
        int c = idx >> 4, rh = idx & 15;
        __half2 v = __floats2half2_rn(t[2 * rh][c], t[2 * rh + 1][c]);
        size_t orow = (size_t)(c0 + c) * rowmul + rowoff;
        *(__half2*)&out[orow * ostride + r0 + 2 * rh] = v;
    }
}

// ---------------- RMSNorm -> fp16 ----------------
__global__ void rmsnorm_kernel(const float* __restrict__ x,
                               const float* __restrict__ g,
                               __half* __restrict__ y) {
    int row = blockIdx.x;
    const float* xr = x + (size_t)row * DMODEL;
    __half* yr = y + (size_t)row * DMODEL;
    __shared__ float red[256];
    float s = 0.f;
    for (int i = threadIdx.x; i < DMODEL; i += 256) {
        float v = xr[i];
        s += v * v;
    }
    red[threadIdx.x] = s;
    __syncthreads();
    for (int st = 128; st > 0; st >>= 1) {
        if (threadIdx.x < st) red[threadIdx.x] += red[threadIdx.x + st];
        __syncthreads();
    }
    float inv = rsqrtf(red[0] * (1.0f / DMODEL) + EPSV);
    for (int i = threadIdx.x; i < DMODEL; i += 256)
        yr[i] = __float2half(xr[i] * inv * g[i]);
}

// ---------------- fp16 GEMM (templated tile width; mode epilogue) --------
// mode 0: fp32 out (+R residual); mode 1: half out; mode 2: swiglu-fused
// (interleaved x1/x3 pairs -> gate half, stride KP2).
#define BM 128
#define BK 32
#define HSTR 40
#define ASTG_H (BM * HSTR)

template<int TBN>
__device__ __forceinline__ void issue_stage(
    __half* As, __half* Bs, int s,
    const __half* Abase, const __half* Bbase, int K, int k0, int tid) {
    __half* as = As + s * ASTG_H;
    __half* bs = Bs + s * (TBN * HSTR);
#pragma unroll
    for (int i = 0; i < 2; i++) {
        int c = tid + i * 256;
        int r = c >> 2, ch = c & 3;
        cp_async16(as + r * HSTR + ch * 8, Abase + (size_t)r * K + k0 + ch * 8);
    }
#pragma unroll
    for (int i = 0; i < TBN / 64; i++) {
        int c = tid + i * 256;
        int n = c >> 2, ch = c & 3;
        cp_async16(bs + n * HSTR + ch * 8, Bbase + (size_t)n * K + k0 + ch * 8);
    }
    cp_commit();
}

template<int TBN>
__global__ __launch_bounds__(256, TBN == 128 ? 2 : 1)
void gemm_h(const __half* __restrict__ A, const __half* __restrict__ BT,
            void* __restrict__ Cv, const float* __restrict__ R,
            int N, int K, int mode) {
    constexpr int BSTG_H = TBN * HSTR;
    constexpr int WSPAN = TBN / 4;
    constexpr int NFI = WSPAN / 8;
    constexpr int NLD = WSPAN / 16;

    extern __shared__ __half hsm[];
    __half* As = hsm;
    __half* Bs = hsm + 3 * ASTG_H;
    const uint32_t sbase = (uint32_t)__cvta_generic_to_shared(hsm);

    const int tid = threadIdx.x;
    const int warp = tid >> 5, lane = tid & 31;
    const int gid = lane >> 2, tg = lane & 3;
    const int wm = warp >> 2, wn = warp & 3;
    const int ttile = lane >> 3, trow = lane & 7;
    const int rowBase = blockIdx.y * BM, colBase = blockIdx.x * TBN;

    const __half* Abase = A + (size_t)rowBase * K;
    const __half* Bbase = BT + (size_t)colBase * K;
    const int nst = K / BK;

    issue_stage<TBN>(As, Bs, 0, Abase, Bbase, K, 0, tid);
    if (nst > 1) issue_stage<TBN>(As, Bs, 1, Abase, Bbase, K, BK, tid);

    float acc[4][NFI][4];
#pragma unroll
    for (int i = 0; i < 4; i++)
#pragma unroll
        for (int j = 0; j < NFI; j++)
#pragma unroll
            for (int q = 0; q < 4; q++) acc[i][j][q] = 0.f;

    const int frag_m = (ttile & 1) * 8 + trow;
    const int frag_k = (ttile >> 1) * 8;

    for (int it = 0; it < nst; it++) {
        if (it + 1 < nst) {
            asm volatile("cp.async.wait_group 1;\n");
        } else {
            asm volatile("cp.async.wait_group 0;\n");
        }
        __syncthreads();
        if (it + 2 < nst)
            issue_stage<TBN>(As, Bs, (it + 2) % 3, Abase, Bbase, K, (it + 2) * BK, tid);

        const uint32_t asu = sbase + ((it % 3) * ASTG_H) * 2;
        const uint32_t bsu = sbase + (3 * ASTG_H + (it % 3) * BSTG_H) * 2;

#pragma unroll
        for (int ks = 0; ks < 2; ks++) {
            const int kk = ks * 16;
            uint32_t af[4][4];
#pragma unroll
            for (int mfi = 0; mfi < 4; mfi++) {
                int m0 = wm * 64 + mfi * 16;
                ldsm4(asu + (uint32_t)((m0 + frag_m) * HSTR + kk + frag_k) * 2,
                      af[mfi][0], af[mfi][1], af[mfi][2], af[mfi][3]);
            }
            uint32_t bf[NFI][2];
#pragma unroll
            for (int nfp = 0; nfp < NLD; nfp++) {
                int n0 = wn * WSPAN + nfp * 16;
                ldsm4(bsu + (uint32_t)((n0 + frag_m) * HSTR + kk + frag_k) * 2,
                      bf[2 * nfp][0], bf[2 * nfp + 1][0],
                      bf[2 * nfp][1], bf[2 * nfp + 1][1]);
            }
#pragma unroll
            for (int mfi = 0; mfi < 4; mfi++)
#pragma unroll
                for (int nfi = 0; nfi < NFI; nfi++)
                    mma_f16(acc[mfi][nfi], af[mfi], bf[nfi]);
        }
        __syncthreads();
    }

#pragma unroll
    for (int mfi = 0; mfi < 4; mfi++) {
#pragma unroll
        for (int nfi = 0; nfi < NFI; nfi++) {
            int r0 = rowBase + wm * 64 + mfi * 16 + gid;
            int c0 = colBase + wn * WSPAN + nfi * 8 + tg * 2;
            float v0 = acc[mfi][nfi][0], v1 = acc[mfi][nfi][1];
            float v2 = acc[mfi][nfi][2], v3 = acc[mfi][nfi][3];
            if (mode == 2) {
                // interleaved pairs: v0=x1, v1=x3 (row r0); v2=x1, v3=x3 (row r0+8)
                __half* G = (__half*)Cv;
                int gc = (colBase + wn * WSPAN + nfi * 8) / 2 + tg;
                float s0 = v0 / (1.f + __expf(-v0));
                float s1 = v2 / (1.f + __expf(-v2));
                G[(size_t)r0 * KP2 + gc] = __float2half(s0 * v1);
                G[(size_t)(r0 + 8) * KP2 + gc] = __float2half(s1 * v3);
            } else if (mode == 1) {
                __half* Ch = (__half*)Cv;
                *(__half2*)&Ch[(size_t)r0 * N + c0] = __floats2half2_rn(v0, v1);
                *(__half2*)&Ch[(size_t)(r0 + 8) * N + c0] = __floats2half2_rn(v2, v3);
            } else {
                float* C = (float*)Cv;
                if (R) {
                    v0 += R[(size_t)r0 * N + c0];
                    v1 += R[(size_t)r0 * N + c0 + 1];
                    v2 += R[(size_t)(r0 + 8) * N + c0];
                    v3 += R[(size_t)(r0 + 8) * N + c0 + 1];
                }
                *(float2*)&C[(size_t)r0 * N + c0] = make_float2(v0, v1);
                *(float2*)&C[(size_t)(r0 + 8) * N + c0] = make_float2(v2, v3);
            }
        }
    }
}

#define GH_SMEM_256 ((3 * (ASTG_H + 256 * HSTR)) * 2)
#define GH_SMEM_128 ((3 * (ASTG_H + 128 * HSTR)) * 2)

// ---------------- fp16 flash attention, register softmax ----------------
#define ATQ 64
#define ACJ 128
#define QSTRH 72
#define KSTRH 72
#define VSTRH 72
#define PSTRH 136
#define ATT_SMEM 65536

__global__ __launch_bounds__(256, 2)
void attn_h() {
    extern __shared__ char asm_[];
    __half* Qh = (__half*)asm_;
    __half* Kh = (__half*)(asm_ + 9216);
    __half* Vh = (__half*)(asm_ + 27648);
    __half* Ph = (__half*)(asm_ + 46080);
    float*  redm = (float*)(asm_ + 63488);
    float*  reds = (float*)(asm_ + 64512);

    const uint32_t qbase = (uint32_t)__cvta_generic_to_shared(Qh);
    const uint32_t kbase = (uint32_t)__cvta_generic_to_shared(Kh);
    const uint32_t vbase = (uint32_t)__cvta_generic_to_shared(Vh);
    const uint32_t pbase = (uint32_t)__cvta_generic_to_shared(Ph);

    const int tid = threadIdx.x;
    const int warp = tid >> 5, lane = tid & 31;
    const int gid = lane >> 2, tg = lane & 3;
    const int wm = warp >> 2, wn = warp & 3;
    const int ttile = lane >> 3, trow = lane & 7;
    const int frag_m = (ttile & 1) * 8 + trow;
    const int frag_k = (ttile >> 1) * 8;

    const int qt = blockIdx.x, h = blockIdx.y, b = blockIdx.z;
    const int q0 = qt * ATQ;

    const __half* qg = g_qkvH + (size_t)b * SEQ * NQKV + h * DHEAD;
    const __half* kg = qg + DMODEL;
    const __half* vg = qg + 2 * DMODEL;

#pragma unroll
    for (int i = 0; i < 2; i++) {
        int c = tid + i * 256;
        int r = c >> 3, p = c & 7;
        *(uint4*)&Qh[r * QSTRH + p * 8] =
            *(const uint4*)(qg + (size_t)(q0 + r) * NQKV + p * 8);
    }

    float o[2][2][4];
#pragma unroll
    for (int i = 0; i < 2; i++)
#pragma unroll
        for (int j = 0; j < 2; j++)
#pragma unroll
            for (int q = 0; q < 4; q++) o[i][j][q] = 0.f;
    float m_lo[2] = {-1e30f, -1e30f}, m_hi[2] = {-1e30f, -1e30f};
    float l_lo[2] = {0.f, 0.f}, l_hi[2] = {0.f, 0.f};

    __syncthreads();

    const int nchunks = (q0 + ATQ + ACJ - 1) / ACJ;
    for (int c = 0; c < nchunks; c++) {
        const int j0 = c * ACJ;
        if (c) __syncthreads();

#pragma unroll
        for (int i = 0; i < 4; i++) {
            int cc = tid + i * 256;
            int j = cc >> 3, p = cc & 7;
            *(uint4*)&Kh[j * KSTRH + p * 8] =
                *(const uint4*)(kg + (size_t)(j0 + j) * NQKV + p * 8);
            *(uint4*)&Vh[j * VSTRH + p * 8] =
                *(const uint4*)(vg + (size_t)(j0 + j) * NQKV + p * 8);
        }
        __syncthreads();

        float sacc[2][4][4];
#pragma unroll
        for (int i = 0; i < 2; i++)
#pragma unroll
            for (int j = 0; j < 4; j++)
#pragma unroll
                for (int q = 0; q < 4; q++) sacc[i][j][q] = 0.f;
#pragma unroll
        for (int kk = 0; kk < 64; kk += 16) {
            uint32_t af[2][4];
#pragma unroll
            for (int mfi = 0; mfi < 2; mfi++) {
                int m0 = wm * 32 + mfi * 16;
                ldsm4(qbase + (uint32_t)((m0 + frag_m) * QSTRH + kk + frag_k) * 2,
                      af[mfi][0], af[mfi][1], af[mfi][2], af[mfi][3]);
            }
            uint32_t bf[4][2];
#pragma unroll
            for (int nfp = 0; nfp < 2; nfp++) {
                int n0 = wn * 32 + nfp * 16;
                ldsm4(kbase + (uint32_t)((n0 + frag_m) * KSTRH + kk + frag_k) * 2,
                      bf[2 * nfp][0], bf[2 * nfp + 1][0],
                      bf[2 * nfp][1], bf[2 * nfp + 1][1]);
            }
#pragma unroll
            for (int mfi = 0; mfi < 2; mfi++)
#pragma unroll
                for (int nfi = 0; nfi < 4; nfi++)
                    mma_f16(sacc[mfi][nfi], af[mfi], bf[nfi]);
        }

        float mx_lo[2], mx_hi[2];
#pragma unroll
        for (int mfi = 0; mfi < 2; mfi++) {
            int r = wm * 32 + mfi * 16 + gid;
            int lim_lo = q0 + r - j0;
            int lim_hi = lim_lo + 8;
            mx_lo[mfi] = -1e30f; mx_hi[mfi] = -1e30f;
#pragma unroll
            for (int nfi = 0; nfi < 4; nfi++) {
                int cb = wn * 32 + nfi * 8 + tg * 2;
                float s0 = (cb     <= lim_lo) ? sacc[mfi][nfi][0] * 0.125f : -1e30f;
                float s1 = (cb + 1 <= lim_lo) ? sacc[mfi][nfi][1] * 0.125f : -1e30f;
                float s2 = (cb     <= lim_hi) ? sacc[mfi][nfi][2] * 0.125f : -1e30f;
                float s3 = (cb + 1 <= lim_hi) ? sacc[mfi][nfi][3] * 0.125f : -1e30f;
                sacc[mfi][nfi][0] = s0; sacc[mfi][nfi][1] = s1;
                sacc[mfi][nfi][2] = s2; sacc[mfi][nfi][3] = s3;
                mx_lo[mfi] = fmaxf(mx_lo[mfi], fmaxf(s0, s1));
                mx_hi[mfi] = fmaxf(mx_hi[mfi], fmaxf(s2, s3));
            }
            mx_lo[mfi] = fmaxf(mx_lo[mfi], __shfl_xor_sync(0xffffffffu, mx_lo[mfi], 1));
            mx_lo[mfi] = fmaxf(mx_lo[mfi], __shfl_xor_sync(0xffffffffu, mx_lo[mfi], 2));
            mx_hi[mfi] = fmaxf(mx_hi[mfi], __shfl_xor_sync(0xffffffffu, mx_hi[mfi], 1));
            mx_hi[mfi] = fmaxf(mx_hi[mfi], __shfl_xor_sync(0xffffffffu, mx_hi[mfi], 2));
            if (tg == 0) {
                redm[wn * 64 + r] = mx_lo[mfi];
                redm[wn * 64 + r + 8] = mx_hi[mfi];
            }
        }
        __syncthreads();

        float corr_lo[2], corr_hi[2];
#pragma unroll
        for (int mfi = 0; mfi < 2; mfi++) {
            int r = wm * 32 + mfi * 16 + gid;
            float ml = fmaxf(fmaxf(redm[r], redm[64 + r]),
                             fmaxf(redm[128 + r], redm[192 + r]));
            float mh = fmaxf(fmaxf(redm[r + 8], redm[64 + r + 8]),
                             fmaxf(redm[128 + r + 8], redm[192 + r + 8]));
            float mnl = fmaxf(m_lo[mfi], ml);
            float mnh = fmaxf(m_hi[mfi], mh);
            corr_lo[mfi] = __expf(m_lo[mfi] - mnl);
            corr_hi[mfi] = __expf(m_hi[mfi] - mnh);
            m_lo[mfi] = mnl; m_hi[mfi] = mnh;

            float ps_lo = 0.f, ps_hi = 0.f;
#pragma unroll
            for (int nfi = 0; nfi < 4; nfi++) {
                int cb = wn * 32 + nfi * 8 + tg * 2;
                float p0 = __expf(sacc[mfi][nfi][0] - mnl);
                float p1 = __expf(sacc[mfi][nfi][1] - mnl);
                float p2 = __expf(sacc[mfi][nfi][2] - mnh);
                float p3 = __expf(sacc[mfi][nfi][3] - mnh);
                ps_lo += p0 + p1; ps_hi += p2 + p3;
                *(__half2*)&Ph[r * PSTRH + cb] = __floats2half2_rn(p0, p1);
                *(__half2*)&Ph[(r + 8) * PSTRH + cb] = __floats2half2_rn(p2, p3);
            }
            ps_lo += __shfl_xor_sync(0xffffffffu, ps_lo, 1);
            ps_lo += __shfl_xor_sync(0xffffffffu, ps_lo, 2);
            ps_hi += __shfl_xor_sync(0xffffffffu, ps_hi, 1);
            ps_hi += __shfl_xor_sync(0xffffffffu, ps_hi, 2);
            if (tg == 0) {
                reds[wn * 64 + r] = ps_lo;
                reds[wn * 64 + r + 8] = ps_hi;
            }
        }
        __syncthreads();

#pragma unroll
        for (int mfi = 0; mfi < 2; mfi++) {
            int r = wm * 32 + mfi * 16 + gid;
            float sl = reds[r] + reds[64 + r] + reds[128 + r] + reds[192 + r];
            float sh = reds[r + 8] + reds[64 + r + 8] + reds[128 + r + 8] + reds[192 + r + 8];
            l_lo[mfi] = l_lo[mfi] * corr_lo[mfi] + sl;
            l_hi[mfi] = l_hi[mfi] * corr_hi[mfi] + sh;
#pragma unroll
            for (int nfi = 0; nfi < 2; nfi++) {
                o[mfi][nfi][0] *= corr_lo[mfi]; o[mfi][nfi][1] *= corr_lo[mfi];
                o[mfi][nfi][2] *= corr_hi[mfi]; o[mfi][nfi][3] *= corr_hi[mfi];
            }
        }

#pragma unroll
        for (int kk = 0; kk < ACJ; kk += 16) {
            uint32_t pa[2][4];
#pragma unroll
            for (int mfi = 0; mfi < 2; mfi++) {
                int m0 = wm * 32 + mfi * 16;
                ldsm4(pbase + (uint32_t)((m0 + frag_m) * PSTRH + kk + frag_k) * 2,
                      pa[mfi][0], pa[mfi][1], pa[mfi][2], pa[mfi][3]);
            }
            uint32_t v0r, v1r, v2r, v3r;
            ldsm4t(vbase + (uint32_t)(((kk + (lane & 15)) * VSTRH +
                                       wn * 16 + ((lane >> 4) << 3)) * 2),
                   v0r, v1r, v2r, v3r);
            uint32_t b_lo[2] = {v0r, v1r};
            uint32_t b_hi[2] = {v2r, v3r};
#pragma unroll
            for (int mfi = 0; mfi < 2; mfi++) {
                mma_f16(o[mfi][0], pa[mfi], b_lo);
                mma_f16(o[mfi][1], pa[mfi], b_hi);
            }
        }
    }

#pragma unroll
    for (int mfi = 0; mfi < 2; mfi++) {
        float iv  = 1.0f / l_lo[mfi];
        float iv8 = 1.0f / l_hi[mfi];
        int r0 = q0 + wm * 32 + mfi * 16 + gid;
#pragma unroll
        for (int nfi = 0; nfi < 2; nfi++) {
            int c0 = h * DHEAD + wn * 16 + nfi * 8 + tg * 2;
            __half* dst = g_attnH + ((size_t)(b * SEQ + r0)) * DMODEL + c0;
            *(__half2*)dst = __floats2half2_rn(o[mfi][nfi][0] * iv, o[mfi][nfi][1] * iv);
            __half* dst8 = dst + 8 * DMODEL;
            *(__half2*)dst8 = __floats2half2_rn(o[mfi][nfi][2] * iv8, o[mfi][nfi][3] * iv8);
        }
    }
}

// ---------------- launch ----------------
extern "C" void kernel_launch(void* const* d_in, const int* in_sizes, int n_in,
                              void* d_out, int out_size) {
    const float* x   = (const float*)d_in[0];
    const float* g1  = (const float*)d_in[1];
    const float* g2  = (const float*)d_in[2];
    const float* w_q = (const float*)d_in[3];
    const float* w_k = (const float*)d_in[4];
    const float* w_v = (const float*)d_in[5];
    const float* w_o = (const float*)d_in[6];
    const float* w1  = (const float*)d_in[7];
    const float* w2  = (const float*)d_in[8];
    const float* w3  = (const float*)d_in[9];
    float* out = (float*)d_out;

    __half *p_xn, *p_qkvH, *p_attnH, *p_hn, *p_gate;
    __half *p_wqkvT, *p_woT, *p_w13T, *p_w2T;
    float *p_hres;
    cudaGetSymbolAddress((void**)&p_xn,    g_xn);
    cudaGetSymbolAddress((void**)&p_qkvH,  g_qkvH);
    cudaGetSymbolAddress((void**)&p_attnH, g_attnH);
    cudaGetSymbolAddress((void**)&p_hres,  g_hres);
    cudaGetSymbolAddress((void**)&p_hn,    g_hn);
    cudaGetSymbolAddress((void**)&p_gate,  g_gate);
    cudaGetSymbolAddress((void**)&p_wqkvT, g_wqkvT);
    cudaGetSymbolAddress((void**)&p_woT,   g_woT);
    cudaGetSymbolAddress((void**)&p_w13T,  g_w13T);
    cudaGetSymbolAddress((void**)&p_w2T,   g_w2T);

    static int attr_set = 0;
    if (!attr_set) {
        cudaFuncSetAttribute(gemm_h<256>, cudaFuncAttributeMaxDynamicSharedMemorySize, GH_SMEM_256);
        cudaFuncSetAttribute(gemm_h<128>, cudaFuncAttributeMaxDynamicSharedMemorySize, GH_SMEM_128);
        cudaFuncSetAttribute(attn_h, cudaFuncAttributeMaxDynamicSharedMemorySize, ATT_SMEM);
        attr_set = 1;
    }

    // all weight transposes in one launch
    cvt_all<<<12352, 256>>>(w_q, w_k, w_v, w_o, w1, w3, w2,
                            p_wqkvT, p_woT, p_w13T, p_w2T);

    rmsnorm_kernel<<<NTOK, 256>>>(x, g1, p_xn);
    gemm_h<256><<<dim3(NQKV / 256, NTOK / BM), 256, GH_SMEM_256>>>(
        p_xn, p_wqkvT, p_qkvH, nullptr, NQKV, DMODEL, 1);
    attn_h<<<dim3(SEQ / ATQ, NHEADS, BATCH), 256, ATT_SMEM>>>();
    gemm_h<128><<<dim3(DMODEL / 128, NTOK / BM), 256, GH_SMEM_128>>>(
        p_attnH, p_woT, p_hres, x, DMODEL, DMODEL, 0);
    rmsnorm_kernel<<<NTOK, 256>>>(p_hres, g2, p_hn);
    // FFN1 with fused swiglu: interleaved w13, writes gate[NTOK][KP2]
    gemm_h<256><<<dim3(NFF2P / 256, NTOK / BM), 256, GH_SMEM_256>>>(
        p_hn, p_w13T, p_gate, nullptr, NFF2P, DMODEL, 2);
    // FFN2: K padded to 2816 (zero tail contributes nothing)
    gemm_h<128><<<dim3(DMODEL / 128, NTOK / BM), 256, GH_SMEM_128>>>(
        p_gate, p_w2T, out, p_hres, DMODEL, KP2, 0);
}

// round 12
// speedup vs baseline: 13.2088x; 1.0143x over previous
#include <cuda_runtime.h>
#include <cuda_fp16.h>
#include <math.h>
#include <stdint.h>

#define BATCH 2
#define SEQ 2048
#define DMODEL 1024
#define NHEADS 16
#define DHEAD 64
#define DFF 2752
#define NTOK (BATCH * SEQ)
#define EPSV 1e-5f
#define NQKV 3072
#define NFF2P 5632
#define KP2 2816

// ---------------- scratch ----------------
__device__ __half g_xn   [NTOK * DMODEL];
__device__ __half g_qkvH [NTOK * NQKV];
__device__ __half g_attnH[NTOK * DMODEL];
__device__ float  g_hres [NTOK * DMODEL];
__device__ __half g_hn   [NTOK * DMODEL];
__device__ __half g_gate [NTOK * KP2];
__device__ __half g_wqkvT[NQKV * DMODEL];
__device__ __half g_woT  [DMODEL * DMODEL];
__device__ __half g_w13T [NFF2P * DMODEL];
__device__ __half g_w2T  [DMODEL * KP2];

// ---------------- helpers ----------------
__device__ __forceinline__ void mma_f16(float c[4], const uint32_t a[4], const uint32_t b[2]) {
    asm volatile(
        "mma.sync.aligned.m16n8k16.row.col.f32.f16.f16.f32 "
        "{%0,%1,%2,%3}, {%4,%5,%6,%7}, {%8,%9}, {%0,%1,%2,%3};\n"
        : "+f"(c[0]), "+f"(c[1]), "+f"(c[2]), "+f"(c[3])
        : "r"(a[0]), "r"(a[1]), "r"(a[2]), "r"(a[3]), "r"(b[0]), "r"(b[1]));
}

__device__ __forceinline__ void cp_async16(void* smem_dst, const void* gsrc) {
    unsigned s = (unsigned)__cvta_generic_to_shared(smem_dst);
    asm volatile("cp.async.cg.shared.global [%0], [%1], 16;\n" :: "r"(s), "l"(gsrc));
}
__device__ __forceinline__ void cp_commit() {
    asm volatile("cp.async.commit_group;\n");
}

__device__ __forceinline__ void ldsm4(uint32_t addr, uint32_t& r0, uint32_t& r1,
                                      uint32_t& r2, uint32_t& r3) {
    asm volatile("ldmatrix.sync.aligned.m8n8.x4.shared.b16 {%0,%1,%2,%3}, [%4];"
                 : "=r"(r0), "=r"(r1), "=r"(r2), "=r"(r3) : "r"(addr));
}
__device__ __forceinline__ void ldsm4t(uint32_t addr, uint32_t& r0, uint32_t& r1,
                                       uint32_t& r2, uint32_t& r3) {
    asm volatile("ldmatrix.sync.aligned.m8n8.x4.trans.shared.b16 {%0,%1,%2,%3}, [%4];"
                 : "=r"(r0), "=r"(r1), "=r"(r2), "=r"(r3) : "r"(addr));
}

// ---------------- fused weight prep (7 transposes, one launch) ------------
__global__ void cvt_all(const float* __restrict__ wq, const float* __restrict__ wk,
                        const float* __restrict__ wv, const float* __restrict__ wo,
                        const float* __restrict__ w1, const float* __restrict__ w3,
                        const float* __restrict__ w2,
                        __half* __restrict__ wqkvT, __half* __restrict__ woT,
                        __half* __restrict__ w13T, __half* __restrict__ w2T) {
    __shared__ float t[32][33];
    int bid = blockIdx.x;
    const float* in;
    __half* out;
    int C, ostride, rowmul, rowoff, local;
    if (bid < 1024)      { in = wq; out = wqkvT;               C = 1024; ostride = 1024; rowmul = 1; rowoff = 0; local = bid; }
    else if (bid < 2048) { in = wk; out = wqkvT + 1024 * 1024; C = 1024; ostride = 1024; rowmul = 1; rowoff = 0; local = bid - 1024; }
    else if (bid < 3072) { in = wv; out = wqkvT + 2 * 1024 * 1024; C = 1024; ostride = 1024; rowmul = 1; rowoff = 0; local = bid - 2048; }
    else if (bid < 4096) { in = wo; out = woT;                 C = 1024; ostride = 1024; rowmul = 1; rowoff = 0; local = bid - 3072; }
    else if (bid < 6848) { in = w1; out = w13T;                C = DFF;  ostride = 1024; rowmul = 2; rowoff = 0; local = bid - 4096; }
    else if (bid < 9600) { in = w3; out = w13T;                C = DFF;  ostride = 1024; rowmul = 2; rowoff = 1; local = bid - 6848; }
    else                 { in = w2; out = w2T;                 C = 1024; ostride = KP2;  rowmul = 1; rowoff = 0; local = bid - 9600; }
    int ntx = C >> 5;
    int c0 = (local % ntx) * 32, r0 = (local / ntx) * 32;
    int tid = threadIdx.x;
#pragma unroll
    for (int i = 0; i < 4; i++) {
        int idx = tid + i * 256;
        int r = idx >> 5, c = idx & 31;
        t[r][c] = in[(size_t)(r0 + r) * C + c0 + c];
    }
    __syncthreads();
#pragma unroll
    for (int i = 0; i < 2; i++) {
        int idx = tid + i * 256;
        int c = idx >> 4, rh = idx & 15;
        __half2 v = __floats2half2_rn(t[2 * rh][c], t[2 * rh + 1][c]);
        size_t orow = (size_t)(c0 + c) * rowmul + rowoff;
        *(__half2*)&out[orow * ostride + r0 + 2 * rh] = v;
    }
}

// ---------------- RMSNorm -> fp16 ----------------
__global__ void rmsnorm_kernel(const float* __restrict__ x,
                               const float* __restrict__ g,
                               __half* __restrict__ y) {
    int row = blockIdx.x;
    const float* xr = x + (size_t)row * DMODEL;
    __half* yr = y + (size_t)row * DMODEL;
    __shared__ float red[256];
    float s = 0.f;
    for (int i = threadIdx.x; i < DMODEL; i += 256) {
        float v = xr[i];
        s += v * v;
    }
    red[threadIdx.x] = s;
    __syncthreads();
    for (int st = 128; st > 0; st >>= 1) {
        if (threadIdx.x < st) red[threadIdx.x] += red[threadIdx.x + st];
        __syncthreads();
    }
    float inv = rsqrtf(red[0] * (1.0f / DMODEL) + EPSV);
    for (int i = threadIdx.x; i < DMODEL; i += 256)
        yr[i] = __float2half(xr[i] * inv * g[i]);
}

// ---------------- fp16 GEMM (single-sync mainloop) ----------------
#define BM 128
#define BK 32
#define HSTR 40
#define ASTG_H (BM * HSTR)

template<int TBN>
__device__ __forceinline__ void issue_stage(
    __half* As, __half* Bs, int s,
    const __half* Abase, const __half* Bbase, int K, int k0, int tid) {
    __half* as = As + s * ASTG_H;
    __half* bs = Bs + s * (TBN * HSTR);
#pragma unroll
    for (int i = 0; i < 2; i++) {
        int c = tid + i * 256;
        int r = c >> 2, ch = c & 3;
        cp_async16(as + r * HSTR + ch * 8, Abase + (size_t)r * K + k0 + ch * 8);
    }
#pragma unroll
    for (int i = 0; i < TBN / 64; i++) {
        int c = tid + i * 256;
        int n = c >> 2, ch = c & 3;
        cp_async16(bs + n * HSTR + ch * 8, Bbase + (size_t)n * K + k0 + ch * 8);
    }
    cp_commit();
}

template<int TBN>
__global__ __launch_bounds__(256, TBN == 128 ? 2 : 1)
void gemm_h(const __half* __restrict__ A, const __half* __restrict__ BT,
            void* __restrict__ Cv, const float* __restrict__ R,
            int N, int K, int mode) {
    constexpr int BSTG_H = TBN * HSTR;
    constexpr int WSPAN = TBN / 4;
    constexpr int NFI = WSPAN / 8;
    constexpr int NLD = WSPAN / 16;

    extern __shared__ __half hsm[];
    __half* As = hsm;
    __half* Bs = hsm + 3 * ASTG_H;
    const uint32_t sbase = (uint32_t)__cvta_generic_to_shared(hsm);

    const int tid = threadIdx.x;
    const int warp = tid >> 5, lane = tid & 31;
    const int gid = lane >> 2, tg = lane & 3;
    const int wm = warp >> 2, wn = warp & 3;
    const int ttile = lane >> 3, trow = lane & 7;
    const int rowBase = blockIdx.y * BM, colBase = blockIdx.x * TBN;

    const __half* Abase = A + (size_t)rowBase * K;
    const __half* Bbase = BT + (size_t)colBase * K;
    const int nst = K / BK;

    issue_stage<TBN>(As, Bs, 0, Abase, Bbase, K, 0, tid);
    if (nst > 1) issue_stage<TBN>(As, Bs, 1, Abase, Bbase, K, BK, tid);

    float acc[4][NFI][4];
#pragma unroll
    for (int i = 0; i < 4; i++)
#pragma unroll
        for (int j = 0; j < NFI; j++)
#pragma unroll
            for (int q = 0; q < 4; q++) acc[i][j][q] = 0.f;

    const int frag_m = (ttile & 1) * 8 + trow;
    const int frag_k = (ttile >> 1) * 8;

    for (int it = 0; it < nst; it++) {
        if (it + 1 < nst) {
            asm volatile("cp.async.wait_group 1;\n");
        } else {
            asm volatile("cp.async.wait_group 0;\n");
        }
        // single barrier per iteration: orders (a) smem visibility of the
        // just-arrived stage and (b) completion of everyone's compute on
        // stage (it-1) before it gets overwritten by issue below.
        __syncthreads();
        if (it + 2 < nst)
            issue_stage<TBN>(As, Bs, (it + 2) % 3, Abase, Bbase, K, (it + 2) * BK, tid);

        const uint32_t asu = sbase + ((it % 3) * ASTG_H) * 2;
        const uint32_t bsu = sbase + (3 * ASTG_H + (it % 3) * BSTG_H) * 2;

#pragma unroll
        for (int ks = 0; ks < 2; ks++) {
            const int kk = ks * 16;
            uint32_t af[4][4];
#pragma unroll
            for (int mfi = 0; mfi < 4; mfi++) {
                int m0 = wm * 64 + mfi * 16;
                ldsm4(asu + (uint32_t)((m0 + frag_m) * HSTR + kk + frag_k) * 2,
                      af[mfi][0], af[mfi][1], af[mfi][2], af[mfi][3]);
            }
            uint32_t bf[NFI][2];
#pragma unroll
            for (int nfp = 0; nfp < NLD; nfp++) {
                int n0 = wn * WSPAN + nfp * 16;
                ldsm4(bsu + (uint32_t)((n0 + frag_m) * HSTR + kk + frag_k) * 2,
                      bf[2 * nfp][0], bf[2 * nfp + 1][0],
                      bf[2 * nfp][1], bf[2 * nfp + 1][1]);
            }
#pragma unroll
            for (int mfi = 0; mfi < 4; mfi++)
#pragma unroll
                for (int nfi = 0; nfi < NFI; nfi++)
                    mma_f16(acc[mfi][nfi], af[mfi], bf[nfi]);
        }
    }

#pragma unroll
    for (int mfi = 0; mfi < 4; mfi++) {
#pragma unroll
        for (int nfi = 0; nfi < NFI; nfi++) {
            int r0 = rowBase + wm * 64 + mfi * 16 + gid;
            int c0 = colBase + wn * WSPAN + nfi * 8 + tg * 2;
            float v0 = acc[mfi][nfi][0], v1 = acc[mfi][nfi][1];
            float v2 = acc[mfi][nfi][2], v3 = acc[mfi][nfi][3];
            if (mode == 2) {
                __half* G = (__half*)Cv;
                int gc = (colBase + wn * WSPAN + nfi * 8) / 2 + tg;
                float s0 = v0 / (1.f + __expf(-v0));
                float s1 = v2 / (1.f + __expf(-v2));
                G[(size_t)r0 * KP2 + gc] = __float2half(s0 * v1);
                G[(size_t)(r0 + 8) * KP2 + gc] = __float2half(s1 * v3);
            } else if (mode == 1) {
                __half* Ch = (__half*)Cv;
                *(__half2*)&Ch[(size_t)r0 * N + c0] = __floats2half2_rn(v0, v1);
                *(__half2*)&Ch[(size_t)(r0 + 8) * N + c0] = __floats2half2_rn(v2, v3);
            } else {
                float* C = (float*)Cv;
                if (R) {
                    v0 += R[(size_t)r0 * N + c0];
                    v1 += R[(size_t)r0 * N + c0 + 1];
                    v2 += R[(size_t)(r0 + 8) * N + c0];
                    v3 += R[(size_t)(r0 + 8) * N + c0 + 1];
                }
                *(float2*)&C[(size_t)r0 * N + c0] = make_float2(v0, v1);
                *(float2*)&C[(size_t)(r0 + 8) * N + c0] = make_float2(v2, v3);
            }
        }
    }
}

#define GH_SMEM_256 ((3 * (ASTG_H + 256 * HSTR)) * 2)
#define GH_SMEM_128 ((3 * (ASTG_H + 128 * HSTR)) * 2)

// ---------------- fp16 flash attention, register softmax ----------------
#define ATQ 64
#define ACJ 128
#define QSTRH 72
#define KSTRH 72
#define VSTRH 72
#define PSTRH 136
#define ATT_SMEM 65536

__global__ __launch_bounds__(256, 2)
void attn_h() {
    extern __shared__ char asm_[];
    __half* Qh = (__half*)asm_;
    __half* Kh = (__half*)(asm_ + 9216);
    __half* Vh = (__half*)(asm_ + 27648);
    __half* Ph = (__half*)(asm_ + 46080);
    float*  redm = (float*)(asm_ + 63488);
    float*  reds = (float*)(asm_ + 64512);

    const uint32_t qbase = (uint32_t)__cvta_generic_to_shared(Qh);
    const uint32_t kbase = (uint32_t)__cvta_generic_to_shared(Kh);
    const uint32_t vbase = (uint32_t)__cvta_generic_to_shared(Vh);
    const uint32_t pbase = (uint32_t)__cvta_generic_to_shared(Ph);

    const int tid = threadIdx.x;
    const int warp = tid >> 5, lane = tid & 31;
    const int gid = lane >> 2, tg = lane & 3;
    const int wm = warp >> 2, wn = warp & 3;
    const int ttile = lane >> 3, trow = lane & 7;
    const int frag_m = (ttile & 1) * 8 + trow;
    const int frag_k = (ttile >> 1) * 8;

    // LPT scheduling: heaviest (largest qt) blocks first
    const int qt = (gridDim.x - 1) - blockIdx.x;
    const int h = blockIdx.y, b = blockIdx.z;
    const int q0 = qt * ATQ;

    const __half* qg = g_qkvH + (size_t)b * SEQ * NQKV + h * DHEAD;
    const __half* kg = qg + DMODEL;
    const __half* vg = qg + 2 * DMODEL;

#pragma unroll
    for (int i = 0; i < 2; i++) {
        int c = tid + i * 256;
        int r = c >> 3, p = c & 7;
        *(uint4*)&Qh[r * QSTRH + p * 8] =
            *(const uint4*)(qg + (size_t)(q0 + r) * NQKV + p * 8);
    }

    float o[2][2][4];
#pragma unroll
    for (int i = 0; i < 2; i++)
#pragma unroll
        for (int j = 0; j < 2; j++)
#pragma unroll
            for (int q = 0; q < 4; q++) o[i][j][q] = 0.f;
    float m_lo[2] = {-1e30f, -1e30f}, m_hi[2] = {-1e30f, -1e30f};
    float l_lo[2] = {0.f, 0.f}, l_hi[2] = {0.f, 0.f};

    __syncthreads();

    const int nchunks = (q0 + ATQ + ACJ - 1) / ACJ;
    for (int c = 0; c < nchunks; c++) {
        const int j0 = c * ACJ;
        if (c) __syncthreads();

#pragma unroll
        for (int i = 0; i < 4; i++) {
            int cc = tid + i * 256;
            int j = cc >> 3, p = cc & 7;
            *(uint4*)&Kh[j * KSTRH + p * 8] =
                *(const uint4*)(kg + (size_t)(j0 + j) * NQKV + p * 8);
            *(uint4*)&Vh[j * VSTRH + p * 8] =
                *(const uint4*)(vg + (size_t)(j0 + j) * NQKV + p * 8);
        }
        __syncthreads();

        float sacc[2][4][4];
#pragma unroll
        for (int i = 0; i < 2; i++)
#pragma unroll
            for (int j = 0; j < 4; j++)
#pragma unroll
                for (int q = 0; q < 4; q++) sacc[i][j][q] = 0.f;
#pragma unroll
        for (int kk = 0; kk < 64; kk += 16) {
            uint32_t af[2][4];
#pragma unroll
            for (int mfi = 0; mfi < 2; mfi++) {
                int m0 = wm * 32 + mfi * 16;
                ldsm4(qbase + (uint32_t)((m0 + frag_m) * QSTRH + kk + frag_k) * 2,
                      af[mfi][0], af[mfi][1], af[mfi][2], af[mfi][3]);
            }
            uint32_t bf[4][2];
#pragma unroll
            for (int nfp = 0; nfp < 2; nfp++) {
                int n0 = wn * 32 + nfp * 16;
                ldsm4(kbase + (uint32_t)((n0 + frag_m) * KSTRH + kk + frag_k) * 2,
                      bf[2 * nfp][0], bf[2 * nfp + 1][0],
                      bf[2 * nfp][1], bf[2 * nfp + 1][1]);
            }
#pragma unroll
            for (int mfi = 0; mfi < 2; mfi++)
#pragma unroll
                for (int nfi = 0; nfi < 4; nfi++)
                    mma_f16(sacc[mfi][nfi], af[mfi], bf[nfi]);
        }

        float mx_lo[2], mx_hi[2];
#pragma unroll
        for (int mfi = 0; mfi < 2; mfi++) {
            int r = wm * 32 + mfi * 16 + gid;
            int lim_lo = q0 + r - j0;
            int lim_hi = lim_lo + 8;
            mx_lo[mfi] = -1e30f; mx_hi[mfi] = -1e30f;
#pragma unroll
            for (int nfi = 0; nfi < 4; nfi++) {
                int cb = wn * 32 + nfi * 8 + tg * 2;
                float s0 = (cb     <= lim_lo) ? sacc[mfi][nfi][0] * 0.125f : -1e30f;
                float s1 = (cb + 1 <= lim_lo) ? sacc[mfi][nfi][1] * 0.125f : -1e30f;
                float s2 = (cb     <= lim_hi) ? sacc[mfi][nfi][2] * 0.125f : -1e30f;
                float s3 = (cb + 1 <= lim_hi) ? sacc[mfi][nfi][3] * 0.125f : -1e30f;
                sacc[mfi][nfi][0] = s0; sacc[mfi][nfi][1] = s1;
                sacc[mfi][nfi][2] = s2; sacc[mfi][nfi][3] = s3;
                mx_lo[mfi] = fmaxf(mx_lo[mfi], fmaxf(s0, s1));
                mx_hi[mfi] = fmaxf(mx_hi[mfi], fmaxf(s2, s3));
            }
            mx_lo[mfi] = fmaxf(mx_lo[mfi], __shfl_xor_sync(0xffffffffu, mx_lo[mfi], 1));
            mx_lo[mfi] = fmaxf(mx_lo[mfi], __shfl_xor_sync(0xffffffffu, mx_lo[mfi], 2));
            mx_hi[mfi] = fmaxf(mx_hi[mfi], __shfl_xor_sync(0xffffffffu, mx_hi[mfi], 1));
            mx_hi[mfi] = fmaxf(mx_hi[mfi], __shfl_xor_sync(0xffffffffu, mx_hi[mfi], 2));
            if (tg == 0) {
                redm[wn * 64 + r] = mx_lo[mfi];
                redm[wn * 64 + r + 8] = mx_hi[mfi];
            }
        }
        __syncthreads();

        float corr_lo[2], corr_hi[2];
#pragma unroll
        for (int mfi = 0; mfi < 2; mfi++) {
            int r = wm * 32 + mfi * 16 + gid;
            float ml = fmaxf(fmaxf(redm[r], redm[64 + r]),
                             fmaxf(redm[128 + r], redm[192 + r]));
            float mh = fmaxf(fmaxf(redm[r + 8], redm[64 + r + 8]),
                             fmaxf(redm[128 + r + 8], redm[192 + r + 8]));
            float mnl = fmaxf(m_lo[mfi], ml);
            float mnh = fmaxf(m_hi[mfi], mh);
            corr_lo[mfi] = __expf(m_lo[mfi] - mnl);
            corr_hi[mfi] = __expf(m_hi[mfi] - mnh);
            m_lo[mfi] = mnl; m_hi[mfi] = mnh;

            float ps_lo = 0.f, ps_hi = 0.f;
#pragma unroll
            for (int nfi = 0; nfi < 4; nfi++) {
                int cb = wn * 32 + nfi * 8 + tg * 2;
                float p0 = __expf(sacc[mfi][nfi][0] - mnl);
                float p1 = __expf(sacc[mfi][nfi][1] - mnl);
                float p2 = __expf(sacc[mfi][nfi][2] - mnh);
                float p3 = __expf(sacc[mfi][nfi][3] - mnh);
                ps_lo += p0 + p1; ps_hi += p2 + p3;
                *(__half2*)&Ph[r * PSTRH + cb] = __floats2half2_rn(p0, p1);
                *(__half2*)&Ph[(r + 8) * PSTRH + cb] = __floats2half2_rn(p2, p3);
            }
            ps_lo += __shfl_xor_sync(0xffffffffu, ps_lo, 1);
            ps_lo += __shfl_xor_sync(0xffffffffu, ps_lo, 2);
            ps_hi += __shfl_xor_sync(0xffffffffu, ps_hi, 1);
            ps_hi += __shfl_xor_sync(0xffffffffu, ps_hi, 2);
            if (tg == 0) {
                reds[wn * 64 + r] = ps_lo;
                reds[wn * 64 + r + 8] = ps_hi;
            }
        }
        __syncthreads();

#pragma unroll
        for (int mfi = 0; mfi < 2; mfi++) {
            int r = wm * 32 + mfi * 16 + gid;
            float sl = reds[r] + reds[64 + r] + reds[128 + r] + reds[192 + r];
            float sh = reds[r + 8] + reds[64 + r + 8] + reds[128 + r + 8] + reds[192 + r + 8];
            l_lo[mfi] = l_lo[mfi] * corr_lo[mfi] + sl;
            l_hi[mfi] = l_hi[mfi] * corr_hi[mfi] + sh;
#pragma unroll
            for (int nfi = 0; nfi < 2; nfi++) {
                o[mfi][nfi][0] *= corr_lo[mfi]; o[mfi][nfi][1] *= corr_lo[mfi];
                o[mfi][nfi][2] *= corr_hi[mfi]; o[mfi][nfi][3] *= corr_hi[mfi];
            }
        }

#pragma unroll
        for (int kk = 0; kk < ACJ; kk += 16) {
            uint32_t pa[2][4];
#pragma unroll
            for (int mfi = 0; mfi < 2; mfi++) {
                int m0 = wm * 32 + mfi * 16;
                ldsm4(pbase + (uint32_t)((m0 + frag_m) * PSTRH + kk + frag_k) * 2,
                      pa[mfi][0], pa[mfi][1], pa[mfi][2], pa[mfi][3]);
            }
            uint32_t v0r, v1r, v2r, v3r;
            ldsm4t(vbase + (uint32_t)(((kk + (lane & 15)) * VSTRH +
                                       wn * 16 + ((lane >> 4) << 3)) * 2),
                   v0r, v1r, v2r, v3r);
            uint32_t b_lo[2] = {v0r, v1r};
            uint32_t b_hi[2] = {v2r, v3r};
#pragma unroll
            for (int mfi = 0; mfi < 2; mfi++) {
                mma_f16(o[mfi][0], pa[mfi], b_lo);
                mma_f16(o[mfi][1], pa[mfi], b_hi);
            }
        }
    }

#pragma unroll
    for (int mfi = 0; mfi < 2; mfi++) {
        float iv  = 1.0f / l_lo[mfi];
        float iv8 = 1.0f / l_hi[mfi];
        int r0 = q0 + wm * 32 + mfi * 16 + gid;
#pragma unroll
        for (int nfi = 0; nfi < 2; nfi++) {
            int c0 = h * DHEAD + wn * 16 + nfi * 8 + tg * 2;
            __half* dst = g_attnH + ((size_t)(b * SEQ + r0)) * DMODEL + c0;
            *(__half2*)dst = __floats2half2_rn(o[mfi][nfi][0] * iv, o[mfi][nfi][1] * iv);
            __half* dst8 = dst + 8 * DMODEL;
            *(__half2*)dst8 = __floats2half2_rn(o[mfi][nfi][2] * iv8, o[mfi][nfi][3] * iv8);
        }
    }
}

// ---------------- launch ----------------
extern "C" void kernel_launch(void* const* d_in, const int* in_sizes, int n_in,
                              void* d_out, int out_size) {
    const float* x   = (const float*)d_in[0];
    const float* g1  = (const float*)d_in[1];
    const float* g2  = (const float*)d_in[2];
    const float* w_q = (const float*)d_in[3];
    const float* w_k = (const float*)d_in[4];
    const float* w_v = (const float*)d_in[5];
    const float* w_o = (const float*)d_in[6];
    const float* w1  = (const float*)d_in[7];
    const float* w2  = (const float*)d_in[8];
    const float* w3  = (const float*)d_in[9];
    float* out = (float*)d_out;

    __half *p_xn, *p_qkvH, *p_attnH, *p_hn, *p_gate;
    __half *p_wqkvT, *p_woT, *p_w13T, *p_w2T;
    float *p_hres;
    cudaGetSymbolAddress((void**)&p_xn,    g_xn);
    cudaGetSymbolAddress((void**)&p_qkvH,  g_qkvH);
    cudaGetSymbolAddress((void**)&p_attnH, g_attnH);
    cudaGetSymbolAddress((void**)&p_hres,  g_hres);
    cudaGetSymbolAddress((void**)&p_hn,    g_hn);
    cudaGetSymbolAddress((void**)&p_gate,  g_gate);
    cudaGetSymbolAddress((void**)&p_wqkvT, g_wqkvT);
    cudaGetSymbolAddress((void**)&p_woT,   g_woT);
    cudaGetSymbolAddress((void**)&p_w13T,  g_w13T);
    cudaGetSymbolAddress((void**)&p_w2T,   g_w2T);

    static int attr_set = 0;
    if (!attr_set) {
        cudaFuncSetAttribute(gemm_h<256>, cudaFuncAttributeMaxDynamicSharedMemorySize, GH_SMEM_256);
        cudaFuncSetAttribute(gemm_h<128>, cudaFuncAttributeMaxDynamicSharedMemorySize, GH_SMEM_128);
        cudaFuncSetAttribute(attn_h, cudaFuncAttributeMaxDynamicSharedMemorySize, ATT_SMEM);
        attr_set = 1;
    }

    cvt_all<<<12352, 256>>>(w_q, w_k, w_v, w_o, w1, w3, w2,
                            p_wqkvT, p_woT, p_w13T, p_w2T);

    rmsnorm_kernel<<<NTOK, 256>>>(x, g1, p_xn);
    gemm_h<256><<<dim3(NQKV / 256, NTOK / BM), 256, GH_SMEM_256>>>(
        p_xn, p_wqkvT, p_qkvH, nullptr, NQKV, DMODEL, 1);
    attn_h<<<dim3(SEQ / ATQ, NHEADS, BATCH), 256, ATT_SMEM>>>();
    gemm_h<128><<<dim3(DMODEL / 128, NTOK / BM), 256, GH_SMEM_128>>>(
        p_attnH, p_woT, p_hres, x, DMODEL, DMODEL, 0);
    rmsnorm_kernel<<<NTOK, 256>>>(p_hres, g2, p_hn);
    gemm_h<256><<<dim3(NFF2P / 256, NTOK / BM), 256, GH_SMEM_256>>>(
        p_hn, p_w13T, p_gate, nullptr, NFF2P, DMODEL, 2);
    gemm_h<128><<<dim3(DMODEL / 128, NTOK / BM), 256, GH_SMEM_128>>>(
        p_gate, p_w2T, out, p_hres, DMODEL, KP2, 0);
}